// round 1
// baseline (speedup 1.0000x reference)
#include <cuda_runtime.h>
#include <math.h>
#include <stdint.h>

#define BATCH 4
#define SEQ   2048
#define EMB   1024
#define HEADS 16
#define HDIM  64
#define MROWS (BATCH*SEQ)   // 8192

// ---------------- scratch (static __device__ — no allocations allowed) ------
__device__ float g_Q[MROWS*EMB];
__device__ float g_K[MROWS*EMB];
__device__ float g_V[MROWS*EMB];
__device__ float g_CTX[MROWS*EMB];

// ---------------- GEMM: C = A @ W^T + bias ----------------------------------
// A: [M,K] row-major, W: [N,K] row-major (torch Linear weight), C: [M,N]
#define BM 128
#define BN 128
#define BK 16
#define LDS_STRIDE 136   // padded row stride (floats); 136*4 % 16 == 0 for float4

__global__ __launch_bounds__(256)
void gemm_nt_bias(const float* __restrict__ A, const float* __restrict__ W,
                  const float* __restrict__ bias, float* __restrict__ C,
                  int Mdim, int Ndim, int Kdim) {
    __shared__ float As[BK][LDS_STRIDE];
    __shared__ float Bs[BK][LDS_STRIDE];

    const int tid = threadIdx.x;
    const int tn = tid & 15;       // 0..15 -> 8 cols each
    const int tm = tid >> 4;       // 0..15 -> 8 rows each
    const int m0 = blockIdx.y * BM;
    const int n0 = blockIdx.x * BN;

    float acc[8][8];
#pragma unroll
    for (int i = 0; i < 8; i++)
#pragma unroll
        for (int j = 0; j < 8; j++) acc[i][j] = 0.f;

    for (int k0 = 0; k0 < Kdim; k0 += BK) {
        // load A tile [BM x BK] transposed into As[k][m]
#pragma unroll
        for (int l = tid; l < BM * BK / 4; l += 256) {
            int m = l >> 2, kq = l & 3;
            float4 v = *(const float4*)&A[(size_t)(m0 + m) * Kdim + k0 + kq * 4];
            As[kq * 4 + 0][m] = v.x;
            As[kq * 4 + 1][m] = v.y;
            As[kq * 4 + 2][m] = v.z;
            As[kq * 4 + 3][m] = v.w;
        }
        // load W tile [BN x BK] transposed into Bs[k][n]
#pragma unroll
        for (int l = tid; l < BN * BK / 4; l += 256) {
            int n = l >> 2, kq = l & 3;
            float4 v = *(const float4*)&W[(size_t)(n0 + n) * Kdim + k0 + kq * 4];
            Bs[kq * 4 + 0][n] = v.x;
            Bs[kq * 4 + 1][n] = v.y;
            Bs[kq * 4 + 2][n] = v.z;
            Bs[kq * 4 + 3][n] = v.w;
        }
        __syncthreads();

#pragma unroll
        for (int k = 0; k < BK; ++k) {
            float a[8], b[8];
            *(float4*)&a[0] = *(const float4*)&As[k][tm * 8];
            *(float4*)&a[4] = *(const float4*)&As[k][tm * 8 + 4];
            *(float4*)&b[0] = *(const float4*)&Bs[k][tn * 8];
            *(float4*)&b[4] = *(const float4*)&Bs[k][tn * 8 + 4];
#pragma unroll
            for (int i = 0; i < 8; i++)
#pragma unroll
                for (int j = 0; j < 8; j++)
                    acc[i][j] = fmaf(a[i], b[j], acc[i][j]);
        }
        __syncthreads();
    }

    // epilogue: add bias, store
    float bsv[8];
#pragma unroll
    for (int j = 0; j < 8; j++) bsv[j] = bias[n0 + tn * 8 + j];
#pragma unroll
    for (int i = 0; i < 8; i++) {
        int m = m0 + tm * 8 + i;
        float4 o0, o1;
        o0.x = acc[i][0] + bsv[0]; o0.y = acc[i][1] + bsv[1];
        o0.z = acc[i][2] + bsv[2]; o0.w = acc[i][3] + bsv[3];
        o1.x = acc[i][4] + bsv[4]; o1.y = acc[i][5] + bsv[5];
        o1.z = acc[i][6] + bsv[6]; o1.w = acc[i][7] + bsv[7];
        *(float4*)&C[(size_t)m * Ndim + n0 + tn * 8]     = o0;
        *(float4*)&C[(size_t)m * Ndim + n0 + tn * 8 + 4] = o1;
    }
}

// ---------------- fused attention + mean ------------------------------------
// Q,K,V,ctx in [B,S,E] (= [B,S,H,D]) layout.
// Block = (b, q-tile of 16 rows), loops all 16 heads; scores tile lives in smem.
#define QROWS 16

__global__ __launch_bounds__(256)
void attn_kernel(const float* __restrict__ Q, const float* __restrict__ K,
                 const float* __restrict__ V, float* __restrict__ ctx,
                 float* __restrict__ meanOut, int writeMean) {
    extern __shared__ float smem[];
    float* sc = smem;                  // [QROWS][SEQ]
    float* qs = smem + QROWS * SEQ;    // [QROWS][HDIM]

    const int b   = blockIdx.y;
    const int q0  = blockIdx.x * QROWS;
    const int tid = threadIdx.x;
    const float rscale = 0.125f;       // 1/sqrt(64)
    const float invH   = 1.0f / HEADS;

    for (int h = 0; h < HEADS; h++) {
        // ---- load Q tile [QROWS x HDIM]
        for (int idx = tid; idx < QROWS * HDIM; idx += 256) {
            int q = idx >> 6, d = idx & 63;
            qs[idx] = Q[(size_t)(b * SEQ + q0 + q) * EMB + h * HDIM + d];
        }
        __syncthreads();

        // ---- scores: sc[q][k] = (Q_q . K_k) * rscale
        const float4* qs4 = (const float4*)qs;
        for (int k = tid; k < SEQ; k += 256) {
            const float4* Kr = (const float4*)&K[(size_t)(b * SEQ + k) * EMB + h * HDIM];
            float acc[QROWS];
#pragma unroll
            for (int q = 0; q < QROWS; q++) acc[q] = 0.f;
#pragma unroll
            for (int d4 = 0; d4 < HDIM / 4; d4++) {
                float4 kv = Kr[d4];
#pragma unroll
                for (int q = 0; q < QROWS; q++) {
                    float4 qv = qs4[q * (HDIM / 4) + d4];
                    acc[q] += kv.x * qv.x + kv.y * qv.y + kv.z * qv.z + kv.w * qv.w;
                }
            }
#pragma unroll
            for (int q = 0; q < QROWS; q++) sc[q * SEQ + k] = acc[q] * rscale;
        }
        __syncthreads();

        // ---- softmax per row (16 threads per row) + mean accumulation
        {
            const int r = tid >> 4;   // row 0..15
            const int j = tid & 15;
            float* row = sc + r * SEQ;
            float mx = -1e30f;
            for (int k = j; k < SEQ; k += 16) mx = fmaxf(mx, row[k]);
#pragma unroll
            for (int o = 8; o > 0; o >>= 1)
                mx = fmaxf(mx, __shfl_xor_sync(0xffffffffu, mx, o, 16));
            float sum = 0.f;
            for (int k = j; k < SEQ; k += 16) {
                float e = __expf(row[k] - mx);
                row[k] = e;
                sum += e;
            }
#pragma unroll
            for (int o = 8; o > 0; o >>= 1)
                sum += __shfl_xor_sync(0xffffffffu, sum, o, 16);
            float inv = 1.0f / sum;

            if (writeMean) {
                float* mrow = meanOut + ((size_t)b * SEQ + q0 + r) * SEQ;
                if (h == 0) {
                    for (int k = j; k < SEQ; k += 16) {
                        float p = row[k] * inv;
                        row[k] = p;
                        mrow[k] = p * invH;
                    }
                } else {
                    for (int k = j; k < SEQ; k += 16) {
                        float p = row[k] * inv;
                        row[k] = p;
                        mrow[k] += p * invH;
                    }
                }
            } else {
                for (int k = j; k < SEQ; k += 16) row[k] *= inv;
            }
        }
        __syncthreads();

        // ---- out tile = P @ V   (thread = one q row x 4 d columns)
        {
            const int d4 = tid & 15;
            const int q  = tid >> 4;
            const float* srow = sc + q * SEQ;
            const float* Vb = V + (size_t)b * SEQ * EMB + h * HDIM + d4 * 4;
            float4 a = {0.f, 0.f, 0.f, 0.f};
#pragma unroll 4
            for (int k = 0; k < SEQ; k++) {
                float p = srow[k];
                float4 vv = *(const float4*)&Vb[(size_t)k * EMB];
                a.x += p * vv.x; a.y += p * vv.y;
                a.z += p * vv.z; a.w += p * vv.w;
            }
            *(float4*)&ctx[(size_t)(b * SEQ + q0 + q) * EMB + h * HDIM + d4 * 4] = a;
        }
        __syncthreads();
    }
}

// ---------------- launch -----------------------------------------------------
extern "C" void kernel_launch(void* const* d_in, const int* in_sizes, int n_in,
                              void* d_out, int out_size) {
    const float* query = (const float*)d_in[0];
    const float* key_  = (const float*)d_in[1];
    const float* value = (const float*)d_in[2];
    const float* Wq = (const float*)d_in[3];
    const float* bq = (const float*)d_in[4];
    const float* Wk = (const float*)d_in[5];
    const float* bk = (const float*)d_in[6];
    const float* Wv = (const float*)d_in[7];
    const float* bv = (const float*)d_in[8];
    const float* Wo = (const float*)d_in[9];
    const float* bo = (const float*)d_in[10];

    float* out = (float*)d_out;
    const size_t outElems  = (size_t)MROWS * EMB;              // 8,388,608
    const size_t meanElems = (size_t)BATCH * SEQ * SEQ;        // 16,777,216
    int writeMean = ((size_t)out_size >= outElems + meanElems) ? 1 : 0;
    float* meanOut = out + outElems;

    float *Qb, *Kb, *Vb, *Cb;
    cudaGetSymbolAddress((void**)&Qb, g_Q);
    cudaGetSymbolAddress((void**)&Kb, g_K);
    cudaGetSymbolAddress((void**)&Vb, g_V);
    cudaGetSymbolAddress((void**)&Cb, g_CTX);

    dim3 gproj(EMB / BN, MROWS / BM);   // (8, 64)

    gemm_nt_bias<<<gproj, 256>>>(query, Wq, bq, Qb, MROWS, EMB, EMB);
    gemm_nt_bias<<<gproj, 256>>>(key_,  Wk, bk, Kb, MROWS, EMB, EMB);
    gemm_nt_bias<<<gproj, 256>>>(value, Wv, bv, Vb, MROWS, EMB, EMB);

    size_t smemBytes = (size_t)(QROWS * SEQ + QROWS * HDIM) * sizeof(float); // 135,168
    cudaFuncSetAttribute(attn_kernel, cudaFuncAttributeMaxDynamicSharedMemorySize,
                         (int)smemBytes);
    attn_kernel<<<dim3(SEQ / QROWS, BATCH), 256, smemBytes>>>(
        Qb, Kb, Vb, Cb, meanOut, writeMean);

    gemm_nt_bias<<<gproj, 256>>>(Cb, Wo, bo, out, MROWS, EMB, EMB);
}

// round 2
// speedup vs baseline: 2.4097x; 2.4097x over previous
#include <cuda_runtime.h>
#include <math.h>
#include <stdint.h>

#define BATCH 4
#define SEQ   2048
#define EMB   1024
#define HEADS 16
#define HDIM  64
#define MROWS (BATCH*SEQ)   // 8192

// ---------------- scratch (static __device__ — no allocations allowed) ------
__device__ float g_Q[MROWS*EMB];
__device__ float g_K[MROWS*EMB];
__device__ float g_V[MROWS*EMB];
__device__ float g_CTX[MROWS*EMB];
__device__ float g_Kt[BATCH*HEADS*HDIM*SEQ];   // K transposed: [b][h][d][s]

// ---------------- GEMM: C = A @ W^T + bias ----------------------------------
#define BM 128
#define BN 128
#define BK 16
#define LDS_STRIDE 136

__global__ __launch_bounds__(256)
void gemm_nt_bias(const float* __restrict__ A, const float* __restrict__ W,
                  const float* __restrict__ bias, float* __restrict__ C,
                  int Mdim, int Ndim, int Kdim) {
    __shared__ float As[BK][LDS_STRIDE];
    __shared__ float Bs[BK][LDS_STRIDE];

    const int tid = threadIdx.x;
    const int tn = tid & 15;
    const int tm = tid >> 4;
    const int m0 = blockIdx.y * BM;
    const int n0 = blockIdx.x * BN;

    float acc[8][8];
#pragma unroll
    for (int i = 0; i < 8; i++)
#pragma unroll
        for (int j = 0; j < 8; j++) acc[i][j] = 0.f;

    for (int k0 = 0; k0 < Kdim; k0 += BK) {
#pragma unroll
        for (int l = tid; l < BM * BK / 4; l += 256) {
            int m = l >> 2, kq = l & 3;
            float4 v = *(const float4*)&A[(size_t)(m0 + m) * Kdim + k0 + kq * 4];
            As[kq * 4 + 0][m] = v.x;
            As[kq * 4 + 1][m] = v.y;
            As[kq * 4 + 2][m] = v.z;
            As[kq * 4 + 3][m] = v.w;
        }
#pragma unroll
        for (int l = tid; l < BN * BK / 4; l += 256) {
            int n = l >> 2, kq = l & 3;
            float4 v = *(const float4*)&W[(size_t)(n0 + n) * Kdim + k0 + kq * 4];
            Bs[kq * 4 + 0][n] = v.x;
            Bs[kq * 4 + 1][n] = v.y;
            Bs[kq * 4 + 2][n] = v.z;
            Bs[kq * 4 + 3][n] = v.w;
        }
        __syncthreads();

#pragma unroll
        for (int k = 0; k < BK; ++k) {
            float a[8], b[8];
            *(float4*)&a[0] = *(const float4*)&As[k][tm * 8];
            *(float4*)&a[4] = *(const float4*)&As[k][tm * 8 + 4];
            *(float4*)&b[0] = *(const float4*)&Bs[k][tn * 8];
            *(float4*)&b[4] = *(const float4*)&Bs[k][tn * 8 + 4];
#pragma unroll
            for (int i = 0; i < 8; i++)
#pragma unroll
                for (int j = 0; j < 8; j++)
                    acc[i][j] = fmaf(a[i], b[j], acc[i][j]);
        }
        __syncthreads();
    }

    float bsv[8];
#pragma unroll
    for (int j = 0; j < 8; j++) bsv[j] = bias[n0 + tn * 8 + j];
#pragma unroll
    for (int i = 0; i < 8; i++) {
        int m = m0 + tm * 8 + i;
        float4 o0, o1;
        o0.x = acc[i][0] + bsv[0]; o0.y = acc[i][1] + bsv[1];
        o0.z = acc[i][2] + bsv[2]; o0.w = acc[i][3] + bsv[3];
        o1.x = acc[i][4] + bsv[4]; o1.y = acc[i][5] + bsv[5];
        o1.z = acc[i][6] + bsv[6]; o1.w = acc[i][7] + bsv[7];
        *(float4*)&C[(size_t)m * Ndim + n0 + tn * 8]     = o0;
        *(float4*)&C[(size_t)m * Ndim + n0 + tn * 8 + 4] = o1;
    }
}

// ---------------- K transpose: g_K [b,s,h,d] -> g_Kt [b,h,d,s] ---------------
__global__ __launch_bounds__(256)
void transpose_k(const float* __restrict__ K, float* __restrict__ Kt) {
    __shared__ float st[64][65];
    const int tid = threadIdx.x;
    const int s0 = blockIdx.x * 64;
    const int h  = blockIdx.y;
    const int b  = blockIdx.z;

#pragma unroll
    for (int i = 0; i < 4; i++) {
        int idx = tid + i * 256;          // 1024 float4s
        int ss = idx >> 4, d4 = idx & 15;
        float4 v = *(const float4*)&K[((size_t)(b * SEQ + s0 + ss)) * EMB + h * HDIM + d4 * 4];
        st[ss][d4 * 4 + 0] = v.x;
        st[ss][d4 * 4 + 1] = v.y;
        st[ss][d4 * 4 + 2] = v.z;
        st[ss][d4 * 4 + 3] = v.w;
    }
    __syncthreads();
#pragma unroll
    for (int i = 0; i < 4; i++) {
        int idx = tid + i * 256;
        int d = idx >> 4, s4 = idx & 15;
        float4 v;
        v.x = st[s4 * 4 + 0][d];
        v.y = st[s4 * 4 + 1][d];
        v.z = st[s4 * 4 + 2][d];
        v.w = st[s4 * 4 + 3][d];
        *(float4*)&Kt[((size_t)((b * HEADS + h) * HDIM + d)) * SEQ + s0 + s4 * 4] = v;
    }
}

// ---------------- fused attention + mean ------------------------------------
#define QROWS 16
#define KCH   256
#define KSP   264     // Ks row stride (floats), mult of 4
#define VSP   68      // Vs row stride
#define QSP   20      // Qs row stride

__global__ __launch_bounds__(256)
void attn_kernel(const float* __restrict__ Q, const float* __restrict__ Kt,
                 const float* __restrict__ V, float* __restrict__ ctx,
                 float* __restrict__ meanOut, int writeMean) {
    extern __shared__ float smem[];
    float* sc = smem;                                // [16][2048]
    float* Qs = smem + QROWS * SEQ;                  // [64][QSP]
    float* Ks = Qs + HDIM * QSP;                     // [64][KSP] (scores)
    float* Vs = Ks;                                  // [KCH][VSP] (PV, aliased)

    const int b   = blockIdx.y;
    const int q0  = blockIdx.x * QROWS;
    const int tid = threadIdx.x;
    const float rscale = 0.125f;     // 1/sqrt(64)
    const float invH   = 1.0f / HEADS;

    // scores mapping: thread tile 8q x 8k, 4-way d-split (in-warp)
    const int s_ds = tid & 3;
    const int s_kg = (tid >> 2) & 31;
    const int s_qg = tid >> 7;
    // PV mapping: thread tile 8q x 4d, 8-way k-split (in-warp)
    const int p_ks = tid & 7;
    const int p_dg = (tid >> 3) & 15;
    const int p_qg = tid >> 7;

    for (int h = 0; h < HEADS; h++) {
        // ---- load Q tile transposed into Qs[d][q] (one float4 per thread)
        {
            int q = tid >> 4, d4 = tid & 15;
            float4 v = *(const float4*)&Q[((size_t)(b * SEQ + q0 + q)) * EMB + h * HDIM + d4 * 4];
            Qs[(d4 * 4 + 0) * QSP + q] = v.x;
            Qs[(d4 * 4 + 1) * QSP + q] = v.y;
            Qs[(d4 * 4 + 2) * QSP + q] = v.z;
            Qs[(d4 * 4 + 3) * QSP + q] = v.w;
        }
        __syncthreads();

        // =================== scores: sc = (Qtile @ K^T) * rscale ============
        const float* KtH = Kt + ((size_t)(b * HEADS + h) * HDIM) * SEQ;
        for (int kc = 0; kc < SEQ; kc += KCH) {
            // load Ks[d][kk] from Kt (coalesced rows)
#pragma unroll
            for (int i = 0; i < 16; i++) {
                int idx = tid + i * 256;         // 4096 float4s
                int d = idx >> 6, kk4 = idx & 63;
                float4 v = *(const float4*)&KtH[(size_t)d * SEQ + kc + kk4 * 4];
                *(float4*)&Ks[d * KSP + kk4 * 4] = v;
            }
            __syncthreads();

            float acc[8][8];
#pragma unroll
            for (int i = 0; i < 8; i++)
#pragma unroll
                for (int j = 0; j < 8; j++) acc[i][j] = 0.f;

#pragma unroll
            for (int dd = 0; dd < 16; dd++) {
                int d = s_ds * 16 + dd;
                float a[8], bb[8];
                *(float4*)&a[0]  = *(const float4*)&Qs[d * QSP + s_qg * 8];
                *(float4*)&a[4]  = *(const float4*)&Qs[d * QSP + s_qg * 8 + 4];
                *(float4*)&bb[0] = *(const float4*)&Ks[d * KSP + s_kg * 8];
                *(float4*)&bb[4] = *(const float4*)&Ks[d * KSP + s_kg * 8 + 4];
#pragma unroll
                for (int i = 0; i < 8; i++)
#pragma unroll
                    for (int j = 0; j < 8; j++)
                        acc[i][j] = fmaf(a[i], bb[j], acc[i][j]);
            }

            // reduce over d-split (lanes differing in bits 0..1)
#pragma unroll
            for (int i = 0; i < 8; i++)
#pragma unroll
                for (int j = 0; j < 8; j++) {
                    float v = acc[i][j];
                    v += __shfl_xor_sync(0xffffffffu, v, 1);
                    v += __shfl_xor_sync(0xffffffffu, v, 2);
                    acc[i][j] = v;
                }

            if (s_ds == 0) {
#pragma unroll
                for (int i = 0; i < 8; i++) {
                    float4 w0, w1;
                    w0.x = acc[i][0] * rscale; w0.y = acc[i][1] * rscale;
                    w0.z = acc[i][2] * rscale; w0.w = acc[i][3] * rscale;
                    w1.x = acc[i][4] * rscale; w1.y = acc[i][5] * rscale;
                    w1.z = acc[i][6] * rscale; w1.w = acc[i][7] * rscale;
                    float* dst = &sc[(s_qg * 8 + i) * SEQ + kc + s_kg * 8];
                    *(float4*)dst       = w0;
                    *(float4*)(dst + 4) = w1;
                }
            }
            __syncthreads();
        }

        // =================== softmax per row + mean =========================
        {
            const int r = tid >> 4;
            const int j = tid & 15;
            float* row = sc + r * SEQ;
            float mx = -1e30f;
            for (int k = j; k < SEQ; k += 16) mx = fmaxf(mx, row[k]);
#pragma unroll
            for (int o = 8; o > 0; o >>= 1)
                mx = fmaxf(mx, __shfl_xor_sync(0xffffffffu, mx, o, 16));
            float sum = 0.f;
            for (int k = j; k < SEQ; k += 16) {
                float e = __expf(row[k] - mx);
                row[k] = e;
                sum += e;
            }
#pragma unroll
            for (int o = 8; o > 0; o >>= 1)
                sum += __shfl_xor_sync(0xffffffffu, sum, o, 16);
            float inv = 1.0f / sum;

            if (writeMean) {
                float* mrow = meanOut + ((size_t)b * SEQ + q0 + r) * SEQ;
                if (h == 0) {
                    for (int k = j; k < SEQ; k += 16) {
                        float p = row[k] * inv;
                        row[k] = p;
                        mrow[k] = p * invH;
                    }
                } else {
                    for (int k = j; k < SEQ; k += 16) {
                        float p = row[k] * inv;
                        row[k] = p;
                        mrow[k] += p * invH;
                    }
                }
            } else {
                for (int k = j; k < SEQ; k += 16) row[k] *= inv;
            }
        }
        __syncthreads();

        // =================== PV: out = P @ V ================================
        float4 pacc[8];
#pragma unroll
        for (int i = 0; i < 8; i++) pacc[i] = make_float4(0.f, 0.f, 0.f, 0.f);

        for (int kc = 0; kc < SEQ; kc += KCH) {
            // load Vs[kk][d] (coalesced)
            const float* Vb = V + ((size_t)(b * SEQ + kc)) * EMB + h * HDIM;
#pragma unroll
            for (int i = 0; i < 16; i++) {
                int idx = tid + i * 256;         // 4096 float4s
                int kk = idx >> 4, d4 = idx & 15;
                float4 v = *(const float4*)&Vb[(size_t)kk * EMB + d4 * 4];
                *(float4*)&Vs[kk * VSP + d4 * 4] = v;
            }
            __syncthreads();

#pragma unroll 4
            for (int kk = 0; kk < KCH / 8; kk++) {
                int kl = kk * 8 + p_ks;
                float4 vv = *(const float4*)&Vs[kl * VSP + p_dg * 4];
                const float* prow = &sc[(p_qg * 8) * SEQ + kc + kl];
#pragma unroll
                for (int i = 0; i < 8; i++) {
                    float p = prow[i * SEQ];
                    pacc[i].x = fmaf(p, vv.x, pacc[i].x);
                    pacc[i].y = fmaf(p, vv.y, pacc[i].y);
                    pacc[i].z = fmaf(p, vv.z, pacc[i].z);
                    pacc[i].w = fmaf(p, vv.w, pacc[i].w);
                }
            }
            __syncthreads();
        }

        // reduce over k-split (lanes differing in bits 0..2) and store
#pragma unroll
        for (int i = 0; i < 8; i++) {
            pacc[i].x += __shfl_xor_sync(0xffffffffu, pacc[i].x, 1);
            pacc[i].y += __shfl_xor_sync(0xffffffffu, pacc[i].y, 1);
            pacc[i].z += __shfl_xor_sync(0xffffffffu, pacc[i].z, 1);
            pacc[i].w += __shfl_xor_sync(0xffffffffu, pacc[i].w, 1);
            pacc[i].x += __shfl_xor_sync(0xffffffffu, pacc[i].x, 2);
            pacc[i].y += __shfl_xor_sync(0xffffffffu, pacc[i].y, 2);
            pacc[i].z += __shfl_xor_sync(0xffffffffu, pacc[i].z, 2);
            pacc[i].w += __shfl_xor_sync(0xffffffffu, pacc[i].w, 2);
            pacc[i].x += __shfl_xor_sync(0xffffffffu, pacc[i].x, 4);
            pacc[i].y += __shfl_xor_sync(0xffffffffu, pacc[i].y, 4);
            pacc[i].z += __shfl_xor_sync(0xffffffffu, pacc[i].z, 4);
            pacc[i].w += __shfl_xor_sync(0xffffffffu, pacc[i].w, 4);
        }
        if (p_ks == 0) {
#pragma unroll
            for (int i = 0; i < 8; i++) {
                *(float4*)&ctx[((size_t)(b * SEQ + q0 + p_qg * 8 + i)) * EMB
                               + h * HDIM + p_dg * 4] = pacc[i];
            }
        }
        __syncthreads();
    }
}

// ---------------- launch -----------------------------------------------------
extern "C" void kernel_launch(void* const* d_in, const int* in_sizes, int n_in,
                              void* d_out, int out_size) {
    const float* query = (const float*)d_in[0];
    const float* key_  = (const float*)d_in[1];
    const float* value = (const float*)d_in[2];
    const float* Wq = (const float*)d_in[3];
    const float* bq = (const float*)d_in[4];
    const float* Wk = (const float*)d_in[5];
    const float* bk = (const float*)d_in[6];
    const float* Wv = (const float*)d_in[7];
    const float* bv = (const float*)d_in[8];
    const float* Wo = (const float*)d_in[9];
    const float* bo = (const float*)d_in[10];

    float* out = (float*)d_out;
    const size_t outElems  = (size_t)MROWS * EMB;
    const size_t meanElems = (size_t)BATCH * SEQ * SEQ;
    int writeMean = ((size_t)out_size >= outElems + meanElems) ? 1 : 0;
    float* meanOut = out + outElems;

    float *Qb, *Kb, *Vb, *Cb, *Ktb;
    cudaGetSymbolAddress((void**)&Qb,  g_Q);
    cudaGetSymbolAddress((void**)&Kb,  g_K);
    cudaGetSymbolAddress((void**)&Vb,  g_V);
    cudaGetSymbolAddress((void**)&Cb,  g_CTX);
    cudaGetSymbolAddress((void**)&Ktb, g_Kt);

    dim3 gproj(EMB / BN, MROWS / BM);

    gemm_nt_bias<<<gproj, 256>>>(query, Wq, bq, Qb, MROWS, EMB, EMB);
    gemm_nt_bias<<<gproj, 256>>>(key_,  Wk, bk, Kb, MROWS, EMB, EMB);
    gemm_nt_bias<<<gproj, 256>>>(value, Wv, bv, Vb, MROWS, EMB, EMB);

    transpose_k<<<dim3(SEQ / 64, HEADS, BATCH), 256>>>(Kb, Ktb);

    size_t smemBytes = (size_t)(QROWS * SEQ + HDIM * QSP + KCH * VSP) * sizeof(float);
    cudaFuncSetAttribute(attn_kernel, cudaFuncAttributeMaxDynamicSharedMemorySize,
                         (int)smemBytes);
    attn_kernel<<<dim3(SEQ / QROWS, BATCH), 256, smemBytes>>>(
        Qb, Ktb, Vb, Cb, meanOut, writeMean);

    gemm_nt_bias<<<gproj, 256>>>(Cb, Wo, bo, out, MROWS, EMB, EMB);
}

// round 3
// speedup vs baseline: 2.5010x; 1.0379x over previous
#include <cuda_runtime.h>
#include <math.h>
#include <stdint.h>

#define BATCH 4
#define SEQ   2048
#define EMB   1024
#define HEADS 16
#define HDIM  64
#define MROWS (BATCH*SEQ)   // 8192

// ---------------- scratch (static __device__ — no allocations allowed) ------
__device__ float g_Q[MROWS*EMB];
__device__ float g_K[MROWS*EMB];
__device__ float g_V[MROWS*EMB];
__device__ float g_CTX[MROWS*EMB];
__device__ float g_Kt[BATCH*HEADS*HDIM*SEQ];   // K transposed: [b][h][d][s]

// ---------------- fast exp: FMA-pipe only, no MUFU --------------------------
// exp(x) = 2^(x*log2e); magic-number round-to-nearest; deg-5 poly on [-.5,.5].
// Valid for |x| < ~80 (scores here are bounded by ~±12). Rel err ~3e-6.
__device__ __forceinline__ float fast_exp(float x) {
    const float L2E   = 1.4426950408889634f;
    const float MAGIC = 12582912.0f;           // 1.5 * 2^23
    float t = x * L2E;
    float z = t + MAGIC;
    int   i = __float_as_int(z);
    float k = z - MAGIC;
    float f = t - k;                           // f in [-0.5, 0.5]
    float p =         1.3333558146e-3f;
    p = fmaf(p, f,    9.6181291076e-3f);
    p = fmaf(p, f,    5.5504108665e-2f);
    p = fmaf(p, f,    2.4022650696e-1f);
    p = fmaf(p, f,    6.9314718056e-1f);
    p = fmaf(p, f,    1.0f);
    float s = __int_as_float((i - 0x4B400000 + 127) << 23);  // 2^round(t)
    return p * s;
}

// ---------------- GEMM: C = A @ W^T + bias ----------------------------------
#define BM 128
#define BN 128
#define BK 16
#define LDS_STRIDE 136

__global__ __launch_bounds__(256)
void gemm_nt_bias(const float* __restrict__ A, const float* __restrict__ W,
                  const float* __restrict__ bias, float* __restrict__ C,
                  int Mdim, int Ndim, int Kdim) {
    __shared__ float As[BK][LDS_STRIDE];
    __shared__ float Bs[BK][LDS_STRIDE];

    const int tid = threadIdx.x;
    const int tn = tid & 15;
    const int tm = tid >> 4;
    const int m0 = blockIdx.y * BM;
    const int n0 = blockIdx.x * BN;

    float acc[8][8];
#pragma unroll
    for (int i = 0; i < 8; i++)
#pragma unroll
        for (int j = 0; j < 8; j++) acc[i][j] = 0.f;

    for (int k0 = 0; k0 < Kdim; k0 += BK) {
#pragma unroll
        for (int l = tid; l < BM * BK / 4; l += 256) {
            int m = l >> 2, kq = l & 3;
            float4 v = *(const float4*)&A[(size_t)(m0 + m) * Kdim + k0 + kq * 4];
            As[kq * 4 + 0][m] = v.x;
            As[kq * 4 + 1][m] = v.y;
            As[kq * 4 + 2][m] = v.z;
            As[kq * 4 + 3][m] = v.w;
        }
#pragma unroll
        for (int l = tid; l < BN * BK / 4; l += 256) {
            int n = l >> 2, kq = l & 3;
            float4 v = *(const float4*)&W[(size_t)(n0 + n) * Kdim + k0 + kq * 4];
            Bs[kq * 4 + 0][n] = v.x;
            Bs[kq * 4 + 1][n] = v.y;
            Bs[kq * 4 + 2][n] = v.z;
            Bs[kq * 4 + 3][n] = v.w;
        }
        __syncthreads();

#pragma unroll
        for (int k = 0; k < BK; ++k) {
            float a[8], b[8];
            *(float4*)&a[0] = *(const float4*)&As[k][tm * 8];
            *(float4*)&a[4] = *(const float4*)&As[k][tm * 8 + 4];
            *(float4*)&b[0] = *(const float4*)&Bs[k][tn * 8];
            *(float4*)&b[4] = *(const float4*)&Bs[k][tn * 8 + 4];
#pragma unroll
            for (int i = 0; i < 8; i++)
#pragma unroll
                for (int j = 0; j < 8; j++)
                    acc[i][j] = fmaf(a[i], b[j], acc[i][j]);
        }
        __syncthreads();
    }

    float bsv[8];
#pragma unroll
    for (int j = 0; j < 8; j++) bsv[j] = bias[n0 + tn * 8 + j];
#pragma unroll
    for (int i = 0; i < 8; i++) {
        int m = m0 + tm * 8 + i;
        float4 o0, o1;
        o0.x = acc[i][0] + bsv[0]; o0.y = acc[i][1] + bsv[1];
        o0.z = acc[i][2] + bsv[2]; o0.w = acc[i][3] + bsv[3];
        o1.x = acc[i][4] + bsv[4]; o1.y = acc[i][5] + bsv[5];
        o1.z = acc[i][6] + bsv[6]; o1.w = acc[i][7] + bsv[7];
        *(float4*)&C[(size_t)m * Ndim + n0 + tn * 8]     = o0;
        *(float4*)&C[(size_t)m * Ndim + n0 + tn * 8 + 4] = o1;
    }
}

// ---------------- K transpose: g_K [b,s,h,d] -> g_Kt [b,h,d,s] ---------------
__global__ __launch_bounds__(256)
void transpose_k(const float* __restrict__ K, float* __restrict__ Kt) {
    __shared__ float st[64][65];
    const int tid = threadIdx.x;
    const int s0 = blockIdx.x * 64;
    const int h  = blockIdx.y;
    const int b  = blockIdx.z;

#pragma unroll
    for (int i = 0; i < 4; i++) {
        int idx = tid + i * 256;
        int ss = idx >> 4, d4 = idx & 15;
        float4 v = *(const float4*)&K[((size_t)(b * SEQ + s0 + ss)) * EMB + h * HDIM + d4 * 4];
        st[ss][d4 * 4 + 0] = v.x;
        st[ss][d4 * 4 + 1] = v.y;
        st[ss][d4 * 4 + 2] = v.z;
        st[ss][d4 * 4 + 3] = v.w;
    }
    __syncthreads();
#pragma unroll
    for (int i = 0; i < 4; i++) {
        int idx = tid + i * 256;
        int d = idx >> 4, s4 = idx & 15;
        float4 v;
        v.x = st[s4 * 4 + 0][d];
        v.y = st[s4 * 4 + 1][d];
        v.z = st[s4 * 4 + 2][d];
        v.w = st[s4 * 4 + 3][d];
        *(float4*)&Kt[((size_t)((b * HEADS + h) * HDIM + d)) * SEQ + s0 + s4 * 4] = v;
    }
}

// ---------------- fused attention + mean ------------------------------------
#define QROWS 16
#define KCH   256
#define KSP   264     // Ks row stride (floats)
#define VSP   68      // Vs row stride
#define QSP   20      // Qs row stride

__global__ __launch_bounds__(256)
void attn_kernel(const float* __restrict__ Q, const float* __restrict__ Kt,
                 const float* __restrict__ V, float* __restrict__ ctx,
                 float* __restrict__ meanOut, int writeMean) {
    extern __shared__ float smem[];
    float* sc   = smem;                                // [16][2048]
    float* Qs   = smem + QROWS * SEQ;                  // [64][QSP]
    float* Ks   = Qs + HDIM * QSP;                     // [64][KSP] (scores)
    float* Vs   = Ks;                                  // [KCH][VSP] (PV, aliased)
    float* sInv = Ks + KCH * VSP;                      // [16] row inverse sums

    const int b   = blockIdx.y;
    const int q0  = blockIdx.x * QROWS;
    const int tid = threadIdx.x;
    const float rscale = 0.125f;     // 1/sqrt(64)
    const float invH   = 1.0f / HEADS;

    // scores mapping: thread tile 8q x 8k, 4-way d-split (in-warp)
    const int s_ds = tid & 3;
    const int s_kg = (tid >> 2) & 31;
    const int s_qg = tid >> 7;
    // PV mapping: thread tile 8q x 4d, 8-way k-split (in-warp)
    const int p_ks = tid & 7;
    const int p_dg = (tid >> 3) & 15;
    const int p_qg = tid >> 7;

    for (int h = 0; h < HEADS; h++) {
        // ---- load Q tile transposed into Qs[d][q]
        {
            int q = tid >> 4, d4 = tid & 15;
            float4 v = *(const float4*)&Q[((size_t)(b * SEQ + q0 + q)) * EMB + h * HDIM + d4 * 4];
            Qs[(d4 * 4 + 0) * QSP + q] = v.x;
            Qs[(d4 * 4 + 1) * QSP + q] = v.y;
            Qs[(d4 * 4 + 2) * QSP + q] = v.z;
            Qs[(d4 * 4 + 3) * QSP + q] = v.w;
        }
        __syncthreads();

        // =================== scores: sc = (Qtile @ K^T) * rscale ============
        const float* KtH = Kt + ((size_t)(b * HEADS + h) * HDIM) * SEQ;
        for (int kc = 0; kc < SEQ; kc += KCH) {
#pragma unroll
            for (int i = 0; i < 16; i++) {
                int idx = tid + i * 256;
                int d = idx >> 6, kk4 = idx & 63;
                float4 v = *(const float4*)&KtH[(size_t)d * SEQ + kc + kk4 * 4];
                *(float4*)&Ks[d * KSP + kk4 * 4] = v;
            }
            __syncthreads();

            float acc[8][8];
#pragma unroll
            for (int i = 0; i < 8; i++)
#pragma unroll
                for (int j = 0; j < 8; j++) acc[i][j] = 0.f;

#pragma unroll
            for (int dd = 0; dd < 16; dd++) {
                int d = s_ds * 16 + dd;
                float a[8], bb[8];
                *(float4*)&a[0]  = *(const float4*)&Qs[d * QSP + s_qg * 8];
                *(float4*)&a[4]  = *(const float4*)&Qs[d * QSP + s_qg * 8 + 4];
                *(float4*)&bb[0] = *(const float4*)&Ks[d * KSP + s_kg * 8];
                *(float4*)&bb[4] = *(const float4*)&Ks[d * KSP + s_kg * 8 + 4];
#pragma unroll
                for (int i = 0; i < 8; i++)
#pragma unroll
                    for (int j = 0; j < 8; j++)
                        acc[i][j] = fmaf(a[i], bb[j], acc[i][j]);
            }

#pragma unroll
            for (int i = 0; i < 8; i++)
#pragma unroll
                for (int j = 0; j < 8; j++) {
                    float v = acc[i][j];
                    v += __shfl_xor_sync(0xffffffffu, v, 1);
                    v += __shfl_xor_sync(0xffffffffu, v, 2);
                    acc[i][j] = v;
                }

            if (s_ds == 0) {
#pragma unroll
                for (int i = 0; i < 8; i++) {
                    float4 w0, w1;
                    w0.x = acc[i][0] * rscale; w0.y = acc[i][1] * rscale;
                    w0.z = acc[i][2] * rscale; w0.w = acc[i][3] * rscale;
                    w1.x = acc[i][4] * rscale; w1.y = acc[i][5] * rscale;
                    w1.z = acc[i][6] * rscale; w1.w = acc[i][7] * rscale;
                    float* dst = &sc[(s_qg * 8 + i) * SEQ + kc + s_kg * 8];
                    *(float4*)dst       = w0;
                    *(float4*)(dst + 4) = w1;
                }
            }
            __syncthreads();
        }

        // ========== softmax: exp (no max-sub; scores bounded) + sum =========
        // sc holds UNNORMALIZED exp after this; sInv[r] = 1/rowsum.
        {
            const int r = tid >> 4;
            const int j = tid & 15;
            float* row = sc + r * SEQ;
            float sum = 0.f;
            for (int k4 = j; k4 < SEQ / 4; k4 += 16) {
                float4 v = *(float4*)&row[k4 * 4];
                v.x = fast_exp(v.x); v.y = fast_exp(v.y);
                v.z = fast_exp(v.z); v.w = fast_exp(v.w);
                sum += (v.x + v.y) + (v.z + v.w);
                *(float4*)&row[k4 * 4] = v;
            }
#pragma unroll
            for (int o = 8; o > 0; o >>= 1)
                sum += __shfl_xor_sync(0xffffffffu, sum, o, 16);
            float inv = 1.0f / sum;
            if (j == 0) sInv[r] = inv;

            if (writeMean) {
                float fac = inv * invH;
                float* mrow = meanOut + ((size_t)b * SEQ + q0 + r) * SEQ;
                if (h == 0) {
                    for (int k4 = j; k4 < SEQ / 4; k4 += 16) {
                        float4 v = *(const float4*)&row[k4 * 4];
                        float4 m;
                        m.x = v.x * fac; m.y = v.y * fac;
                        m.z = v.z * fac; m.w = v.w * fac;
                        *(float4*)&mrow[k4 * 4] = m;
                    }
                } else {
                    for (int k4 = j; k4 < SEQ / 4; k4 += 16) {
                        float4 v = *(const float4*)&row[k4 * 4];
                        float4 m = *(const float4*)&mrow[k4 * 4];
                        m.x = fmaf(v.x, fac, m.x); m.y = fmaf(v.y, fac, m.y);
                        m.z = fmaf(v.z, fac, m.z); m.w = fmaf(v.w, fac, m.w);
                        *(float4*)&mrow[k4 * 4] = m;
                    }
                }
            }
        }
        __syncthreads();

        // =================== PV: out = (exp @ V) * inv ======================
        float4 pacc[8];
#pragma unroll
        for (int i = 0; i < 8; i++) pacc[i] = make_float4(0.f, 0.f, 0.f, 0.f);

        for (int kc = 0; kc < SEQ; kc += KCH) {
            const float* Vb = V + ((size_t)(b * SEQ + kc)) * EMB + h * HDIM;
#pragma unroll
            for (int i = 0; i < 16; i++) {
                int idx = tid + i * 256;
                int kk = idx >> 4, d4 = idx & 15;
                float4 v = *(const float4*)&Vb[(size_t)kk * EMB + d4 * 4];
                *(float4*)&Vs[kk * VSP + d4 * 4] = v;
            }
            __syncthreads();

#pragma unroll 4
            for (int kk = 0; kk < KCH / 8; kk++) {
                int kl = kk * 8 + p_ks;
                float4 vv = *(const float4*)&Vs[kl * VSP + p_dg * 4];
                const float* prow = &sc[(p_qg * 8) * SEQ + kc + kl];
#pragma unroll
                for (int i = 0; i < 8; i++) {
                    float p = prow[i * SEQ];
                    pacc[i].x = fmaf(p, vv.x, pacc[i].x);
                    pacc[i].y = fmaf(p, vv.y, pacc[i].y);
                    pacc[i].z = fmaf(p, vv.z, pacc[i].z);
                    pacc[i].w = fmaf(p, vv.w, pacc[i].w);
                }
            }
            __syncthreads();
        }

        // reduce over k-split, normalize by row sum, store
#pragma unroll
        for (int i = 0; i < 8; i++) {
            pacc[i].x += __shfl_xor_sync(0xffffffffu, pacc[i].x, 1);
            pacc[i].y += __shfl_xor_sync(0xffffffffu, pacc[i].y, 1);
            pacc[i].z += __shfl_xor_sync(0xffffffffu, pacc[i].z, 1);
            pacc[i].w += __shfl_xor_sync(0xffffffffu, pacc[i].w, 1);
            pacc[i].x += __shfl_xor_sync(0xffffffffu, pacc[i].x, 2);
            pacc[i].y += __shfl_xor_sync(0xffffffffu, pacc[i].y, 2);
            pacc[i].z += __shfl_xor_sync(0xffffffffu, pacc[i].z, 2);
            pacc[i].w += __shfl_xor_sync(0xffffffffu, pacc[i].w, 2);
            pacc[i].x += __shfl_xor_sync(0xffffffffu, pacc[i].x, 4);
            pacc[i].y += __shfl_xor_sync(0xffffffffu, pacc[i].y, 4);
            pacc[i].z += __shfl_xor_sync(0xffffffffu, pacc[i].z, 4);
            pacc[i].w += __shfl_xor_sync(0xffffffffu, pacc[i].w, 4);
        }
        if (p_ks == 0) {
#pragma unroll
            for (int i = 0; i < 8; i++) {
                float inv = sInv[p_qg * 8 + i];
                float4 o;
                o.x = pacc[i].x * inv; o.y = pacc[i].y * inv;
                o.z = pacc[i].z * inv; o.w = pacc[i].w * inv;
                *(float4*)&ctx[((size_t)(b * SEQ + q0 + p_qg * 8 + i)) * EMB
                               + h * HDIM + p_dg * 4] = o;
            }
        }
        __syncthreads();
    }
}

// ---------------- launch -----------------------------------------------------
extern "C" void kernel_launch(void* const* d_in, const int* in_sizes, int n_in,
                              void* d_out, int out_size) {
    const float* query = (const float*)d_in[0];
    const float* key_  = (const float*)d_in[1];
    const float* value = (const float*)d_in[2];
    const float* Wq = (const float*)d_in[3];
    const float* bq = (const float*)d_in[4];
    const float* Wk = (const float*)d_in[5];
    const float* bk = (const float*)d_in[6];
    const float* Wv = (const float*)d_in[7];
    const float* bv = (const float*)d_in[8];
    const float* Wo = (const float*)d_in[9];
    const float* bo = (const float*)d_in[10];

    float* out = (float*)d_out;
    const size_t outElems  = (size_t)MROWS * EMB;
    const size_t meanElems = (size_t)BATCH * SEQ * SEQ;
    int writeMean = ((size_t)out_size >= outElems + meanElems) ? 1 : 0;
    float* meanOut = out + outElems;

    float *Qb, *Kb, *Vb, *Cb, *Ktb;
    cudaGetSymbolAddress((void**)&Qb,  g_Q);
    cudaGetSymbolAddress((void**)&Kb,  g_K);
    cudaGetSymbolAddress((void**)&Vb,  g_V);
    cudaGetSymbolAddress((void**)&Cb,  g_CTX);
    cudaGetSymbolAddress((void**)&Ktb, g_Kt);

    dim3 gproj(EMB / BN, MROWS / BM);

    gemm_nt_bias<<<gproj, 256>>>(query, Wq, bq, Qb, MROWS, EMB, EMB);
    gemm_nt_bias<<<gproj, 256>>>(key_,  Wk, bk, Kb, MROWS, EMB, EMB);
    gemm_nt_bias<<<gproj, 256>>>(value, Wv, bv, Vb, MROWS, EMB, EMB);

    transpose_k<<<dim3(SEQ / 64, HEADS, BATCH), 256>>>(Kb, Ktb);

    size_t smemBytes = (size_t)(QROWS * SEQ + HDIM * QSP + KCH * VSP + 16) * sizeof(float);
    cudaFuncSetAttribute(attn_kernel, cudaFuncAttributeMaxDynamicSharedMemorySize,
                         (int)smemBytes);
    attn_kernel<<<dim3(SEQ / QROWS, BATCH), 256, smemBytes>>>(
        Qb, Ktb, Vb, Cb, meanOut, writeMean);

    gemm_nt_bias<<<gproj, 256>>>(Cb, Wo, bo, out, MROWS, EMB, EMB);
}

// round 4
// speedup vs baseline: 2.9238x; 1.1690x over previous
#include <cuda_runtime.h>
#include <math.h>
#include <stdint.h>

#define BATCH 4
#define SEQ   2048
#define EMB   1024
#define HEADS 16
#define HDIM  64
#define MROWS (BATCH*SEQ)   // 8192

// ---------------- scratch ----------------------------------------------------
__device__ float g_Q[MROWS*EMB];
__device__ float g_K[MROWS*EMB];
__device__ float g_V[MROWS*EMB];
__device__ float g_CTX[MROWS*EMB];
__device__ float g_Kt[BATCH*HEADS*HDIM*SEQ];   // [b][h][d][s]

// ---------------- fast exp (FMA pipe only) -----------------------------------
__device__ __forceinline__ float fast_exp(float x) {
    const float L2E   = 1.4426950408889634f;
    const float MAGIC = 12582912.0f;           // 1.5 * 2^23
    float t = x * L2E;
    float z = t + MAGIC;
    int   i = __float_as_int(z);
    float k = z - MAGIC;
    float f = t - k;
    float p =         1.3333558146e-3f;
    p = fmaf(p, f,    9.6181291076e-3f);
    p = fmaf(p, f,    5.5504108665e-2f);
    p = fmaf(p, f,    2.4022650696e-1f);
    p = fmaf(p, f,    6.9314718056e-1f);
    p = fmaf(p, f,    1.0f);
    float s = __int_as_float((i - 0x4B400000 + 127) << 23);
    return p * s;
}

// ---------------- GEMM: C = A @ W^T + bias ------------------------------------
#define BM 128
#define BN 128
#define BK 16
#define LDS_STRIDE 136

__global__ __launch_bounds__(256)
void gemm_nt_bias(const float* __restrict__ A, const float* __restrict__ W,
                  const float* __restrict__ bias, float* __restrict__ C,
                  int Mdim, int Ndim, int Kdim) {
    __shared__ float As[BK][LDS_STRIDE];
    __shared__ float Bs[BK][LDS_STRIDE];

    const int tid = threadIdx.x;
    const int tn = tid & 15;
    const int tm = tid >> 4;
    const int m0 = blockIdx.y * BM;
    const int n0 = blockIdx.x * BN;

    float acc[8][8];
#pragma unroll
    for (int i = 0; i < 8; i++)
#pragma unroll
        for (int j = 0; j < 8; j++) acc[i][j] = 0.f;

    for (int k0 = 0; k0 < Kdim; k0 += BK) {
#pragma unroll
        for (int l = tid; l < BM * BK / 4; l += 256) {
            int m = l >> 2, kq = l & 3;
            float4 v = *(const float4*)&A[(size_t)(m0 + m) * Kdim + k0 + kq * 4];
            As[kq * 4 + 0][m] = v.x;
            As[kq * 4 + 1][m] = v.y;
            As[kq * 4 + 2][m] = v.z;
            As[kq * 4 + 3][m] = v.w;
        }
#pragma unroll
        for (int l = tid; l < BN * BK / 4; l += 256) {
            int n = l >> 2, kq = l & 3;
            float4 v = *(const float4*)&W[(size_t)(n0 + n) * Kdim + k0 + kq * 4];
            Bs[kq * 4 + 0][n] = v.x;
            Bs[kq * 4 + 1][n] = v.y;
            Bs[kq * 4 + 2][n] = v.z;
            Bs[kq * 4 + 3][n] = v.w;
        }
        __syncthreads();

#pragma unroll
        for (int k = 0; k < BK; ++k) {
            float a[8], b[8];
            *(float4*)&a[0] = *(const float4*)&As[k][tm * 8];
            *(float4*)&a[4] = *(const float4*)&As[k][tm * 8 + 4];
            *(float4*)&b[0] = *(const float4*)&Bs[k][tn * 8];
            *(float4*)&b[4] = *(const float4*)&Bs[k][tn * 8 + 4];
#pragma unroll
            for (int i = 0; i < 8; i++)
#pragma unroll
                for (int j = 0; j < 8; j++)
                    acc[i][j] = fmaf(a[i], b[j], acc[i][j]);
        }
        __syncthreads();
    }

    float bsv[8];
#pragma unroll
    for (int j = 0; j < 8; j++) bsv[j] = bias[n0 + tn * 8 + j];
#pragma unroll
    for (int i = 0; i < 8; i++) {
        int m = m0 + tm * 8 + i;
        float4 o0, o1;
        o0.x = acc[i][0] + bsv[0]; o0.y = acc[i][1] + bsv[1];
        o0.z = acc[i][2] + bsv[2]; o0.w = acc[i][3] + bsv[3];
        o1.x = acc[i][4] + bsv[4]; o1.y = acc[i][5] + bsv[5];
        o1.z = acc[i][6] + bsv[6]; o1.w = acc[i][7] + bsv[7];
        *(float4*)&C[(size_t)m * Ndim + n0 + tn * 8]     = o0;
        *(float4*)&C[(size_t)m * Ndim + n0 + tn * 8 + 4] = o1;
    }
}

// ---------------- K transpose -------------------------------------------------
__global__ __launch_bounds__(256)
void transpose_k(const float* __restrict__ K, float* __restrict__ Kt) {
    __shared__ float st[64][65];
    const int tid = threadIdx.x;
    const int s0 = blockIdx.x * 64;
    const int h  = blockIdx.y;
    const int b  = blockIdx.z;

#pragma unroll
    for (int i = 0; i < 4; i++) {
        int idx = tid + i * 256;
        int ss = idx >> 4, d4 = idx & 15;
        float4 v = *(const float4*)&K[((size_t)(b * SEQ + s0 + ss)) * EMB + h * HDIM + d4 * 4];
        st[ss][d4 * 4 + 0] = v.x;
        st[ss][d4 * 4 + 1] = v.y;
        st[ss][d4 * 4 + 2] = v.z;
        st[ss][d4 * 4 + 3] = v.w;
    }
    __syncthreads();
#pragma unroll
    for (int i = 0; i < 4; i++) {
        int idx = tid + i * 256;
        int d = idx >> 4, s4 = idx & 15;
        float4 v;
        v.x = st[s4 * 4 + 0][d];
        v.y = st[s4 * 4 + 1][d];
        v.z = st[s4 * 4 + 2][d];
        v.w = st[s4 * 4 + 3][d];
        *(float4*)&Kt[((size_t)((b * HEADS + h) * HDIM + d)) * SEQ + s0 + s4 * 4] = v;
    }
}

// ---------------- fused attention + mean (512 threads) -------------------------
#define QROWS 16
#define KCH   256
#define KSP   264     // Ks row stride (floats)
#define VSP   68      // Vs row stride
#define QSP   20      // Qs row stride
#define NTHR  512

__global__ __launch_bounds__(NTHR)
void attn_kernel(const float* __restrict__ Q, const float* __restrict__ Kt,
                 const float* __restrict__ V, float* __restrict__ ctx,
                 float* __restrict__ meanOut, int writeMean) {
    extern __shared__ float smem[];
    float* sc   = smem;                                // [16][2048]
    float* Qs   = smem + QROWS * SEQ;                  // [64][QSP]
    float* Ks   = Qs + HDIM * QSP;                     // [64][KSP] (scores)
    float* Vs   = Ks;                                  // [KCH][VSP] (PV, aliased)
    float* sInv = Ks + KCH * VSP;                      // [16]

    const int b   = blockIdx.y;
    const int q0  = blockIdx.x * QROWS;
    const int tid = threadIdx.x;
    const float rscale = 0.125f;
    const float invH   = 1.0f / HEADS;

    // scores mapping: thread = 8 q-rows x 1 k-col, full d
    const int s_k  = tid & 255;
    const int s_qg = tid >> 8;       // 0..1
    // PV mapping: thread = 8 q x 1 float4-d, 16-way k-split
    const int p_ks = tid & 15;
    const int p_d4 = (tid >> 4) & 15;
    const int p_qg = tid >> 8;       // 0..1

    for (int h = 0; h < HEADS; h++) {
        // ---- load Q tile (pre-scaled) transposed into Qs[d][q]
        if (tid < 256) {
            int q = tid >> 4, d4 = tid & 15;
            float4 v = *(const float4*)&Q[((size_t)(b * SEQ + q0 + q)) * EMB + h * HDIM + d4 * 4];
            Qs[(d4 * 4 + 0) * QSP + q] = v.x * rscale;
            Qs[(d4 * 4 + 1) * QSP + q] = v.y * rscale;
            Qs[(d4 * 4 + 2) * QSP + q] = v.z * rscale;
            Qs[(d4 * 4 + 3) * QSP + q] = v.w * rscale;
        }
        __syncthreads();

        // =================== scores ========================================
        const float* KtH = Kt + ((size_t)(b * HEADS + h) * HDIM) * SEQ;
        for (int kc = 0; kc < SEQ; kc += KCH) {
            // load Ks[d][kk] (coalesced, 8 float4 per thread)
#pragma unroll
            for (int i = 0; i < 8; i++) {
                int idx = tid + i * NTHR;        // 4096 float4s
                int d = idx >> 6, kk4 = idx & 63;
                float4 v = *(const float4*)&KtH[(size_t)d * SEQ + kc + kk4 * 4];
                *(float4*)&Ks[d * KSP + kk4 * 4] = v;
            }
            __syncthreads();

            float acc[8];
#pragma unroll
            for (int i = 0; i < 8; i++) acc[i] = 0.f;

            const float* QsB = Qs + s_qg * 8;
            const float* KsC = Ks + s_k;
#pragma unroll 8
            for (int d = 0; d < HDIM; d++) {
                float kv = KsC[d * KSP];
                float a[8];
                *(float4*)&a[0] = *(const float4*)&QsB[d * QSP];
                *(float4*)&a[4] = *(const float4*)&QsB[d * QSP + 4];
#pragma unroll
                for (int i = 0; i < 8; i++)
                    acc[i] = fmaf(a[i], kv, acc[i]);
            }
#pragma unroll
            for (int i = 0; i < 8; i++)
                sc[(s_qg * 8 + i) * SEQ + kc + s_k] = acc[i];
            __syncthreads();
        }

        // ========== softmax (no max-sub; scores bounded) ====================
        {
            const int r = tid >> 5;          // row 0..15, one warp per row
            const int j = tid & 31;
            float* row = sc + r * SEQ;
            float sum = 0.f;
#pragma unroll 4
            for (int k4 = j; k4 < SEQ / 4; k4 += 32) {
                float4 v = *(float4*)&row[k4 * 4];
                v.x = fast_exp(v.x); v.y = fast_exp(v.y);
                v.z = fast_exp(v.z); v.w = fast_exp(v.w);
                sum += (v.x + v.y) + (v.z + v.w);
                *(float4*)&row[k4 * 4] = v;
            }
#pragma unroll
            for (int o = 16; o > 0; o >>= 1)
                sum += __shfl_xor_sync(0xffffffffu, sum, o);
            float inv = 1.0f / sum;
            if (j == 0) sInv[r] = inv;

            if (writeMean) {
                float fac = inv * invH;
                float* mrow = meanOut + ((size_t)b * SEQ + q0 + r) * SEQ;
                if (h == 0) {
#pragma unroll 4
                    for (int k4 = j; k4 < SEQ / 4; k4 += 32) {
                        float4 v = *(const float4*)&row[k4 * 4];
                        float4 m;
                        m.x = v.x * fac; m.y = v.y * fac;
                        m.z = v.z * fac; m.w = v.w * fac;
                        *(float4*)&mrow[k4 * 4] = m;
                    }
                } else {
#pragma unroll 4
                    for (int k4 = j; k4 < SEQ / 4; k4 += 32) {
                        float4 v = *(const float4*)&row[k4 * 4];
                        float4 m = *(const float4*)&mrow[k4 * 4];
                        m.x = fmaf(v.x, fac, m.x); m.y = fmaf(v.y, fac, m.y);
                        m.z = fmaf(v.z, fac, m.z); m.w = fmaf(v.w, fac, m.w);
                        *(float4*)&mrow[k4 * 4] = m;
                    }
                }
            }
        }
        __syncthreads();

        // =================== PV: out = (exp @ V) * inv ======================
        float4 pacc[8];
#pragma unroll
        for (int i = 0; i < 8; i++) pacc[i] = make_float4(0.f, 0.f, 0.f, 0.f);

        for (int kc = 0; kc < SEQ; kc += KCH) {
            const float* Vb = V + ((size_t)(b * SEQ + kc)) * EMB + h * HDIM;
#pragma unroll
            for (int i = 0; i < 8; i++) {
                int idx = tid + i * NTHR;        // 4096 float4s
                int kk = idx >> 4, d4 = idx & 15;
                float4 v = *(const float4*)&Vb[(size_t)kk * EMB + d4 * 4];
                *(float4*)&Vs[kk * VSP + d4 * 4] = v;
            }
            __syncthreads();

            const float* prow0 = &sc[(p_qg * 8) * SEQ + kc];
#pragma unroll 4
            for (int kk = 0; kk < KCH / 16; kk++) {
                int kl = kk * 16 + p_ks;
                float4 vv = *(const float4*)&Vs[kl * VSP + p_d4 * 4];
#pragma unroll
                for (int i = 0; i < 8; i++) {
                    float p = prow0[i * SEQ + kl];
                    pacc[i].x = fmaf(p, vv.x, pacc[i].x);
                    pacc[i].y = fmaf(p, vv.y, pacc[i].y);
                    pacc[i].z = fmaf(p, vv.z, pacc[i].z);
                    pacc[i].w = fmaf(p, vv.w, pacc[i].w);
                }
            }
            __syncthreads();
        }

        // reduce over 16-way k-split (lane bits 0..3), normalize, store
#pragma unroll
        for (int i = 0; i < 8; i++) {
#pragma unroll
            for (int o = 1; o < 16; o <<= 1) {
                pacc[i].x += __shfl_xor_sync(0xffffffffu, pacc[i].x, o);
                pacc[i].y += __shfl_xor_sync(0xffffffffu, pacc[i].y, o);
                pacc[i].z += __shfl_xor_sync(0xffffffffu, pacc[i].z, o);
                pacc[i].w += __shfl_xor_sync(0xffffffffu, pacc[i].w, o);
            }
        }
        if (p_ks == 0) {
#pragma unroll
            for (int i = 0; i < 8; i++) {
                float inv = sInv[p_qg * 8 + i];
                float4 o;
                o.x = pacc[i].x * inv; o.y = pacc[i].y * inv;
                o.z = pacc[i].z * inv; o.w = pacc[i].w * inv;
                *(float4*)&ctx[((size_t)(b * SEQ + q0 + p_qg * 8 + i)) * EMB
                               + h * HDIM + p_d4 * 4] = o;
            }
        }
        __syncthreads();
    }
}

// ---------------- launch --------------------------------------------------------
extern "C" void kernel_launch(void* const* d_in, const int* in_sizes, int n_in,
                              void* d_out, int out_size) {
    const float* query = (const float*)d_in[0];
    const float* key_  = (const float*)d_in[1];
    const float* value = (const float*)d_in[2];
    const float* Wq = (const float*)d_in[3];
    const float* bq = (const float*)d_in[4];
    const float* Wk = (const float*)d_in[5];
    const float* bk = (const float*)d_in[6];
    const float* Wv = (const float*)d_in[7];
    const float* bv = (const float*)d_in[8];
    const float* Wo = (const float*)d_in[9];
    const float* bo = (const float*)d_in[10];

    float* out = (float*)d_out;
    const size_t outElems  = (size_t)MROWS * EMB;
    const size_t meanElems = (size_t)BATCH * SEQ * SEQ;
    int writeMean = ((size_t)out_size >= outElems + meanElems) ? 1 : 0;
    float* meanOut = out + outElems;

    float *Qb, *Kb, *Vb, *Cb, *Ktb;
    cudaGetSymbolAddress((void**)&Qb,  g_Q);
    cudaGetSymbolAddress((void**)&Kb,  g_K);
    cudaGetSymbolAddress((void**)&Vb,  g_V);
    cudaGetSymbolAddress((void**)&Cb,  g_CTX);
    cudaGetSymbolAddress((void**)&Ktb, g_Kt);

    dim3 gproj(EMB / BN, MROWS / BM);

    gemm_nt_bias<<<gproj, 256>>>(query, Wq, bq, Qb, MROWS, EMB, EMB);
    gemm_nt_bias<<<gproj, 256>>>(key_,  Wk, bk, Kb, MROWS, EMB, EMB);
    gemm_nt_bias<<<gproj, 256>>>(value, Wv, bv, Vb, MROWS, EMB, EMB);

    transpose_k<<<dim3(SEQ / 64, HEADS, BATCH), 256>>>(Kb, Ktb);

    size_t smemBytes = (size_t)(QROWS * SEQ + HDIM * QSP + KCH * VSP + 16) * sizeof(float);
    cudaFuncSetAttribute(attn_kernel, cudaFuncAttributeMaxDynamicSharedMemorySize,
                         (int)smemBytes);
    attn_kernel<<<dim3(SEQ / QROWS, BATCH), NTHR, smemBytes>>>(
        Qb, Ktb, Vb, Cb, meanOut, writeMean);

    gemm_nt_bias<<<gproj, 256>>>(Cb, Wo, bo, out, MROWS, EMB, EMB);
}

// round 5
// speedup vs baseline: 5.3465x; 1.8286x over previous
#include <cuda_runtime.h>
#include <cuda_bf16.h>
#include <math.h>
#include <stdint.h>

#define BATCH 4
#define SEQ   2048
#define EMB   1024
#define HEADS 16
#define HDIM  64
#define MROWS (BATCH*SEQ)   // 8192

typedef __nv_bfloat16 bf16;

// ---------------- scratch ------------------------------------------------------
__device__ float g_Q[MROWS*EMB];
__device__ float g_K[MROWS*EMB];
__device__ float g_V[MROWS*EMB];
__device__ float g_CTX[MROWS*EMB];
__device__ bf16  g_Ah[MROWS*EMB],  g_Al[MROWS*EMB];    // GEMM A split (reused)
__device__ bf16  g_Wh[EMB*EMB],    g_Wl[EMB*EMB];      // GEMM W split (reused)
__device__ bf16  g_Qh[MROWS*EMB],  g_Ql[MROWS*EMB];    // Q (rscale folded)
__device__ bf16  g_Kth[MROWS*EMB], g_Ktl[MROWS*EMB];   // K^T [b,h,d,s]
__device__ bf16  g_Vh[MROWS*EMB],  g_Vl[MROWS*EMB];

// ---------------- helpers ------------------------------------------------------
__device__ __forceinline__ uint32_t smem_u32(const void* p) {
    return (uint32_t)__cvta_generic_to_shared(p);
}
__device__ __forceinline__ void ldsm_x4(uint32_t& r0, uint32_t& r1, uint32_t& r2,
                                        uint32_t& r3, uint32_t addr) {
    asm volatile("ldmatrix.sync.aligned.m8n8.x4.shared.b16 {%0,%1,%2,%3}, [%4];"
                 : "=r"(r0), "=r"(r1), "=r"(r2), "=r"(r3) : "r"(addr));
}
__device__ __forceinline__ void ldsm_x2(uint32_t& r0, uint32_t& r1, uint32_t addr) {
    asm volatile("ldmatrix.sync.aligned.m8n8.x2.shared.b16 {%0,%1}, [%2];"
                 : "=r"(r0), "=r"(r1) : "r"(addr));
}
__device__ __forceinline__ void ldsm_x2t(uint32_t& r0, uint32_t& r1, uint32_t addr) {
    asm volatile("ldmatrix.sync.aligned.m8n8.x2.trans.shared.b16 {%0,%1}, [%2];"
                 : "=r"(r0), "=r"(r1) : "r"(addr));
}
__device__ __forceinline__ void mma_bf16(float (&c)[4], const uint32_t (&a)[4],
                                         const uint32_t (&b)[2]) {
    asm volatile(
        "mma.sync.aligned.m16n8k16.row.col.f32.bf16.bf16.f32 "
        "{%0,%1,%2,%3}, {%4,%5,%6,%7}, {%8,%9}, {%0,%1,%2,%3};"
        : "+f"(c[0]), "+f"(c[1]), "+f"(c[2]), "+f"(c[3])
        : "r"(a[0]), "r"(a[1]), "r"(a[2]), "r"(a[3]), "r"(b[0]), "r"(b[1]));
}
__device__ __forceinline__ uint32_t pack2(bf16 a, bf16 b) {
    __nv_bfloat162 t = __halves2bfloat162(a, b);
    return *(uint32_t*)&t;
}
__device__ __forceinline__ void split2(float x, bf16& h, bf16& l) {
    h = __float2bfloat16(x);
    l = __float2bfloat16(x - __bfloat162float(h));
}
__device__ __forceinline__ float fast_exp(float x) {
    const float L2E   = 1.4426950408889634f;
    const float MAGIC = 12582912.0f;           // 1.5 * 2^23
    float t = x * L2E;
    float z = t + MAGIC;
    int   i = __float_as_int(z);
    float k = z - MAGIC;
    float f = t - k;
    float p =         1.3333558146e-3f;
    p = fmaf(p, f,    9.6181291076e-3f);
    p = fmaf(p, f,    5.5504108665e-2f);
    p = fmaf(p, f,    2.4022650696e-1f);
    p = fmaf(p, f,    6.9314718056e-1f);
    p = fmaf(p, f,    1.0f);
    float s = __int_as_float((i - 0x4B400000 + 127) << 23);
    return p * s;
}

// ---------------- split kernel: fp32 -> bf16 hi/lo (optional scale) ------------
__global__ __launch_bounds__(256)
void split_kernel(const float* __restrict__ src, bf16* __restrict__ ho,
                  bf16* __restrict__ lo, float scale, int n4) {
    int i = blockIdx.x * 256 + threadIdx.x;
    if (i >= n4) return;
    float4 v = ((const float4*)src)[i];
    v.x *= scale; v.y *= scale; v.z *= scale; v.w *= scale;
    bf16 h0, h1, h2, h3, l0, l1, l2, l3;
    split2(v.x, h0, l0); split2(v.y, h1, l1);
    split2(v.z, h2, l2); split2(v.w, h3, l3);
    ((uint2*)ho)[i] = make_uint2(pack2(h0, h1), pack2(h2, h3));
    ((uint2*)lo)[i] = make_uint2(pack2(l0, l1), pack2(l2, l3));
}

// ---------------- K transpose + split: g_K [b,s,h,d] -> Kt hi/lo [b,h,d,s] -----
__global__ __launch_bounds__(256)
void transpose_split_k(const float* __restrict__ K, bf16* __restrict__ Kth,
                       bf16* __restrict__ Ktl) {
    __shared__ float st[64][65];
    const int tid = threadIdx.x;
    const int s0 = blockIdx.x * 64;
    const int h  = blockIdx.y;
    const int b  = blockIdx.z;

#pragma unroll
    for (int i = 0; i < 4; i++) {
        int idx = tid + i * 256;
        int ss = idx >> 4, d4 = idx & 15;
        float4 v = *(const float4*)&K[((size_t)(b * SEQ + s0 + ss)) * EMB + h * HDIM + d4 * 4];
        st[ss][d4 * 4 + 0] = v.x;
        st[ss][d4 * 4 + 1] = v.y;
        st[ss][d4 * 4 + 2] = v.z;
        st[ss][d4 * 4 + 3] = v.w;
    }
    __syncthreads();
#pragma unroll
    for (int i = 0; i < 4; i++) {
        int idx = tid + i * 256;
        int d = idx >> 4, s4 = idx & 15;
        bf16 h0, h1, h2, h3, l0, l1, l2, l3;
        split2(st[s4 * 4 + 0][d], h0, l0);
        split2(st[s4 * 4 + 1][d], h1, l1);
        split2(st[s4 * 4 + 2][d], h2, l2);
        split2(st[s4 * 4 + 3][d], h3, l3);
        size_t base = ((size_t)((b * HEADS + h) * HDIM + d)) * SEQ + s0 + s4 * 4;
        *(uint2*)&Kth[base] = make_uint2(pack2(h0, h1), pack2(h2, h3));
        *(uint2*)&Ktl[base] = make_uint2(pack2(l0, l1), pack2(l2, l3));
    }
}

// ---------------- GEMM (tensor core): C = A @ W^T + bias -----------------------
// A split hi/lo [M][K] bf16, W split hi/lo [N][K] bf16, C fp32 [M][N].
// block 128x128, BK=32, 8 warps (2m x 4n), warp tile 64x32.
#define GROW 40   // smem row stride (bf16) for 32-wide k tiles

__global__ __launch_bounds__(256)
void gemm_mma(const bf16* __restrict__ Ah, const bf16* __restrict__ Al,
              const bf16* __restrict__ Wh, const bf16* __restrict__ Wl,
              const float* __restrict__ bias, float* __restrict__ C,
              int M, int N, int K) {
    __shared__ bf16 sAh[128 * GROW];
    __shared__ bf16 sAl[128 * GROW];
    __shared__ bf16 sBh[128 * GROW];
    __shared__ bf16 sBl[128 * GROW];

    const int tid  = threadIdx.x;
    const int lane = tid & 31;
    const int wid  = tid >> 5;
    const int wm   = wid >> 2;     // 0..1
    const int wn   = wid & 3;      // 0..3
    const int m0 = blockIdx.y * 128;
    const int n0 = blockIdx.x * 128;

    float acc[4][4][4];
#pragma unroll
    for (int i = 0; i < 4; i++)
#pragma unroll
        for (int j = 0; j < 4; j++)
#pragma unroll
            for (int q = 0; q < 4; q++) acc[i][j][q] = 0.f;

    const uint32_t sAh_b = smem_u32(sAh), sAl_b = smem_u32(sAl);
    const uint32_t sBh_b = smem_u32(sBh), sBl_b = smem_u32(sBl);

    for (int k0 = 0; k0 < K; k0 += 32) {
        // load A hi/lo and B hi/lo tiles: 128x32 bf16 each, u4 = 8 bf16
#pragma unroll
        for (int i = 0; i < 2; i++) {
            int idx = tid + i * 256;           // 512 u4 per plane
            int row = idx >> 2, c8 = (idx & 3) * 8;
            uint4 va = *(const uint4*)&Ah[(size_t)(m0 + row) * K + k0 + c8];
            uint4 vb = *(const uint4*)&Al[(size_t)(m0 + row) * K + k0 + c8];
            *(uint4*)&sAh[row * GROW + c8] = va;
            *(uint4*)&sAl[row * GROW + c8] = vb;
            uint4 wa = *(const uint4*)&Wh[(size_t)(n0 + row) * K + k0 + c8];
            uint4 wb = *(const uint4*)&Wl[(size_t)(n0 + row) * K + k0 + c8];
            *(uint4*)&sBh[row * GROW + c8] = wa;
            *(uint4*)&sBl[row * GROW + c8] = wb;
        }
        __syncthreads();

#pragma unroll
        for (int kk = 0; kk < 2; kk++) {
            uint32_t afh[4][4], afl[4][4], bfh[4][2], bfl[4][2];
#pragma unroll
            for (int mt = 0; mt < 4; mt++) {
                uint32_t off = ((wm * 64 + mt * 16 + (lane & 15)) * GROW
                                + kk * 16 + (lane >> 4) * 8) * 2;
                ldsm_x4(afh[mt][0], afh[mt][1], afh[mt][2], afh[mt][3], sAh_b + off);
                ldsm_x4(afl[mt][0], afl[mt][1], afl[mt][2], afl[mt][3], sAl_b + off);
            }
#pragma unroll
            for (int nt = 0; nt < 4; nt++) {
                int l = lane & 15;
                uint32_t off = ((wn * 32 + nt * 8 + (l & 7)) * GROW
                                + kk * 16 + ((l >> 3) & 1) * 8) * 2;
                ldsm_x2(bfh[nt][0], bfh[nt][1], sBh_b + off);
                ldsm_x2(bfl[nt][0], bfl[nt][1], sBl_b + off);
            }
#pragma unroll
            for (int mt = 0; mt < 4; mt++)
#pragma unroll
                for (int nt = 0; nt < 4; nt++) {
                    mma_bf16(acc[mt][nt], afh[mt], bfh[nt]);
                    mma_bf16(acc[mt][nt], afh[mt], bfl[nt]);
                    mma_bf16(acc[mt][nt], afl[mt], bfh[nt]);
                }
        }
        __syncthreads();
    }

    // epilogue
#pragma unroll
    for (int mt = 0; mt < 4; mt++) {
#pragma unroll
        for (int nt = 0; nt < 4; nt++) {
            int m = m0 + wm * 64 + mt * 16 + (lane >> 2);
            int n = n0 + wn * 32 + nt * 8 + (lane & 3) * 2;
            float b0 = bias[n], b1 = bias[n + 1];
            float2 o0 = make_float2(acc[mt][nt][0] + b0, acc[mt][nt][1] + b1);
            float2 o1 = make_float2(acc[mt][nt][2] + b0, acc[mt][nt][3] + b1);
            *(float2*)&C[(size_t)m * N + n]       = o0;
            *(float2*)&C[(size_t)(m + 8) * N + n] = o1;
        }
    }
}

// ---------------- fused attention (tensor core) --------------------------------
#define QROWS 16
#define KCH   256
#define SROW  2056   // score plane row stride (bf16)
#define KROW2 264    // Ks row stride (bf16)
#define VROW  72     // Vs row stride (bf16)
#define QROW  72     // Qs row stride (bf16)
#define REDW  68     // red row stride (float)
#define NTHR  512

__global__ __launch_bounds__(NTHR)
void attn_mma(const bf16* __restrict__ Qh, const bf16* __restrict__ Ql,
              const bf16* __restrict__ Kth, const bf16* __restrict__ Ktl,
              const bf16* __restrict__ Vh, const bf16* __restrict__ Vl,
              float* __restrict__ ctx, float* __restrict__ meanOut, int writeMean) {
    extern __shared__ char smem_raw[];
    bf16*  Sh   = (bf16*)smem_raw;                 // [16][SROW]
    bf16*  Sl   = Sh + 16 * SROW;
    bf16*  U0   = Sl + 16 * SROW;                  // 18432 bf16 union
    bf16*  U1   = U0 + 18432;
    bf16*  Qsh  = U1 + 18432;                      // [16][QROW]
    bf16*  Qsl  = Qsh + 16 * QROW;
    float* red  = (float*)(Qsl + 16 * QROW);       // [16][REDW]
    float* sInv = red + 16 * REDW;                 // [16]

    bf16* Ksh = U0; bf16* Ksl = U1;                // scores phase [64][KROW2]
    bf16* Vsh = U0; bf16* Vsl = U1;                // PV phase [256][VROW]

    const int b    = blockIdx.y;
    const int q0   = blockIdx.x * QROWS;
    const int tid  = threadIdx.x;
    const int lane = tid & 31;
    const int wid  = tid >> 5;                     // 0..15
    const float invH = 1.0f / HEADS;

    const uint32_t Sh_b  = smem_u32(Sh),  Sl_b  = smem_u32(Sl);
    const uint32_t U0_b  = smem_u32(U0),  U1_b  = smem_u32(U1);
    const uint32_t Qsh_b = smem_u32(Qsh), Qsl_b = smem_u32(Qsl);

    for (int h = 0; h < HEADS; h++) {
        // ---- load Q tile hi/lo into smem [16][QROW]
        {
            int row = tid >> 5, c2 = (tid & 31) * 2;
            size_t g = (size_t)(b * SEQ + q0 + row) * EMB + h * HDIM + c2;
            *(uint32_t*)&Qsh[row * QROW + c2] = *(const uint32_t*)&Qh[g];
            *(uint32_t*)&Qsl[row * QROW + c2] = *(const uint32_t*)&Ql[g];
        }
        __syncthreads();

        // hoist A fragments (Q): 4 d-steps, hi/lo
        uint32_t Afh[4][4], Afl[4][4];
#pragma unroll
        for (int ds = 0; ds < 4; ds++) {
            uint32_t off = ((lane & 15) * QROW + ds * 16 + (lane >> 4) * 8) * 2;
            ldsm_x4(Afh[ds][0], Afh[ds][1], Afh[ds][2], Afh[ds][3], Qsh_b + off);
            ldsm_x4(Afl[ds][0], Afl[ds][1], Afl[ds][2], Afl[ds][3], Qsl_b + off);
        }

        // =================== scores -> Sh/Sl bf16 planes =====================
        const bf16* KtHh = Kth + ((size_t)(b * HEADS + h) * HDIM) * SEQ;
        const bf16* KtHl = Ktl + ((size_t)(b * HEADS + h) * HDIM) * SEQ;
        for (int kc = 0; kc < SEQ; kc += KCH) {
#pragma unroll
            for (int i = 0; i < 4; i++) {
                int idx = tid + i * NTHR;          // 2048 u4 per plane
                int row = idx >> 5, c8 = (idx & 31) * 8;
                *(uint4*)&Ksh[row * KROW2 + c8] =
                    *(const uint4*)&KtHh[(size_t)row * SEQ + kc + c8];
                *(uint4*)&Ksl[row * KROW2 + c8] =
                    *(const uint4*)&KtHl[(size_t)row * SEQ + kc + c8];
            }
            __syncthreads();

            int n0 = wid * 16;
#pragma unroll
            for (int nt = 0; nt < 2; nt++) {
                float c[4] = {0.f, 0.f, 0.f, 0.f};
#pragma unroll
                for (int ds = 0; ds < 4; ds++) {
                    uint32_t boff = ((ds * 16 + (lane & 15)) * KROW2 + n0 + nt * 8) * 2;
                    uint32_t bh[2], bl[2];
                    ldsm_x2t(bh[0], bh[1], U0_b + boff);
                    ldsm_x2t(bl[0], bl[1], U1_b + boff);
                    mma_bf16(c, Afh[ds], bh);
                    mma_bf16(c, Afh[ds], bl);
                    mma_bf16(c, Afl[ds], bh);
                }
                int row = lane >> 2;
                int col = kc + n0 + nt * 8 + (lane & 3) * 2;
                bf16 h0, h1, h2, h3, l0, l1, l2, l3;
                split2(c[0], h0, l0); split2(c[1], h1, l1);
                split2(c[2], h2, l2); split2(c[3], h3, l3);
                *(uint32_t*)&Sh[row * SROW + col]       = pack2(h0, h1);
                *(uint32_t*)&Sl[row * SROW + col]       = pack2(l0, l1);
                *(uint32_t*)&Sh[(row + 8) * SROW + col] = pack2(h2, h3);
                *(uint32_t*)&Sl[(row + 8) * SROW + col] = pack2(l2, l3);
            }
            __syncthreads();
        }

        // ============ softmax: exp in fp32, store P as hi/lo planes ==========
        {
            const int r = wid;
            float sum = 0.f;
#pragma unroll 2
            for (int it = 0; it < 8; it++) {
                int base = it * 256 + lane * 8;
                uint4 hv = *(uint4*)&Sh[r * SROW + base];
                uint4 lv = *(uint4*)&Sl[r * SROW + base];
                __nv_bfloat162* hp = (__nv_bfloat162*)&hv;
                __nv_bfloat162* lp = (__nv_bfloat162*)&lv;
                uint4 ho, loo;
                uint32_t* hop = (uint32_t*)&ho;
                uint32_t* lop = (uint32_t*)&loo;
#pragma unroll
                for (int p = 0; p < 4; p++) {
                    float2 fh = __bfloat1622float2(hp[p]);
                    float2 fl = __bfloat1622float2(lp[p]);
                    float e0 = fast_exp(fh.x + fl.x);
                    float e1 = fast_exp(fh.y + fl.y);
                    sum += e0 + e1;
                    bf16 eh0, el0, eh1, el1;
                    split2(e0, eh0, el0); split2(e1, eh1, el1);
                    hop[p] = pack2(eh0, eh1);
                    lop[p] = pack2(el0, el1);
                }
                *(uint4*)&Sh[r * SROW + base] = ho;
                *(uint4*)&Sl[r * SROW + base] = loo;
            }
#pragma unroll
            for (int o = 16; o > 0; o >>= 1)
                sum += __shfl_xor_sync(0xffffffffu, sum, o);
            float inv = 1.0f / sum;
            if (lane == 0) sInv[r] = inv;

            if (writeMean) {
                float fac = inv * invH;
                float* mrow = meanOut + ((size_t)b * SEQ + q0 + r) * SEQ;
#pragma unroll 2
                for (int it = 0; it < 8; it++) {
                    int base = it * 256 + lane * 8;
                    uint4 hv = *(uint4*)&Sh[r * SROW + base];
                    uint4 lv = *(uint4*)&Sl[r * SROW + base];
                    __nv_bfloat162* hp = (__nv_bfloat162*)&hv;
                    __nv_bfloat162* lp = (__nv_bfloat162*)&lv;
                    float e[8];
#pragma unroll
                    for (int p = 0; p < 4; p++) {
                        float2 fh = __bfloat1622float2(hp[p]);
                        float2 fl = __bfloat1622float2(lp[p]);
                        e[p * 2]     = fh.x + fl.x;
                        e[p * 2 + 1] = fh.y + fl.y;
                    }
                    if (h == 0) {
                        float4 m0, m1;
                        m0.x = e[0] * fac; m0.y = e[1] * fac;
                        m0.z = e[2] * fac; m0.w = e[3] * fac;
                        m1.x = e[4] * fac; m1.y = e[5] * fac;
                        m1.z = e[6] * fac; m1.w = e[7] * fac;
                        *(float4*)&mrow[base]     = m0;
                        *(float4*)&mrow[base + 4] = m1;
                    } else {
                        float4 m0 = *(const float4*)&mrow[base];
                        float4 m1 = *(const float4*)&mrow[base + 4];
                        m0.x = fmaf(e[0], fac, m0.x); m0.y = fmaf(e[1], fac, m0.y);
                        m0.z = fmaf(e[2], fac, m0.z); m0.w = fmaf(e[3], fac, m0.w);
                        m1.x = fmaf(e[4], fac, m1.x); m1.y = fmaf(e[5], fac, m1.y);
                        m1.z = fmaf(e[6], fac, m1.z); m1.w = fmaf(e[7], fac, m1.w);
                        *(float4*)&mrow[base]     = m0;
                        *(float4*)&mrow[base + 4] = m1;
                    }
                }
            }
        }
        __syncthreads();

        // =================== PV: ctx = (P @ V) * inv =========================
        // warp: n-tile = wid&7 (8 cols of d), k-half = wid>>3 (128 of 256 chunk)
        const int nt    = wid & 7;
        const int khalf = wid >> 3;
        const int n0    = nt * 8;
        float c[4] = {0.f, 0.f, 0.f, 0.f};

        for (int kc = 0; kc < SEQ; kc += KCH) {
            const bf16* VbH = Vh + (size_t)(b * SEQ + kc) * EMB + h * HDIM;
            const bf16* VbL = Vl + (size_t)(b * SEQ + kc) * EMB + h * HDIM;
#pragma unroll
            for (int i = 0; i < 4; i++) {
                int idx = tid + i * NTHR;          // 2048 u4 per plane
                int row = idx >> 3, c8 = (idx & 7) * 8;
                *(uint4*)&Vsh[row * VROW + c8] = *(const uint4*)&VbH[(size_t)row * EMB + c8];
                *(uint4*)&Vsl[row * VROW + c8] = *(const uint4*)&VbL[(size_t)row * EMB + c8];
            }
            __syncthreads();

#pragma unroll
            for (int ks = 0; ks < 8; ks++) {
                int kpos = kc + khalf * 128 + ks * 16;   // column in S planes
                int krow = khalf * 128 + ks * 16;        // row in Vs
                uint32_t aoff = ((lane & 15) * SROW + kpos + (lane >> 4) * 8) * 2;
                uint32_t ah[4], al[4];
                ldsm_x4(ah[0], ah[1], ah[2], ah[3], Sh_b + aoff);
                ldsm_x4(al[0], al[1], al[2], al[3], Sl_b + aoff);
                uint32_t boff = ((krow + (lane & 15)) * VROW + n0) * 2;
                uint32_t bh[2], bl[2];
                ldsm_x2t(bh[0], bh[1], U0_b + boff);
                ldsm_x2t(bl[0], bl[1], U1_b + boff);
                mma_bf16(c, ah, bh);
                mma_bf16(c, ah, bl);
                mma_bf16(c, al, bh);
            }
            __syncthreads();
        }

        // cross-warp k-half reduction via smem, then normalize + store
        {
            int row = lane >> 2;
            int col = n0 + (lane & 3) * 2;
            if (khalf == 1) {
                *(float2*)&red[row * REDW + col]       = make_float2(c[0], c[1]);
                *(float2*)&red[(row + 8) * REDW + col] = make_float2(c[2], c[3]);
            }
            __syncthreads();
            if (khalf == 0) {
                float2 r0 = *(const float2*)&red[row * REDW + col];
                float2 r1 = *(const float2*)&red[(row + 8) * REDW + col];
                float inv0 = sInv[row], inv1 = sInv[row + 8];
                float2 o0 = make_float2((c[0] + r0.x) * inv0, (c[1] + r0.y) * inv0);
                float2 o1 = make_float2((c[2] + r1.x) * inv1, (c[3] + r1.y) * inv1);
                *(float2*)&ctx[(size_t)(b * SEQ + q0 + row) * EMB + h * HDIM + col]     = o0;
                *(float2*)&ctx[(size_t)(b * SEQ + q0 + row + 8) * EMB + h * HDIM + col] = o1;
            }
            __syncthreads();
        }
    }
}

// ---------------- launch --------------------------------------------------------
extern "C" void kernel_launch(void* const* d_in, const int* in_sizes, int n_in,
                              void* d_out, int out_size) {
    const float* query = (const float*)d_in[0];
    const float* key_  = (const float*)d_in[1];
    const float* value = (const float*)d_in[2];
    const float* Wq = (const float*)d_in[3];
    const float* bq = (const float*)d_in[4];
    const float* Wk = (const float*)d_in[5];
    const float* bk = (const float*)d_in[6];
    const float* Wv = (const float*)d_in[7];
    const float* bv = (const float*)d_in[8];
    const float* Wo = (const float*)d_in[9];
    const float* bo = (const float*)d_in[10];

    float* out = (float*)d_out;
    const size_t outElems  = (size_t)MROWS * EMB;
    const size_t meanElems = (size_t)BATCH * SEQ * SEQ;
    int writeMean = ((size_t)out_size >= outElems + meanElems) ? 1 : 0;
    float* meanOut = out + outElems;

    float *Qb, *Kb, *Vb, *Cb;
    bf16 *Ahb, *Alb, *Whb, *Wlb, *Qhb, *Qlb, *Kthb, *Ktlb, *Vhb, *Vlb;
    cudaGetSymbolAddress((void**)&Qb,   g_Q);
    cudaGetSymbolAddress((void**)&Kb,   g_K);
    cudaGetSymbolAddress((void**)&Vb,   g_V);
    cudaGetSymbolAddress((void**)&Cb,   g_CTX);
    cudaGetSymbolAddress((void**)&Ahb,  g_Ah);
    cudaGetSymbolAddress((void**)&Alb,  g_Al);
    cudaGetSymbolAddress((void**)&Whb,  g_Wh);
    cudaGetSymbolAddress((void**)&Wlb,  g_Wl);
    cudaGetSymbolAddress((void**)&Qhb,  g_Qh);
    cudaGetSymbolAddress((void**)&Qlb,  g_Ql);
    cudaGetSymbolAddress((void**)&Kthb, g_Kth);
    cudaGetSymbolAddress((void**)&Ktlb, g_Ktl);
    cudaGetSymbolAddress((void**)&Vhb,  g_Vh);
    cudaGetSymbolAddress((void**)&Vlb,  g_Vl);

    const int n4_in = MROWS * EMB / 4;    // 2,097,152
    const int n4_w  = EMB * EMB / 4;      // 262,144
    dim3 ggemm(EMB / 128, MROWS / 128);   // (8, 64)

    // Q projection
    split_kernel<<<n4_w / 256, 256>>>(Wq, Whb, Wlb, 1.f, n4_w);
    split_kernel<<<n4_in / 256, 256>>>(query, Ahb, Alb, 1.f, n4_in);
    gemm_mma<<<ggemm, 256>>>(Ahb, Alb, Whb, Wlb, bq, Qb, MROWS, EMB, EMB);
    // K projection
    split_kernel<<<n4_w / 256, 256>>>(Wk, Whb, Wlb, 1.f, n4_w);
    split_kernel<<<n4_in / 256, 256>>>(key_, Ahb, Alb, 1.f, n4_in);
    gemm_mma<<<ggemm, 256>>>(Ahb, Alb, Whb, Wlb, bk, Kb, MROWS, EMB, EMB);
    // V projection
    split_kernel<<<n4_w / 256, 256>>>(Wv, Whb, Wlb, 1.f, n4_w);
    split_kernel<<<n4_in / 256, 256>>>(value, Ahb, Alb, 1.f, n4_in);
    gemm_mma<<<ggemm, 256>>>(Ahb, Alb, Whb, Wlb, bv, Vb, MROWS, EMB, EMB);

    // attention operand prep
    split_kernel<<<n4_in / 256, 256>>>(Qb, Qhb, Qlb, 0.125f, n4_in);   // rscale folded
    transpose_split_k<<<dim3(SEQ / 64, HEADS, BATCH), 256>>>(Kb, Kthb, Ktlb);
    split_kernel<<<n4_in / 256, 256>>>(Vb, Vhb, Vlb, 1.f, n4_in);

    // attention
    size_t smemBytes = 214336;
    cudaFuncSetAttribute(attn_mma, cudaFuncAttributeMaxDynamicSharedMemorySize,
                         (int)smemBytes);
    attn_mma<<<dim3(SEQ / QROWS, BATCH), NTHR, smemBytes>>>(
        Qhb, Qlb, Kthb, Ktlb, Vhb, Vlb, Cb, meanOut, writeMean);

    // output projection
    split_kernel<<<n4_w / 256, 256>>>(Wo, Whb, Wlb, 1.f, n4_w);
    split_kernel<<<n4_in / 256, 256>>>(Cb, Ahb, Alb, 1.f, n4_in);
    gemm_mma<<<ggemm, 256>>>(Ahb, Alb, Whb, Wlb, bo, out, MROWS, EMB, EMB);
}

// round 7
// speedup vs baseline: 6.3733x; 1.1920x over previous
#include <cuda_runtime.h>
#include <cuda_bf16.h>
#include <math.h>
#include <stdint.h>

#define BATCH 4
#define SEQ   2048
#define EMB   1024
#define HEADS 16
#define HDIM  64
#define MROWS (BATCH*SEQ)   // 8192

typedef __nv_bfloat16 bf16;

// ---------------- scratch ------------------------------------------------------
__device__ float g_K[MROWS*EMB];                       // K fp32 (for transpose)
__device__ bf16  g_Ah[MROWS*EMB],  g_Al[MROWS*EMB];    // activation split / ctx
__device__ bf16  g_Wh[EMB*EMB],    g_Wl[EMB*EMB];      // weight split (reused)
__device__ bf16  g_Qh[MROWS*EMB],  g_Ql[MROWS*EMB];    // Q (rscale folded)
__device__ bf16  g_Kth[MROWS*EMB], g_Ktl[MROWS*EMB];   // K^T [b,h,d,s]
__device__ bf16  g_Vh[MROWS*EMB],  g_Vl[MROWS*EMB];

// ---------------- helpers ------------------------------------------------------
__device__ __forceinline__ uint32_t smem_u32(const void* p) {
    return (uint32_t)__cvta_generic_to_shared(p);
}
__device__ __forceinline__ void cp_async16(uint32_t dst, const void* src) {
    asm volatile("cp.async.cg.shared.global [%0], [%1], 16;"
                 :: "r"(dst), "l"(src));
}
#define CP_COMMIT() asm volatile("cp.async.commit_group;" ::: "memory")
#define CP_WAIT1()  asm volatile("cp.async.wait_group 1;" ::: "memory")
#define CP_WAIT0()  asm volatile("cp.async.wait_group 0;" ::: "memory")

__device__ __forceinline__ void ldsm_x4(uint32_t& r0, uint32_t& r1, uint32_t& r2,
                                        uint32_t& r3, uint32_t addr) {
    asm volatile("ldmatrix.sync.aligned.m8n8.x4.shared.b16 {%0,%1,%2,%3}, [%4];"
                 : "=r"(r0), "=r"(r1), "=r"(r2), "=r"(r3) : "r"(addr));
}
__device__ __forceinline__ void ldsm_x2(uint32_t& r0, uint32_t& r1, uint32_t addr) {
    asm volatile("ldmatrix.sync.aligned.m8n8.x2.shared.b16 {%0,%1}, [%2];"
                 : "=r"(r0), "=r"(r1) : "r"(addr));
}
__device__ __forceinline__ void ldsm_x2t(uint32_t& r0, uint32_t& r1, uint32_t addr) {
    asm volatile("ldmatrix.sync.aligned.m8n8.x2.trans.shared.b16 {%0,%1}, [%2];"
                 : "=r"(r0), "=r"(r1) : "r"(addr));
}
__device__ __forceinline__ void mma_bf16(float (&c)[4], const uint32_t (&a)[4],
                                         const uint32_t (&b)[2]) {
    asm volatile(
        "mma.sync.aligned.m16n8k16.row.col.f32.bf16.bf16.f32 "
        "{%0,%1,%2,%3}, {%4,%5,%6,%7}, {%8,%9}, {%0,%1,%2,%3};"
        : "+f"(c[0]), "+f"(c[1]), "+f"(c[2]), "+f"(c[3])
        : "r"(a[0]), "r"(a[1]), "r"(a[2]), "r"(a[3]), "r"(b[0]), "r"(b[1]));
}
__device__ __forceinline__ uint32_t pack2(bf16 a, bf16 b) {
    __nv_bfloat162 t = __halves2bfloat162(a, b);
    return *(uint32_t*)&t;
}
__device__ __forceinline__ void split2(float x, bf16& h, bf16& l) {
    h = __float2bfloat16(x);
    l = __float2bfloat16(x - __bfloat162float(h));
}
__device__ __forceinline__ float fast_exp(float x) {
    const float L2E   = 1.4426950408889634f;
    const float MAGIC = 12582912.0f;           // 1.5 * 2^23
    float t = x * L2E;
    float z = t + MAGIC;
    int   i = __float_as_int(z);
    float k = z - MAGIC;
    float f = t - k;
    float p =         1.3333558146e-3f;
    p = fmaf(p, f,    9.6181291076e-3f);
    p = fmaf(p, f,    5.5504108665e-2f);
    p = fmaf(p, f,    2.4022650696e-1f);
    p = fmaf(p, f,    6.9314718056e-1f);
    p = fmaf(p, f,    1.0f);
    float s = __int_as_float((i - 0x4B400000 + 127) << 23);
    return p * s;
}

// ---------------- split kernel (weights + inputs) --------------------------------
__global__ __launch_bounds__(256)
void split_kernel(const float* __restrict__ src, bf16* __restrict__ ho,
                  bf16* __restrict__ lo, float scale, int n4) {
    int i = blockIdx.x * 256 + threadIdx.x;
    if (i >= n4) return;
    float4 v = ((const float4*)src)[i];
    v.x *= scale; v.y *= scale; v.z *= scale; v.w *= scale;
    bf16 h0, h1, h2, h3, l0, l1, l2, l3;
    split2(v.x, h0, l0); split2(v.y, h1, l1);
    split2(v.z, h2, l2); split2(v.w, h3, l3);
    ((uint2*)ho)[i] = make_uint2(pack2(h0, h1), pack2(h2, h3));
    ((uint2*)lo)[i] = make_uint2(pack2(l0, l1), pack2(l2, l3));
}

// ---------------- K transpose + split ---------------------------------------------
__global__ __launch_bounds__(256)
void transpose_split_k(const float* __restrict__ K, bf16* __restrict__ Kth,
                       bf16* __restrict__ Ktl) {
    __shared__ float st[64][65];
    const int tid = threadIdx.x;
    const int s0 = blockIdx.x * 64;
    const int h  = blockIdx.y;
    const int b  = blockIdx.z;

#pragma unroll
    for (int i = 0; i < 4; i++) {
        int idx = tid + i * 256;
        int ss = idx >> 4, d4 = idx & 15;
        float4 v = *(const float4*)&K[((size_t)(b * SEQ + s0 + ss)) * EMB + h * HDIM + d4 * 4];
        st[ss][d4 * 4 + 0] = v.x;
        st[ss][d4 * 4 + 1] = v.y;
        st[ss][d4 * 4 + 2] = v.z;
        st[ss][d4 * 4 + 3] = v.w;
    }
    __syncthreads();
#pragma unroll
    for (int i = 0; i < 4; i++) {
        int idx = tid + i * 256;
        int d = idx >> 4, s4 = idx & 15;
        bf16 h0, h1, h2, h3, l0, l1, l2, l3;
        split2(st[s4 * 4 + 0][d], h0, l0);
        split2(st[s4 * 4 + 1][d], h1, l1);
        split2(st[s4 * 4 + 2][d], h2, l2);
        split2(st[s4 * 4 + 3][d], h3, l3);
        size_t base = ((size_t)((b * HEADS + h) * HDIM + d)) * SEQ + s0 + s4 * 4;
        *(uint2*)&Kth[base] = make_uint2(pack2(h0, h1), pack2(h2, h3));
        *(uint2*)&Ktl[base] = make_uint2(pack2(l0, l1), pack2(l2, l3));
    }
}

// ---------------- GEMM (mma.sync, cp.async 2-stage) -------------------------------
// C = (A @ W^T + bias) * oscale; outputs fp32 (Cf) and/or bf16 hi/lo (Ch/Cl).
#define GROW 40
#define PL   (128*GROW)       // bf16 per plane (5120)
#define GSTG (4*PL)           // bf16 per stage
#define GEMM_SMEM (2*GSTG*2)  // bytes = 81920

__global__ __launch_bounds__(256, 2)
void gemm_mma(const bf16* __restrict__ Ah, const bf16* __restrict__ Al,
              const bf16* __restrict__ Wh, const bf16* __restrict__ Wl,
              const float* __restrict__ bias,
              float* __restrict__ Cf, bf16* __restrict__ Ch, bf16* __restrict__ Cl,
              float oscale, int M, int N, int K) {
    extern __shared__ bf16 gsm[];
    const uint32_t smb = smem_u32(gsm);

    const int tid  = threadIdx.x;
    const int lane = tid & 31;
    const int wid  = tid >> 5;
    const int wm   = wid >> 2;
    const int wn   = wid & 3;
    const int m0 = blockIdx.y * 128;
    const int n0 = blockIdx.x * 128;

    float acc[4][4][4];
#pragma unroll
    for (int i = 0; i < 4; i++)
#pragma unroll
        for (int j = 0; j < 4; j++)
#pragma unroll
            for (int q = 0; q < 4; q++) acc[i][j][q] = 0.f;

    const int r0 = tid >> 2;
    const int c8 = (tid & 3) * 8;

    // prefetch chunk 0
    {
#pragma unroll
        for (int p = 0; p < 4; p++) {
            const bf16* src = (p == 0) ? Ah : (p == 1) ? Al : (p == 2) ? Wh : Wl;
            const int rb = (p < 2) ? m0 : n0;
#pragma unroll
            for (int i = 0; i < 2; i++) {
                int row = r0 + i * 64;
                cp_async16(smb + (p * PL + row * GROW + c8) * 2,
                           src + (size_t)(rb + row) * K + c8);
            }
        }
        CP_COMMIT();
    }

    const int NCH = K / 32;
    for (int ch = 0; ch < NCH; ch++) {
        const int buf = ch & 1;
        if (ch + 1 < NCH) {
            const int nb = buf ^ 1;
            const int k0 = (ch + 1) * 32;
#pragma unroll
            for (int p = 0; p < 4; p++) {
                const bf16* src = (p == 0) ? Ah : (p == 1) ? Al : (p == 2) ? Wh : Wl;
                const int rb = (p < 2) ? m0 : n0;
#pragma unroll
                for (int i = 0; i < 2; i++) {
                    int row = r0 + i * 64;
                    cp_async16(smb + (nb * GSTG + p * PL + row * GROW + c8) * 2,
                               src + (size_t)(rb + row) * K + k0 + c8);
                }
            }
            CP_COMMIT();
            CP_WAIT1();
        } else {
            CP_WAIT0();
        }
        __syncthreads();

        const uint32_t bA = buf * GSTG;
#pragma unroll
        for (int kk = 0; kk < 2; kk++) {
            uint32_t afh[4][4], afl[4][4], bfh[4][2], bfl[4][2];
#pragma unroll
            for (int mt = 0; mt < 4; mt++) {
                uint32_t off = (bA + (wm * 64 + mt * 16 + (lane & 15)) * GROW
                                + kk * 16 + (lane >> 4) * 8) * 2;
                ldsm_x4(afh[mt][0], afh[mt][1], afh[mt][2], afh[mt][3], smb + off);
                ldsm_x4(afl[mt][0], afl[mt][1], afl[mt][2], afl[mt][3],
                        smb + off + PL * 2);
            }
#pragma unroll
            for (int nt = 0; nt < 4; nt++) {
                int l = lane & 15;
                uint32_t off = (bA + 2 * PL + (wn * 32 + nt * 8 + (l & 7)) * GROW
                                + kk * 16 + ((l >> 3) & 1) * 8) * 2;
                ldsm_x2(bfh[nt][0], bfh[nt][1], smb + off);
                ldsm_x2(bfl[nt][0], bfl[nt][1], smb + off + PL * 2);
            }
#pragma unroll
            for (int mt = 0; mt < 4; mt++)
#pragma unroll
                for (int nt = 0; nt < 4; nt++) {
                    mma_bf16(acc[mt][nt], afh[mt], bfh[nt]);
                    mma_bf16(acc[mt][nt], afh[mt], bfl[nt]);
                    mma_bf16(acc[mt][nt], afl[mt], bfh[nt]);
                }
        }
        __syncthreads();
    }

    // epilogue
#pragma unroll
    for (int nt = 0; nt < 4; nt++) {
        int n = n0 + wn * 32 + nt * 8 + (lane & 3) * 2;
        float b0 = bias[n], b1 = bias[n + 1];
#pragma unroll
        for (int mt = 0; mt < 4; mt++) {
            int m = m0 + wm * 64 + mt * 16 + (lane >> 2);
            float v00 = (acc[mt][nt][0] + b0) * oscale;
            float v01 = (acc[mt][nt][1] + b1) * oscale;
            float v10 = (acc[mt][nt][2] + b0) * oscale;
            float v11 = (acc[mt][nt][3] + b1) * oscale;
            size_t i0 = (size_t)m * N + n;
            size_t i1 = (size_t)(m + 8) * N + n;
            if (Cf) {
                *(float2*)&Cf[i0] = make_float2(v00, v01);
                *(float2*)&Cf[i1] = make_float2(v10, v11);
            }
            if (Ch) {
                bf16 h0, l0, h1, l1;
                split2(v00, h0, l0); split2(v01, h1, l1);
                *(uint32_t*)&Ch[i0] = pack2(h0, h1);
                *(uint32_t*)&Cl[i0] = pack2(l0, l1);
                split2(v10, h0, l0); split2(v11, h1, l1);
                *(uint32_t*)&Ch[i1] = pack2(h0, h1);
                *(uint32_t*)&Cl[i1] = pack2(l0, l1);
            }
        }
    }
}

// ---------------- fused attention (mma.sync + cp.async) ---------------------------
#define QROWS 16
#define KCH   128
#define SROW  2056
#define KROWS 136     // K stage row stride (bf16)
#define VROW  72
#define QROW  72
#define REDW  68
#define NTHR  512
// smem byte layout
#define A_SH   0
#define A_SL   (A_SH + 16*SROW*2)          // 65792
#define A_U    (A_SL + 16*SROW*2)          // 131584
#define KPL    (64*KROWS*2)                // 17408 per K plane
#define KSTG   (2*KPL)                     // 34816
#define VPL    (128*VROW*2)                // 18432 per V plane
#define VSTG   (2*VPL)                     // 36864
#define A_QSH  (A_U + 2*VSTG)              // 205312
#define A_QSL  (A_QSH + 16*QROW*2)
#define A_RED  (A_QSL + 16*QROW*2)         // 209920
#define A_SINV (A_RED + 16*REDW*4)         // 214272
#define ATTN_SMEM (A_SINV + 64)            // 214336

__global__ __launch_bounds__(NTHR)
void attn_mma(const bf16* __restrict__ Qh, const bf16* __restrict__ Ql,
              const bf16* __restrict__ Kth, const bf16* __restrict__ Ktl,
              const bf16* __restrict__ Vh, const bf16* __restrict__ Vl,
              bf16* __restrict__ ctxH, bf16* __restrict__ ctxL,
              float* __restrict__ meanOut, int writeMean) {
    extern __shared__ char smem_raw[];
    bf16*  Sh   = (bf16*)(smem_raw + A_SH);
    bf16*  Sl   = (bf16*)(smem_raw + A_SL);
    bf16*  Qsh  = (bf16*)(smem_raw + A_QSH);
    bf16*  Qsl  = (bf16*)(smem_raw + A_QSL);
    float* red  = (float*)(smem_raw + A_RED);
    float* sInv = (float*)(smem_raw + A_SINV);

    const int b    = blockIdx.y;
    const int q0   = blockIdx.x * QROWS;
    const int tid  = threadIdx.x;
    const int lane = tid & 31;
    const int wid  = tid >> 5;
    const float invH = 1.0f / HEADS;

    const uint32_t smb   = smem_u32(smem_raw);
    const uint32_t Sh_b  = smb + A_SH, Sl_b = smb + A_SL;
    const uint32_t U_b   = smb + A_U;
    const uint32_t Qsh_b = smb + A_QSH, Qsl_b = smb + A_QSL;

    // per-thread staging indices
    const int kplane = tid >> 8;              // reuse patterns below
    (void)kplane;

    for (int h = 0; h < HEADS; h++) {
        // ---- load Q tile hi/lo
        {
            int row = tid >> 5, c2 = (tid & 31) * 2;
            size_t g = (size_t)(b * SEQ + q0 + row) * EMB + h * HDIM + c2;
            *(uint32_t*)&Qsh[row * QROW + c2] = *(const uint32_t*)&Qh[g];
            *(uint32_t*)&Qsl[row * QROW + c2] = *(const uint32_t*)&Ql[g];
        }
        __syncthreads();

        uint32_t Afh[4][4], Afl[4][4];
#pragma unroll
        for (int ds = 0; ds < 4; ds++) {
            uint32_t off = ((lane & 15) * QROW + ds * 16 + (lane >> 4) * 8) * 2;
            ldsm_x4(Afh[ds][0], Afh[ds][1], Afh[ds][2], Afh[ds][3], Qsh_b + off);
            ldsm_x4(Afl[ds][0], Afl[ds][1], Afl[ds][2], Afl[ds][3], Qsl_b + off);
        }

        // =================== scores (pipelined K staging) ====================
        const bf16* KtHh = Kth + ((size_t)(b * HEADS + h) * HDIM) * SEQ;
        const bf16* KtHl = Ktl + ((size_t)(b * HEADS + h) * HDIM) * SEQ;

        // prefetch chunk 0
        {
#pragma unroll
            for (int i = 0; i < 4; i++) {
                int idx = tid + i * NTHR;             // 2048 u4
                int pl = idx >> 10, rem = idx & 1023;
                int row = rem >> 4, cc = (rem & 15) * 8;
                const bf16* src = pl ? KtHl : KtHh;
                cp_async16(U_b + pl * KPL + (row * KROWS + cc) * 2,
                           src + (size_t)row * SEQ + cc);
            }
            CP_COMMIT();
        }

        const int n0s = wid * 8;
        for (int ci = 0; ci < SEQ / KCH; ci++) {
            const int buf = ci & 1;
            if (ci + 1 < SEQ / KCH) {
                const int nb = buf ^ 1;
                const int kc2 = (ci + 1) * KCH;
#pragma unroll
                for (int i = 0; i < 4; i++) {
                    int idx = tid + i * NTHR;
                    int pl = idx >> 10, rem = idx & 1023;
                    int row = rem >> 4, cc = (rem & 15) * 8;
                    const bf16* src = pl ? KtHl : KtHh;
                    cp_async16(U_b + nb * KSTG + pl * KPL + (row * KROWS + cc) * 2,
                               src + (size_t)row * SEQ + kc2 + cc);
                }
                CP_COMMIT();
                CP_WAIT1();
            } else {
                CP_WAIT0();
            }
            __syncthreads();

            const uint32_t kb = U_b + buf * KSTG;
            float cc[4] = {0.f, 0.f, 0.f, 0.f};
#pragma unroll
            for (int ds = 0; ds < 4; ds++) {
                uint32_t boff = ((ds * 16 + (lane & 15)) * KROWS + n0s) * 2;
                uint32_t bh[2], bl[2];
                ldsm_x2t(bh[0], bh[1], kb + boff);
                ldsm_x2t(bl[0], bl[1], kb + KPL + boff);
                mma_bf16(cc, Afh[ds], bh);
                mma_bf16(cc, Afh[ds], bl);
                mma_bf16(cc, Afl[ds], bh);
            }
            int row = lane >> 2;
            int col = ci * KCH + n0s + (lane & 3) * 2;
            bf16 h0, h1, h2, h3, l0, l1, l2, l3;
            split2(cc[0], h0, l0); split2(cc[1], h1, l1);
            split2(cc[2], h2, l2); split2(cc[3], h3, l3);
            *(uint32_t*)&Sh[row * SROW + col]       = pack2(h0, h1);
            *(uint32_t*)&Sl[row * SROW + col]       = pack2(l0, l1);
            *(uint32_t*)&Sh[(row + 8) * SROW + col] = pack2(h2, h3);
            *(uint32_t*)&Sl[(row + 8) * SROW + col] = pack2(l2, l3);
            __syncthreads();
        }

        // ============ softmax: exp in fp32, store P hi/lo ====================
        {
            const int r = wid;
            float sum = 0.f;
#pragma unroll 2
            for (int it = 0; it < 8; it++) {
                int base = it * 256 + lane * 8;
                uint4 hv = *(uint4*)&Sh[r * SROW + base];
                uint4 lv = *(uint4*)&Sl[r * SROW + base];
                __nv_bfloat162* hp = (__nv_bfloat162*)&hv;
                __nv_bfloat162* lp = (__nv_bfloat162*)&lv;
                uint4 ho, loo;
                uint32_t* hop = (uint32_t*)&ho;
                uint32_t* lop = (uint32_t*)&loo;
#pragma unroll
                for (int p = 0; p < 4; p++) {
                    float2 fh = __bfloat1622float2(hp[p]);
                    float2 fl = __bfloat1622float2(lp[p]);
                    float e0 = fast_exp(fh.x + fl.x);
                    float e1 = fast_exp(fh.y + fl.y);
                    sum += e0 + e1;
                    bf16 eh0, el0, eh1, el1;
                    split2(e0, eh0, el0); split2(e1, eh1, el1);
                    hop[p] = pack2(eh0, eh1);
                    lop[p] = pack2(el0, el1);
                }
                *(uint4*)&Sh[r * SROW + base] = ho;
                *(uint4*)&Sl[r * SROW + base] = loo;
            }
#pragma unroll
            for (int o = 16; o > 0; o >>= 1)
                sum += __shfl_xor_sync(0xffffffffu, sum, o);
            float inv = 1.0f / sum;
            if (lane == 0) sInv[r] = inv;

            if (writeMean) {
                float fac = inv * invH;
                float* mrow = meanOut + ((size_t)b * SEQ + q0 + r) * SEQ;
#pragma unroll 2
                for (int it = 0; it < 8; it++) {
                    int base = it * 256 + lane * 8;
                    uint4 hv = *(uint4*)&Sh[r * SROW + base];
                    uint4 lv = *(uint4*)&Sl[r * SROW + base];
                    __nv_bfloat162* hp = (__nv_bfloat162*)&hv;
                    __nv_bfloat162* lp = (__nv_bfloat162*)&lv;
                    float e[8];
#pragma unroll
                    for (int p = 0; p < 4; p++) {
                        float2 fh = __bfloat1622float2(hp[p]);
                        float2 fl = __bfloat1622float2(lp[p]);
                        e[p * 2]     = fh.x + fl.x;
                        e[p * 2 + 1] = fh.y + fl.y;
                    }
                    if (h == 0) {
                        float4 m0, m1;
                        m0.x = e[0] * fac; m0.y = e[1] * fac;
                        m0.z = e[2] * fac; m0.w = e[3] * fac;
                        m1.x = e[4] * fac; m1.y = e[5] * fac;
                        m1.z = e[6] * fac; m1.w = e[7] * fac;
                        *(float4*)&mrow[base]     = m0;
                        *(float4*)&mrow[base + 4] = m1;
                    } else {
                        float4 m0 = *(const float4*)&mrow[base];
                        float4 m1 = *(const float4*)&mrow[base + 4];
                        m0.x = fmaf(e[0], fac, m0.x); m0.y = fmaf(e[1], fac, m0.y);
                        m0.z = fmaf(e[2], fac, m0.z); m0.w = fmaf(e[3], fac, m0.w);
                        m1.x = fmaf(e[4], fac, m1.x); m1.y = fmaf(e[5], fac, m1.y);
                        m1.z = fmaf(e[6], fac, m1.z); m1.w = fmaf(e[7], fac, m1.w);
                        *(float4*)&mrow[base]     = m0;
                        *(float4*)&mrow[base + 4] = m1;
                    }
                }
            }
        }
        __syncthreads();

        // =================== PV (pipelined V staging) ========================
        const int ntv   = wid & 7;
        const int khalf = wid >> 3;
        const int n0v   = ntv * 8;
        float cc[4] = {0.f, 0.f, 0.f, 0.f};

        const bf16* VbH0 = Vh + (size_t)(b * SEQ) * EMB + h * HDIM;
        const bf16* VbL0 = Vl + (size_t)(b * SEQ) * EMB + h * HDIM;

        // prefetch chunk 0
        {
#pragma unroll
            for (int i = 0; i < 4; i++) {
                int idx = tid + i * NTHR;             // 2048 u4
                int pl = idx >> 10, rem = idx & 1023;
                int row = rem >> 3, c8v = (rem & 7) * 8;
                const bf16* src = pl ? VbL0 : VbH0;
                cp_async16(U_b + pl * VPL + (row * VROW + c8v) * 2,
                           src + (size_t)row * EMB + c8v);
            }
            CP_COMMIT();
        }

        for (int ci = 0; ci < SEQ / KCH; ci++) {
            const int buf = ci & 1;
            if (ci + 1 < SEQ / KCH) {
                const int nb = buf ^ 1;
                const int kc2 = (ci + 1) * KCH;
#pragma unroll
                for (int i = 0; i < 4; i++) {
                    int idx = tid + i * NTHR;
                    int pl = idx >> 10, rem = idx & 1023;
                    int row = rem >> 3, c8v = (rem & 7) * 8;
                    const bf16* src = pl ? VbL0 : VbH0;
                    cp_async16(U_b + nb * VSTG + pl * VPL + (row * VROW + c8v) * 2,
                               src + (size_t)(kc2 + row) * EMB + c8v);
                }
                CP_COMMIT();
                CP_WAIT1();
            } else {
                CP_WAIT0();
            }
            __syncthreads();

            const uint32_t vb = U_b + buf * VSTG;
            const int kc = ci * KCH;
#pragma unroll
            for (int ks = 0; ks < 4; ks++) {
                int kpos = kc + khalf * 64 + ks * 16;
                int krow = khalf * 64 + ks * 16;
                uint32_t aoff = ((lane & 15) * SROW + kpos + (lane >> 4) * 8) * 2;
                uint32_t ah[4], al[4];
                ldsm_x4(ah[0], ah[1], ah[2], ah[3], Sh_b + aoff);
                ldsm_x4(al[0], al[1], al[2], al[3], Sl_b + aoff);
                uint32_t boff = ((krow + (lane & 15)) * VROW + n0v) * 2;
                uint32_t bh[2], bl[2];
                ldsm_x2t(bh[0], bh[1], vb + boff);
                ldsm_x2t(bl[0], bl[1], vb + VPL + boff);
                mma_bf16(cc, ah, bh);
                mma_bf16(cc, ah, bl);
                mma_bf16(cc, al, bh);
            }
            __syncthreads();
        }

        // cross-warp k-half reduction, normalize, store ctx hi/lo
        {
            int row = lane >> 2;
            int col = n0v + (lane & 3) * 2;
            if (khalf == 1) {
                *(float2*)&red[row * REDW + col]       = make_float2(cc[0], cc[1]);
                *(float2*)&red[(row + 8) * REDW + col] = make_float2(cc[2], cc[3]);
            }
            __syncthreads();
            if (khalf == 0) {
                float2 r0 = *(const float2*)&red[row * REDW + col];
                float2 r1 = *(const float2*)&red[(row + 8) * REDW + col];
                float inv0 = sInv[row], inv1 = sInv[row + 8];
                float v00 = (cc[0] + r0.x) * inv0, v01 = (cc[1] + r0.y) * inv0;
                float v10 = (cc[2] + r1.x) * inv1, v11 = (cc[3] + r1.y) * inv1;
                size_t i0 = (size_t)(b * SEQ + q0 + row) * EMB + h * HDIM + col;
                size_t i1 = (size_t)(b * SEQ + q0 + row + 8) * EMB + h * HDIM + col;
                bf16 h0, l0, h1, l1;
                split2(v00, h0, l0); split2(v01, h1, l1);
                *(uint32_t*)&ctxH[i0] = pack2(h0, h1);
                *(uint32_t*)&ctxL[i0] = pack2(l0, l1);
                split2(v10, h0, l0); split2(v11, h1, l1);
                *(uint32_t*)&ctxH[i1] = pack2(h0, h1);
                *(uint32_t*)&ctxL[i1] = pack2(l0, l1);
            }
            __syncthreads();
        }
    }
}

// ---------------- launch ------------------------------------------------------------
extern "C" void kernel_launch(void* const* d_in, const int* in_sizes, int n_in,
                              void* d_out, int out_size) {
    const float* query = (const float*)d_in[0];
    const float* key_  = (const float*)d_in[1];
    const float* value = (const float*)d_in[2];
    const float* Wq = (const float*)d_in[3];
    const float* bq = (const float*)d_in[4];
    const float* Wk = (const float*)d_in[5];
    const float* bk = (const float*)d_in[6];
    const float* Wv = (const float*)d_in[7];
    const float* bv = (const float*)d_in[8];
    const float* Wo = (const float*)d_in[9];
    const float* bo = (const float*)d_in[10];

    float* out = (float*)d_out;
    const size_t outElems  = (size_t)MROWS * EMB;
    const size_t meanElems = (size_t)BATCH * SEQ * SEQ;
    int writeMean = ((size_t)out_size >= outElems + meanElems) ? 1 : 0;
    float* meanOut = out + outElems;

    float *Kb;
    bf16 *Ahb, *Alb, *Whb, *Wlb, *Qhb, *Qlb, *Kthb, *Ktlb, *Vhb, *Vlb;
    cudaGetSymbolAddress((void**)&Kb,   g_K);
    cudaGetSymbolAddress((void**)&Ahb,  g_Ah);
    cudaGetSymbolAddress((void**)&Alb,  g_Al);
    cudaGetSymbolAddress((void**)&Whb,  g_Wh);
    cudaGetSymbolAddress((void**)&Wlb,  g_Wl);
    cudaGetSymbolAddress((void**)&Qhb,  g_Qh);
    cudaGetSymbolAddress((void**)&Qlb,  g_Ql);
    cudaGetSymbolAddress((void**)&Kthb, g_Kth);
    cudaGetSymbolAddress((void**)&Ktlb, g_Ktl);
    cudaGetSymbolAddress((void**)&Vhb,  g_Vh);
    cudaGetSymbolAddress((void**)&Vlb,  g_Vl);

    const int n4_in = MROWS * EMB / 4;
    const int n4_w  = EMB * EMB / 4;
    dim3 ggemm(EMB / 128, MROWS / 128);   // (8, 64)

    cudaFuncSetAttribute(gemm_mma, cudaFuncAttributeMaxDynamicSharedMemorySize,
                         GEMM_SMEM);
    cudaFuncSetAttribute(attn_mma, cudaFuncAttributeMaxDynamicSharedMemorySize,
                         ATTN_SMEM);

    // Q projection -> Qh/Ql (rscale folded)
    split_kernel<<<n4_w / 256, 256>>>(Wq, Whb, Wlb, 1.f, n4_w);
    split_kernel<<<n4_in / 256, 256>>>(query, Ahb, Alb, 1.f, n4_in);
    gemm_mma<<<ggemm, 256, GEMM_SMEM>>>(Ahb, Alb, Whb, Wlb, bq,
                                        nullptr, Qhb, Qlb, 0.125f,
                                        MROWS, EMB, EMB);
    // K projection -> fp32 (transpose consumes it)
    split_kernel<<<n4_w / 256, 256>>>(Wk, Whb, Wlb, 1.f, n4_w);
    split_kernel<<<n4_in / 256, 256>>>(key_, Ahb, Alb, 1.f, n4_in);
    gemm_mma<<<ggemm, 256, GEMM_SMEM>>>(Ahb, Alb, Whb, Wlb, bk,
                                        Kb, nullptr, nullptr, 1.f,
                                        MROWS, EMB, EMB);
    // V projection -> Vh/Vl
    split_kernel<<<n4_w / 256, 256>>>(Wv, Whb, Wlb, 1.f, n4_w);
    split_kernel<<<n4_in / 256, 256>>>(value, Ahb, Alb, 1.f, n4_in);
    gemm_mma<<<ggemm, 256, GEMM_SMEM>>>(Ahb, Alb, Whb, Wlb, bv,
                                        nullptr, Vhb, Vlb, 1.f,
                                        MROWS, EMB, EMB);

    transpose_split_k<<<dim3(SEQ / 64, HEADS, BATCH), 256>>>(Kb, Kthb, Ktlb);

    // attention -> ctx hi/lo into Ah/Al
    attn_mma<<<dim3(SEQ / QROWS, BATCH), NTHR, ATTN_SMEM>>>(
        Qhb, Qlb, Kthb, Ktlb, Vhb, Vlb, Ahb, Alb, meanOut, writeMean);

    // output projection -> fp32 out
    split_kernel<<<n4_w / 256, 256>>>(Wo, Whb, Wlb, 1.f, n4_w);
    gemm_mma<<<ggemm, 256, GEMM_SMEM>>>(Ahb, Alb, Whb, Wlb, bo,
                                        out, nullptr, nullptr, 1.f,
                                        MROWS, EMB, EMB);
}

// round 8
// speedup vs baseline: 13.1247x; 2.0593x over previous
#include <cuda_runtime.h>
#include <cuda_fp16.h>
#include <math.h>
#include <stdint.h>

#define BATCH 4
#define SEQ   2048
#define EMB   1024
#define HEADS 16
#define HDIM  64
#define MROWS (BATCH*SEQ)   // 8192

typedef __half fp16;

// ---------------- scratch ------------------------------------------------------
__device__ fp16 g_A[MROWS*EMB];     // activation fp16 (input convert / ctx)
__device__ fp16 g_W[EMB*EMB];       // weight fp16 (reused per projection)
__device__ fp16 g_Qf[MROWS*EMB];    // Q fp16 (rscale folded)
__device__ fp16 g_Kf[MROWS*EMB];    // K fp16 [b,s,h,d]
__device__ fp16 g_Ktf[MROWS*EMB];   // K^T fp16 [b,h,d,s]
__device__ fp16 g_Vf[MROWS*EMB];    // V fp16

// ---------------- helpers ------------------------------------------------------
__device__ __forceinline__ uint32_t smem_u32(const void* p) {
    return (uint32_t)__cvta_generic_to_shared(p);
}
__device__ __forceinline__ void cp_async16(uint32_t dst, const void* src) {
    asm volatile("cp.async.cg.shared.global [%0], [%1], 16;"
                 :: "r"(dst), "l"(src));
}
#define CP_COMMIT() asm volatile("cp.async.commit_group;" ::: "memory")
#define CP_WAIT1()  asm volatile("cp.async.wait_group 1;" ::: "memory")
#define CP_WAIT0()  asm volatile("cp.async.wait_group 0;" ::: "memory")

__device__ __forceinline__ void ldsm_x4(uint32_t& r0, uint32_t& r1, uint32_t& r2,
                                        uint32_t& r3, uint32_t addr) {
    asm volatile("ldmatrix.sync.aligned.m8n8.x4.shared.b16 {%0,%1,%2,%3}, [%4];"
                 : "=r"(r0), "=r"(r1), "=r"(r2), "=r"(r3) : "r"(addr));
}
__device__ __forceinline__ void ldsm_x2(uint32_t& r0, uint32_t& r1, uint32_t addr) {
    asm volatile("ldmatrix.sync.aligned.m8n8.x2.shared.b16 {%0,%1}, [%2];"
                 : "=r"(r0), "=r"(r1) : "r"(addr));
}
__device__ __forceinline__ void ldsm_x2t(uint32_t& r0, uint32_t& r1, uint32_t addr) {
    asm volatile("ldmatrix.sync.aligned.m8n8.x2.trans.shared.b16 {%0,%1}, [%2];"
                 : "=r"(r0), "=r"(r1) : "r"(addr));
}
__device__ __forceinline__ void mma_f16(float (&c)[4], const uint32_t (&a)[4],
                                        const uint32_t (&b)[2]) {
    asm volatile(
        "mma.sync.aligned.m16n8k16.row.col.f32.f16.f16.f32 "
        "{%0,%1,%2,%3}, {%4,%5,%6,%7}, {%8,%9}, {%0,%1,%2,%3};"
        : "+f"(c[0]), "+f"(c[1]), "+f"(c[2]), "+f"(c[3])
        : "r"(a[0]), "r"(a[1]), "r"(a[2]), "r"(a[3]), "r"(b[0]), "r"(b[1]));
}
__device__ __forceinline__ uint32_t pack2h(fp16 a, fp16 b) {
    __half2 t = __halves2half2(a, b);
    return *(uint32_t*)&t;
}
__device__ __forceinline__ float fast_exp(float x) {
    const float L2E   = 1.4426950408889634f;
    const float MAGIC = 12582912.0f;           // 1.5 * 2^23
    float t = x * L2E;
    float z = t + MAGIC;
    int   i = __float_as_int(z);
    float k = z - MAGIC;
    float f = t - k;
    float p =         1.3333558146e-3f;
    p = fmaf(p, f,    9.6181291076e-3f);
    p = fmaf(p, f,    5.5504108665e-2f);
    p = fmaf(p, f,    2.4022650696e-1f);
    p = fmaf(p, f,    6.9314718056e-1f);
    p = fmaf(p, f,    1.0f);
    float s = __int_as_float((i - 0x4B400000 + 127) << 23);
    return p * s;
}

// ---------------- convert: fp32 -> fp16 (scaled) ---------------------------------
__global__ __launch_bounds__(256)
void cvt_kernel(const float* __restrict__ src, fp16* __restrict__ dst,
                float scale, int n4) {
    int i = blockIdx.x * 256 + threadIdx.x;
    if (i >= n4) return;
    float4 v = ((const float4*)src)[i];
    uint2 o;
    o.x = pack2h(__float2half_rn(v.x * scale), __float2half_rn(v.y * scale));
    o.y = pack2h(__float2half_rn(v.z * scale), __float2half_rn(v.w * scale));
    ((uint2*)dst)[i] = o;
}

// ---------------- K transpose: fp16 [b,s,h,d] -> fp16 [b,h,d,s] -------------------
__global__ __launch_bounds__(256)
void transpose_k(const fp16* __restrict__ K, fp16* __restrict__ Kt) {
    __shared__ fp16 st[64][72];
    const int tid = threadIdx.x;
    const int s0 = blockIdx.x * 64;
    const int h  = blockIdx.y;
    const int b  = blockIdx.z;

#pragma unroll
    for (int i = 0; i < 4; i++) {
        int idx = tid + i * 256;          // 1024 quads of 4 halves
        int ss = idx >> 4, d4 = idx & 15;
        uint2 v = *(const uint2*)&K[((size_t)(b * SEQ + s0 + ss)) * EMB + h * HDIM + d4 * 4];
        *(uint2*)&st[ss][d4 * 4] = v;
    }
    __syncthreads();
#pragma unroll
    for (int i = 0; i < 4; i++) {
        int idx = tid + i * 256;
        int d = idx >> 4, s4 = idx & 15;
        uint2 v;
        v.x = pack2h(st[s4 * 4 + 0][d], st[s4 * 4 + 1][d]);
        v.y = pack2h(st[s4 * 4 + 2][d], st[s4 * 4 + 3][d]);
        *(uint2*)&Kt[((size_t)((b * HEADS + h) * HDIM + d)) * SEQ + s0 + s4 * 4] = v;
    }
}

// ---------------- GEMM (fp16 mma, cp.async 2-stage) --------------------------------
// C = (A @ W^T + bias) * oscale; outputs fp32 (Cf) or fp16 (Ch).
#define GROW 40
#define PL   (128*GROW)       // fp16 per plane (5120)
#define GSTG (2*PL)           // fp16 per stage (A + W)
#define GEMM_SMEM (2*GSTG*2)  // bytes = 40960

__global__ __launch_bounds__(256, 2)
void gemm_hmma(const fp16* __restrict__ A, const fp16* __restrict__ W,
               const float* __restrict__ bias,
               float* __restrict__ Cf, fp16* __restrict__ Ch,
               float oscale, int M, int N, int K) {
    extern __shared__ fp16 gsm[];
    const uint32_t smb = smem_u32(gsm);

    const int tid  = threadIdx.x;
    const int lane = tid & 31;
    const int wid  = tid >> 5;
    const int wm   = wid >> 2;
    const int wn   = wid & 3;
    const int m0 = blockIdx.y * 128;
    const int n0 = blockIdx.x * 128;

    float acc[4][4][4];
#pragma unroll
    for (int i = 0; i < 4; i++)
#pragma unroll
        for (int j = 0; j < 4; j++)
#pragma unroll
            for (int q = 0; q < 4; q++) acc[i][j][q] = 0.f;

    const int r0 = tid >> 2;
    const int c8 = (tid & 3) * 8;

    // prefetch chunk 0
    {
#pragma unroll
        for (int p = 0; p < 2; p++) {
            const fp16* src = p ? W : A;
            const int rb = p ? n0 : m0;
#pragma unroll
            for (int i = 0; i < 2; i++) {
                int row = r0 + i * 64;
                cp_async16(smb + (p * PL + row * GROW + c8) * 2,
                           src + (size_t)(rb + row) * K + c8);
            }
        }
        CP_COMMIT();
    }

    const int NCH = K / 32;
    for (int ch = 0; ch < NCH; ch++) {
        const int buf = ch & 1;
        if (ch + 1 < NCH) {
            const int nb = buf ^ 1;
            const int k0 = (ch + 1) * 32;
#pragma unroll
            for (int p = 0; p < 2; p++) {
                const fp16* src = p ? W : A;
                const int rb = p ? n0 : m0;
#pragma unroll
                for (int i = 0; i < 2; i++) {
                    int row = r0 + i * 64;
                    cp_async16(smb + (nb * GSTG + p * PL + row * GROW + c8) * 2,
                               src + (size_t)(rb + row) * K + k0 + c8);
                }
            }
            CP_COMMIT();
            CP_WAIT1();
        } else {
            CP_WAIT0();
        }
        __syncthreads();

        const uint32_t bA = buf * GSTG;
#pragma unroll
        for (int kk = 0; kk < 2; kk++) {
            uint32_t af[4][4], bf[4][2];
#pragma unroll
            for (int mt = 0; mt < 4; mt++) {
                uint32_t off = (bA + (wm * 64 + mt * 16 + (lane & 15)) * GROW
                                + kk * 16 + (lane >> 4) * 8) * 2;
                ldsm_x4(af[mt][0], af[mt][1], af[mt][2], af[mt][3], smb + off);
            }
#pragma unroll
            for (int nt = 0; nt < 4; nt++) {
                int l = lane & 15;
                uint32_t off = (bA + PL + (wn * 32 + nt * 8 + (l & 7)) * GROW
                                + kk * 16 + ((l >> 3) & 1) * 8) * 2;
                ldsm_x2(bf[nt][0], bf[nt][1], smb + off);
            }
#pragma unroll
            for (int mt = 0; mt < 4; mt++)
#pragma unroll
                for (int nt = 0; nt < 4; nt++)
                    mma_f16(acc[mt][nt], af[mt], bf[nt]);
        }
        __syncthreads();
    }

    // epilogue
#pragma unroll
    for (int nt = 0; nt < 4; nt++) {
        int n = n0 + wn * 32 + nt * 8 + (lane & 3) * 2;
        float b0 = bias[n], b1 = bias[n + 1];
#pragma unroll
        for (int mt = 0; mt < 4; mt++) {
            int m = m0 + wm * 64 + mt * 16 + (lane >> 2);
            float v00 = (acc[mt][nt][0] + b0) * oscale;
            float v01 = (acc[mt][nt][1] + b1) * oscale;
            float v10 = (acc[mt][nt][2] + b0) * oscale;
            float v11 = (acc[mt][nt][3] + b1) * oscale;
            size_t i0 = (size_t)m * N + n;
            size_t i1 = (size_t)(m + 8) * N + n;
            if (Cf) {
                *(float2*)&Cf[i0] = make_float2(v00, v01);
                *(float2*)&Cf[i1] = make_float2(v10, v11);
            }
            if (Ch) {
                *(uint32_t*)&Ch[i0] = pack2h(__float2half_rn(v00), __float2half_rn(v01));
                *(uint32_t*)&Ch[i1] = pack2h(__float2half_rn(v10), __float2half_rn(v11));
            }
        }
    }
}

// ---------------- fused attention (fp16 mma + cp.async) -----------------------------
#define QROWS 16
#define KCH   128
#define SROW  2056
#define KROWS 136
#define VROW  72
#define QROW  72
#define REDW  68
#define NTHR  512
// smem byte layout
#define A_S    0                           // 16*SROW*2 = 65792
#define A_U    65792                       // 2 stages x 18432 = 36864
#define KPL_B  17408                       // 64*KROWS*2 (fits in 18432 slot)
#define STGB   18432
#define A_QS   (A_U + 2*STGB)              // 102656
#define A_RED  (A_QS + 16*QROW*2)          // 104960
#define A_SINV (A_RED + 16*REDW*4)         // 109312
#define ATTN_SMEM (A_SINV + 64)            // 109376

__global__ __launch_bounds__(NTHR, 2)
void attn_hmma(const fp16* __restrict__ Qf, const fp16* __restrict__ Ktf,
               const fp16* __restrict__ Vf,
               fp16* __restrict__ ctx, float* __restrict__ meanOut, int writeMean) {
    extern __shared__ char smem_raw[];
    fp16*  S    = (fp16*)(smem_raw + A_S);
    fp16*  Qs   = (fp16*)(smem_raw + A_QS);
    float* red  = (float*)(smem_raw + A_RED);
    float* sInv = (float*)(smem_raw + A_SINV);

    const int b    = blockIdx.y;
    const int q0   = blockIdx.x * QROWS;
    const int tid  = threadIdx.x;
    const int lane = tid & 31;
    const int wid  = tid >> 5;
    const float invH = 1.0f / HEADS;

    const uint32_t smb  = smem_u32(smem_raw);
    const uint32_t S_b  = smb + A_S;
    const uint32_t U_b  = smb + A_U;
    const uint32_t Qs_b = smb + A_QS;

    for (int h = 0; h < HEADS; h++) {
        // ---- load Q tile
        {
            int row = tid >> 5, c2 = lane * 2;
            size_t g = (size_t)(b * SEQ + q0 + row) * EMB + h * HDIM + c2;
            *(uint32_t*)&Qs[row * QROW + c2] = *(const uint32_t*)&Qf[g];
        }
        __syncthreads();

        uint32_t Af[4][4];
#pragma unroll
        for (int ds = 0; ds < 4; ds++) {
            uint32_t off = ((lane & 15) * QROW + ds * 16 + (lane >> 4) * 8) * 2;
            ldsm_x4(Af[ds][0], Af[ds][1], Af[ds][2], Af[ds][3], Qs_b + off);
        }

        // =================== scores (pipelined K staging) ====================
        const fp16* KtH = Ktf + ((size_t)(b * HEADS + h) * HDIM) * SEQ;

        // prefetch chunk 0
        {
#pragma unroll
            for (int i = 0; i < 2; i++) {
                int idx = tid + i * NTHR;             // 1024 quads
                int row = idx >> 4, cc = (idx & 15) * 8;
                cp_async16(U_b + (row * KROWS + cc) * 2,
                           KtH + (size_t)row * SEQ + cc);
            }
            CP_COMMIT();
        }

        const int n0s = wid * 8;
        for (int ci = 0; ci < SEQ / KCH; ci++) {
            const int buf = ci & 1;
            if (ci + 1 < SEQ / KCH) {
                const int nb = buf ^ 1;
                const int kc2 = (ci + 1) * KCH;
#pragma unroll
                for (int i = 0; i < 2; i++) {
                    int idx = tid + i * NTHR;
                    int row = idx >> 4, cc = (idx & 15) * 8;
                    cp_async16(U_b + nb * STGB + (row * KROWS + cc) * 2,
                               KtH + (size_t)row * SEQ + kc2 + cc);
                }
                CP_COMMIT();
                CP_WAIT1();
            } else {
                CP_WAIT0();
            }
            __syncthreads();

            const uint32_t kb = U_b + buf * STGB;
            float cc[4] = {0.f, 0.f, 0.f, 0.f};
#pragma unroll
            for (int ds = 0; ds < 4; ds++) {
                uint32_t boff = ((ds * 16 + (lane & 15)) * KROWS + n0s) * 2;
                uint32_t bfr[2];
                ldsm_x2t(bfr[0], bfr[1], kb + boff);
                mma_f16(cc, Af[ds], bfr);
            }
            int row = lane >> 2;
            int col = ci * KCH + n0s + (lane & 3) * 2;
            *(uint32_t*)&S[row * SROW + col] =
                pack2h(__float2half_rn(cc[0]), __float2half_rn(cc[1]));
            *(uint32_t*)&S[(row + 8) * SROW + col] =
                pack2h(__float2half_rn(cc[2]), __float2half_rn(cc[3]));
            __syncthreads();
        }

        // ============ softmax: exp fp32, store fp16, sum the rounded values ==
        {
            const int r = wid;
            float sum = 0.f;
#pragma unroll 2
            for (int it = 0; it < 8; it++) {
                int base = it * 256 + lane * 8;
                uint4 hv = *(uint4*)&S[r * SROW + base];
                __half2* hp = (__half2*)&hv;
                uint4 ho;
                uint32_t* hop = (uint32_t*)&ho;
#pragma unroll
                for (int p = 0; p < 4; p++) {
                    float2 f = __half22float2(hp[p]);
                    fp16 e0 = __float2half_rn(fast_exp(f.x));
                    fp16 e1 = __float2half_rn(fast_exp(f.y));
                    sum += __half2float(e0) + __half2float(e1);
                    hop[p] = pack2h(e0, e1);
                }
                *(uint4*)&S[r * SROW + base] = ho;
            }
#pragma unroll
            for (int o = 16; o > 0; o >>= 1)
                sum += __shfl_xor_sync(0xffffffffu, sum, o);
            float inv = 1.0f / sum;
            if (lane == 0) sInv[r] = inv;

            if (writeMean) {
                float fac = inv * invH;
                float* mrow = meanOut + ((size_t)b * SEQ + q0 + r) * SEQ;
#pragma unroll 2
                for (int it = 0; it < 8; it++) {
                    int base = it * 256 + lane * 8;
                    uint4 hv = *(uint4*)&S[r * SROW + base];
                    __half2* hp = (__half2*)&hv;
                    float e[8];
#pragma unroll
                    for (int p = 0; p < 4; p++) {
                        float2 f = __half22float2(hp[p]);
                        e[p * 2]     = f.x;
                        e[p * 2 + 1] = f.y;
                    }
                    if (h == 0) {
                        float4 m0, m1;
                        m0.x = e[0] * fac; m0.y = e[1] * fac;
                        m0.z = e[2] * fac; m0.w = e[3] * fac;
                        m1.x = e[4] * fac; m1.y = e[5] * fac;
                        m1.z = e[6] * fac; m1.w = e[7] * fac;
                        *(float4*)&mrow[base]     = m0;
                        *(float4*)&mrow[base + 4] = m1;
                    } else {
                        float4 m0 = *(const float4*)&mrow[base];
                        float4 m1 = *(const float4*)&mrow[base + 4];
                        m0.x = fmaf(e[0], fac, m0.x); m0.y = fmaf(e[1], fac, m0.y);
                        m0.z = fmaf(e[2], fac, m0.z); m0.w = fmaf(e[3], fac, m0.w);
                        m1.x = fmaf(e[4], fac, m1.x); m1.y = fmaf(e[5], fac, m1.y);
                        m1.z = fmaf(e[6], fac, m1.z); m1.w = fmaf(e[7], fac, m1.w);
                        *(float4*)&mrow[base]     = m0;
                        *(float4*)&mrow[base + 4] = m1;
                    }
                }
            }
        }
        __syncthreads();

        // =================== PV (pipelined V staging) ========================
        const int ntv   = wid & 7;
        const int khalf = wid >> 3;
        const int n0v   = ntv * 8;
        float cc[4] = {0.f, 0.f, 0.f, 0.f};

        const fp16* Vb0 = Vf + (size_t)(b * SEQ) * EMB + h * HDIM;

        // prefetch chunk 0
        {
#pragma unroll
            for (int i = 0; i < 2; i++) {
                int idx = tid + i * NTHR;             // 1024 quads
                int row = idx >> 3, c8v = (idx & 7) * 8;
                cp_async16(U_b + (row * VROW + c8v) * 2,
                           Vb0 + (size_t)row * EMB + c8v);
            }
            CP_COMMIT();
        }

        for (int ci = 0; ci < SEQ / KCH; ci++) {
            const int buf = ci & 1;
            if (ci + 1 < SEQ / KCH) {
                const int nb = buf ^ 1;
                const int kc2 = (ci + 1) * KCH;
#pragma unroll
                for (int i = 0; i < 2; i++) {
                    int idx = tid + i * NTHR;
                    int row = idx >> 3, c8v = (idx & 7) * 8;
                    cp_async16(U_b + nb * STGB + (row * VROW + c8v) * 2,
                               Vb0 + (size_t)(kc2 + row) * EMB + c8v);
                }
                CP_COMMIT();
                CP_WAIT1();
            } else {
                CP_WAIT0();
            }
            __syncthreads();

            const uint32_t vb = U_b + buf * STGB;
            const int kc = ci * KCH;
#pragma unroll
            for (int ks = 0; ks < 4; ks++) {
                int kpos = kc + khalf * 64 + ks * 16;
                int krow = khalf * 64 + ks * 16;
                uint32_t aoff = ((lane & 15) * SROW + kpos + (lane >> 4) * 8) * 2;
                uint32_t af[4];
                ldsm_x4(af[0], af[1], af[2], af[3], S_b + aoff);
                uint32_t boff = ((krow + (lane & 15)) * VROW + n0v) * 2;
                uint32_t bfr[2];
                ldsm_x2t(bfr[0], bfr[1], vb + boff);
                mma_f16(cc, af, bfr);
            }
            __syncthreads();
        }

        // cross-warp k-half reduction, normalize, store ctx fp16
        {
            int row = lane >> 2;
            int col = n0v + (lane & 3) * 2;
            if (khalf == 1) {
                *(float2*)&red[row * REDW + col]       = make_float2(cc[0], cc[1]);
                *(float2*)&red[(row + 8) * REDW + col] = make_float2(cc[2], cc[3]);
            }
            __syncthreads();
            if (khalf == 0) {
                float2 r0 = *(const float2*)&red[row * REDW + col];
                float2 r1 = *(const float2*)&red[(row + 8) * REDW + col];
                float inv0 = sInv[row], inv1 = sInv[row + 8];
                float v00 = (cc[0] + r0.x) * inv0, v01 = (cc[1] + r0.y) * inv0;
                float v10 = (cc[2] + r1.x) * inv1, v11 = (cc[3] + r1.y) * inv1;
                size_t i0 = (size_t)(b * SEQ + q0 + row) * EMB + h * HDIM + col;
                size_t i1 = (size_t)(b * SEQ + q0 + row + 8) * EMB + h * HDIM + col;
                *(uint32_t*)&ctx[i0] = pack2h(__float2half_rn(v00), __float2half_rn(v01));
                *(uint32_t*)&ctx[i1] = pack2h(__float2half_rn(v10), __float2half_rn(v11));
            }
            __syncthreads();
        }
    }
}

// ---------------- launch ------------------------------------------------------------
extern "C" void kernel_launch(void* const* d_in, const int* in_sizes, int n_in,
                              void* d_out, int out_size) {
    const float* query = (const float*)d_in[0];
    const float* key_  = (const float*)d_in[1];
    const float* value = (const float*)d_in[2];
    const float* Wq = (const float*)d_in[3];
    const float* bq = (const float*)d_in[4];
    const float* Wk = (const float*)d_in[5];
    const float* bk = (const float*)d_in[6];
    const float* Wv = (const float*)d_in[7];
    const float* bv = (const float*)d_in[8];
    const float* Wo = (const float*)d_in[9];
    const float* bo = (const float*)d_in[10];

    float* out = (float*)d_out;
    const size_t outElems  = (size_t)MROWS * EMB;
    const size_t meanElems = (size_t)BATCH * SEQ * SEQ;
    int writeMean = ((size_t)out_size >= outElems + meanElems) ? 1 : 0;
    float* meanOut = out + outElems;

    fp16 *Ab, *Wb, *Qfb, *Kfb, *Ktfb, *Vfb;
    cudaGetSymbolAddress((void**)&Ab,   g_A);
    cudaGetSymbolAddress((void**)&Wb,   g_W);
    cudaGetSymbolAddress((void**)&Qfb,  g_Qf);
    cudaGetSymbolAddress((void**)&Kfb,  g_Kf);
    cudaGetSymbolAddress((void**)&Ktfb, g_Ktf);
    cudaGetSymbolAddress((void**)&Vfb,  g_Vf);

    const int n4_in = MROWS * EMB / 4;
    const int n4_w  = EMB * EMB / 4;
    dim3 ggemm(EMB / 128, MROWS / 128);   // (8, 64)

    cudaFuncSetAttribute(gemm_hmma, cudaFuncAttributeMaxDynamicSharedMemorySize,
                         GEMM_SMEM);
    cudaFuncSetAttribute(attn_hmma, cudaFuncAttributeMaxDynamicSharedMemorySize,
                         ATTN_SMEM);

    // Q projection -> Qf (rscale folded)
    cvt_kernel<<<n4_w / 256, 256>>>(Wq, Wb, 1.f, n4_w);
    cvt_kernel<<<n4_in / 256, 256>>>(query, Ab, 1.f, n4_in);
    gemm_hmma<<<ggemm, 256, GEMM_SMEM>>>(Ab, Wb, bq, nullptr, Qfb, 0.125f,
                                         MROWS, EMB, EMB);
    // K projection -> Kf
    cvt_kernel<<<n4_w / 256, 256>>>(Wk, Wb, 1.f, n4_w);
    cvt_kernel<<<n4_in / 256, 256>>>(key_, Ab, 1.f, n4_in);
    gemm_hmma<<<ggemm, 256, GEMM_SMEM>>>(Ab, Wb, bk, nullptr, Kfb, 1.f,
                                         MROWS, EMB, EMB);
    // V projection -> Vf
    cvt_kernel<<<n4_w / 256, 256>>>(Wv, Wb, 1.f, n4_w);
    cvt_kernel<<<n4_in / 256, 256>>>(value, Ab, 1.f, n4_in);
    gemm_hmma<<<ggemm, 256, GEMM_SMEM>>>(Ab, Wb, bv, nullptr, Vfb, 1.f,
                                         MROWS, EMB, EMB);

    transpose_k<<<dim3(SEQ / 64, HEADS, BATCH), 256>>>(Kfb, Ktfb);

    // attention -> ctx fp16 into g_A
    attn_hmma<<<dim3(SEQ / QROWS, BATCH), NTHR, ATTN_SMEM>>>(
        Qfb, Ktfb, Vfb, Ab, meanOut, writeMean);

    // output projection -> fp32 out
    cvt_kernel<<<n4_w / 256, 256>>>(Wo, Wb, 1.f, n4_w);
    gemm_hmma<<<ggemm, 256, GEMM_SMEM>>>(Ab, Wb, bo, out, nullptr, 1.f,
                                         MROWS, EMB, EMB);
}

// round 9
// speedup vs baseline: 13.3106x; 1.0142x over previous
#include <cuda_runtime.h>
#include <cuda_fp16.h>
#include <math.h>
#include <stdint.h>

#define BATCH 4
#define SEQ   2048
#define EMB   1024
#define HEADS 16
#define HDIM  64
#define MROWS (BATCH*SEQ)   // 8192

typedef __half fp16;

// ---------------- scratch ------------------------------------------------------
__device__ fp16 g_A[MROWS*EMB];     // activation fp16 (input convert / ctx)
__device__ fp16 g_W[EMB*EMB];       // weight fp16 (reused per projection)
__device__ fp16 g_Qf[MROWS*EMB];    // Q fp16 (rscale folded), [b,s,h,d]
__device__ fp16 g_Kf[MROWS*EMB];    // K fp16 [b,s,h,d]
__device__ fp16 g_Vf[MROWS*EMB];    // V fp16 [b,s,h,d]

// ---------------- helpers ------------------------------------------------------
__device__ __forceinline__ uint32_t smem_u32(const void* p) {
    return (uint32_t)__cvta_generic_to_shared(p);
}
__device__ __forceinline__ void cp_async16(uint32_t dst, const void* src) {
    asm volatile("cp.async.cg.shared.global [%0], [%1], 16;"
                 :: "r"(dst), "l"(src));
}
#define CP_COMMIT() asm volatile("cp.async.commit_group;" ::: "memory")
#define CP_WAIT1()  asm volatile("cp.async.wait_group 1;" ::: "memory")
#define CP_WAIT0()  asm volatile("cp.async.wait_group 0;" ::: "memory")

__device__ __forceinline__ void ldsm_x4(uint32_t& r0, uint32_t& r1, uint32_t& r2,
                                        uint32_t& r3, uint32_t addr) {
    asm volatile("ldmatrix.sync.aligned.m8n8.x4.shared.b16 {%0,%1,%2,%3}, [%4];"
                 : "=r"(r0), "=r"(r1), "=r"(r2), "=r"(r3) : "r"(addr));
}
__device__ __forceinline__ void ldsm_x2(uint32_t& r0, uint32_t& r1, uint32_t addr) {
    asm volatile("ldmatrix.sync.aligned.m8n8.x2.shared.b16 {%0,%1}, [%2];"
                 : "=r"(r0), "=r"(r1) : "r"(addr));
}
__device__ __forceinline__ void ldsm_x2t(uint32_t& r0, uint32_t& r1, uint32_t addr) {
    asm volatile("ldmatrix.sync.aligned.m8n8.x2.trans.shared.b16 {%0,%1}, [%2];"
                 : "=r"(r0), "=r"(r1) : "r"(addr));
}
__device__ __forceinline__ void mma_f16(float (&c)[4], const uint32_t (&a)[4],
                                        const uint32_t (&b)[2]) {
    asm volatile(
        "mma.sync.aligned.m16n8k16.row.col.f32.f16.f16.f32 "
        "{%0,%1,%2,%3}, {%4,%5,%6,%7}, {%8,%9}, {%0,%1,%2,%3};"
        : "+f"(c[0]), "+f"(c[1]), "+f"(c[2]), "+f"(c[3])
        : "r"(a[0]), "r"(a[1]), "r"(a[2]), "r"(a[3]), "r"(b[0]), "r"(b[1]));
}
__device__ __forceinline__ uint32_t pack2h(fp16 a, fp16 b) {
    __half2 t = __halves2half2(a, b);
    return *(uint32_t*)&t;
}
__device__ __forceinline__ float fast_exp(float x) {
    const float L2E   = 1.4426950408889634f;
    const float MAGIC = 12582912.0f;           // 1.5 * 2^23
    float t = x * L2E;
    float z = t + MAGIC;
    int   i = __float_as_int(z);
    float k = z - MAGIC;
    float f = t - k;
    float p =         1.3333558146e-3f;
    p = fmaf(p, f,    9.6181291076e-3f);
    p = fmaf(p, f,    5.5504108665e-2f);
    p = fmaf(p, f,    2.4022650696e-1f);
    p = fmaf(p, f,    6.9314718056e-1f);
    p = fmaf(p, f,    1.0f);
    float s = __int_as_float((i - 0x4B400000 + 127) << 23);
    return p * s;
}

// ---------------- convert: fp32 -> fp16 (scaled) ---------------------------------
__global__ __launch_bounds__(256)
void cvt_kernel(const float* __restrict__ src, fp16* __restrict__ dst,
                float scale, int n4) {
    int i = blockIdx.x * 256 + threadIdx.x;
    if (i >= n4) return;
    float4 v = ((const float4*)src)[i];
    uint2 o;
    o.x = pack2h(__float2half_rn(v.x * scale), __float2half_rn(v.y * scale));
    o.y = pack2h(__float2half_rn(v.z * scale), __float2half_rn(v.w * scale));
    ((uint2*)dst)[i] = o;
}

// ---------------- GEMM (fp16 mma, cp.async 2-stage) --------------------------------
#define GROW 40
#define PL   (128*GROW)
#define GSTG (2*PL)
#define GEMM_SMEM (2*GSTG*2)  // 40960

__global__ __launch_bounds__(256, 2)
void gemm_hmma(const fp16* __restrict__ A, const fp16* __restrict__ W,
               const float* __restrict__ bias,
               float* __restrict__ Cf, fp16* __restrict__ Ch,
               float oscale, int M, int N, int K) {
    extern __shared__ fp16 gsm[];
    const uint32_t smb = smem_u32(gsm);

    const int tid  = threadIdx.x;
    const int lane = tid & 31;
    const int wid  = tid >> 5;
    const int wm   = wid >> 2;
    const int wn   = wid & 3;
    const int m0 = blockIdx.y * 128;
    const int n0 = blockIdx.x * 128;

    float acc[4][4][4];
#pragma unroll
    for (int i = 0; i < 4; i++)
#pragma unroll
        for (int j = 0; j < 4; j++)
#pragma unroll
            for (int q = 0; q < 4; q++) acc[i][j][q] = 0.f;

    const int r0 = tid >> 2;
    const int c8 = (tid & 3) * 8;

    {
#pragma unroll
        for (int p = 0; p < 2; p++) {
            const fp16* src = p ? W : A;
            const int rb = p ? n0 : m0;
#pragma unroll
            for (int i = 0; i < 2; i++) {
                int row = r0 + i * 64;
                cp_async16(smb + (p * PL + row * GROW + c8) * 2,
                           src + (size_t)(rb + row) * K + c8);
            }
        }
        CP_COMMIT();
    }

    const int NCH = K / 32;
    for (int ch = 0; ch < NCH; ch++) {
        const int buf = ch & 1;
        if (ch + 1 < NCH) {
            const int nb = buf ^ 1;
            const int k0 = (ch + 1) * 32;
#pragma unroll
            for (int p = 0; p < 2; p++) {
                const fp16* src = p ? W : A;
                const int rb = p ? n0 : m0;
#pragma unroll
                for (int i = 0; i < 2; i++) {
                    int row = r0 + i * 64;
                    cp_async16(smb + (nb * GSTG + p * PL + row * GROW + c8) * 2,
                               src + (size_t)(rb + row) * K + k0 + c8);
                }
            }
            CP_COMMIT();
            CP_WAIT1();
        } else {
            CP_WAIT0();
        }
        __syncthreads();

        const uint32_t bA = buf * GSTG;
#pragma unroll
        for (int kk = 0; kk < 2; kk++) {
            uint32_t af[4][4], bf[4][2];
#pragma unroll
            for (int mt = 0; mt < 4; mt++) {
                uint32_t off = (bA + (wm * 64 + mt * 16 + (lane & 15)) * GROW
                                + kk * 16 + (lane >> 4) * 8) * 2;
                ldsm_x4(af[mt][0], af[mt][1], af[mt][2], af[mt][3], smb + off);
            }
#pragma unroll
            for (int nt = 0; nt < 4; nt++) {
                int l = lane & 15;
                uint32_t off = (bA + PL + (wn * 32 + nt * 8 + (l & 7)) * GROW
                                + kk * 16 + ((l >> 3) & 1) * 8) * 2;
                ldsm_x2(bf[nt][0], bf[nt][1], smb + off);
            }
#pragma unroll
            for (int mt = 0; mt < 4; mt++)
#pragma unroll
                for (int nt = 0; nt < 4; nt++)
                    mma_f16(acc[mt][nt], af[mt], bf[nt]);
        }
        __syncthreads();
    }

#pragma unroll
    for (int nt = 0; nt < 4; nt++) {
        int n = n0 + wn * 32 + nt * 8 + (lane & 3) * 2;
        float b0 = bias[n], b1 = bias[n + 1];
#pragma unroll
        for (int mt = 0; mt < 4; mt++) {
            int m = m0 + wm * 64 + mt * 16 + (lane >> 2);
            float v00 = (acc[mt][nt][0] + b0) * oscale;
            float v01 = (acc[mt][nt][1] + b1) * oscale;
            float v10 = (acc[mt][nt][2] + b0) * oscale;
            float v11 = (acc[mt][nt][3] + b1) * oscale;
            size_t i0 = (size_t)m * N + n;
            size_t i1 = (size_t)(m + 8) * N + n;
            if (Cf) {
                *(float2*)&Cf[i0] = make_float2(v00, v01);
                *(float2*)&Cf[i1] = make_float2(v10, v11);
            }
            if (Ch) {
                *(uint32_t*)&Ch[i0] = pack2h(__float2half_rn(v00), __float2half_rn(v01));
                *(uint32_t*)&Ch[i1] = pack2h(__float2half_rn(v10), __float2half_rn(v11));
            }
        }
    }
}

// ---------------- fused attention (fp16 mma, register-resident mean) ---------------
#define QROWS 16
#define KCH   256
#define SROW  2056
#define KROWS 72      // staging row stride (halves): 64 data + 8 pad
#define QROW  72
#define REDW  68
#define NTHR  512
// smem byte layout
#define A_S    0                           // 16*SROW*2 = 65792
#define A_U    65792                       // 2 stages x 36864 = 73728
#define STGB   (KCH*KROWS*2)               // 36864
#define A_QS   (A_U + 2*STGB)              // 139520
#define A_RED  (A_QS + 16*QROW*2)          // 141824
#define A_SINV (A_RED + 16*REDW*4)         // 146176
#define ATTN_SMEM (A_SINV + 64)            // 146240

__global__ __launch_bounds__(NTHR, 1)
void attn_hmma(const fp16* __restrict__ Qf, const fp16* __restrict__ Kf,
               const fp16* __restrict__ Vf,
               fp16* __restrict__ ctx, float* __restrict__ meanOut, int writeMean) {
    extern __shared__ char smem_raw[];
    fp16*  S    = (fp16*)(smem_raw + A_S);
    fp16*  Qs   = (fp16*)(smem_raw + A_QS);
    float* red  = (float*)(smem_raw + A_RED);
    float* sInv = (float*)(smem_raw + A_SINV);

    const int b    = blockIdx.y;
    const int q0   = blockIdx.x * QROWS;
    const int tid  = threadIdx.x;
    const int lane = tid & 31;
    const int wid  = tid >> 5;
    const float invH = 1.0f / HEADS;

    const uint32_t smb  = smem_u32(smem_raw);
    const uint32_t S_b  = smb + A_S;
    const uint32_t U_b  = smb + A_U;
    const uint32_t Qs_b = smb + A_QS;

    // register-resident mean accumulator: warp = row wid, lane covers cols
    // {it*256 + lane*8 + j : it in 0..7, j in 0..7}
    float meanAcc[64];
#pragma unroll
    for (int i = 0; i < 64; i++) meanAcc[i] = 0.f;

    for (int h = 0; h < HEADS; h++) {
        // ---- load Q tile [16][64]
        {
            int row = tid >> 5, c2 = lane * 2;
            size_t g = (size_t)(b * SEQ + q0 + row) * EMB + h * HDIM + c2;
            *(uint32_t*)&Qs[row * QROW + c2] = *(const uint32_t*)&Qf[g];
        }
        __syncthreads();

        uint32_t Af[4][4];
#pragma unroll
        for (int ds = 0; ds < 4; ds++) {
            uint32_t off = ((lane & 15) * QROW + ds * 16 + (lane >> 4) * 8) * 2;
            ldsm_x4(Af[ds][0], Af[ds][1], Af[ds][2], Af[ds][3], Qs_b + off);
        }

        // =================== scores: S = Q @ K^T (K row-major [s,d]) =========
        const fp16* Kb0 = Kf + (size_t)(b * SEQ) * EMB + h * HDIM;

        // prefetch chunk 0: 256 rows x 64 halves
        {
#pragma unroll
            for (int i = 0; i < 4; i++) {
                int idx = tid + i * NTHR;             // 2048 quads
                int row = idx >> 3, q8 = (idx & 7) * 8;
                cp_async16(U_b + (row * KROWS + q8) * 2,
                           Kb0 + (size_t)row * EMB + q8);
            }
            CP_COMMIT();
        }

        for (int ci = 0; ci < SEQ / KCH; ci++) {
            const int buf = ci & 1;
            if (ci + 1 < SEQ / KCH) {
                const int nb = buf ^ 1;
                const int kc2 = (ci + 1) * KCH;
#pragma unroll
                for (int i = 0; i < 4; i++) {
                    int idx = tid + i * NTHR;
                    int row = idx >> 3, q8 = (idx & 7) * 8;
                    cp_async16(U_b + nb * STGB + (row * KROWS + q8) * 2,
                               Kb0 + (size_t)(kc2 + row) * EMB + q8);
                }
                CP_COMMIT();
                CP_WAIT1();
            } else {
                CP_WAIT0();
            }
            __syncthreads();

            const uint32_t kb = U_b + buf * STGB;
            const int l = lane & 15;
#pragma unroll
            for (int nt = 0; nt < 2; nt++) {
                float cc[4] = {0.f, 0.f, 0.f, 0.f};
#pragma unroll
                for (int ds = 0; ds < 4; ds++) {
                    uint32_t boff = ((wid * 16 + nt * 8 + (l & 7)) * KROWS
                                     + ds * 16 + ((l >> 3) & 1) * 8) * 2;
                    uint32_t bfr[2];
                    ldsm_x2(bfr[0], bfr[1], kb + boff);
                    mma_f16(cc, Af[ds], bfr);
                }
                int row = lane >> 2;
                int col = ci * KCH + wid * 16 + nt * 8 + (lane & 3) * 2;
                *(uint32_t*)&S[row * SROW + col] =
                    pack2h(__float2half_rn(cc[0]), __float2half_rn(cc[1]));
                *(uint32_t*)&S[(row + 8) * SROW + col] =
                    pack2h(__float2half_rn(cc[2]), __float2half_rn(cc[3]));
            }
            __syncthreads();
        }

        // ============ softmax: exp fp32 -> fp16, sum rounded; mean in regs ===
        {
            const int r = wid;
            float sum = 0.f;
#pragma unroll
            for (int it = 0; it < 8; it++) {
                int base = it * 256 + lane * 8;
                uint4 hv = *(uint4*)&S[r * SROW + base];
                __half2* hp = (__half2*)&hv;
                uint4 ho;
                uint32_t* hop = (uint32_t*)&ho;
#pragma unroll
                for (int p = 0; p < 4; p++) {
                    float2 f = __half22float2(hp[p]);
                    fp16 e0 = __float2half_rn(fast_exp(f.x));
                    fp16 e1 = __float2half_rn(fast_exp(f.y));
                    sum += __half2float(e0) + __half2float(e1);
                    hop[p] = pack2h(e0, e1);
                }
                *(uint4*)&S[r * SROW + base] = ho;
            }
#pragma unroll
            for (int o = 16; o > 0; o >>= 1)
                sum += __shfl_xor_sync(0xffffffffu, sum, o);
            float inv = 1.0f / sum;
            if (lane == 0) sInv[r] = inv;

            // accumulate mean into registers (reload rounded exp from smem)
            float fac = inv * invH;
#pragma unroll
            for (int it = 0; it < 8; it++) {
                int base = it * 256 + lane * 8;
                uint4 hv = *(uint4*)&S[r * SROW + base];
                __half2* hp = (__half2*)&hv;
#pragma unroll
                for (int p = 0; p < 4; p++) {
                    float2 f = __half22float2(hp[p]);
                    meanAcc[it * 8 + p * 2]     = fmaf(f.x, fac, meanAcc[it * 8 + p * 2]);
                    meanAcc[it * 8 + p * 2 + 1] = fmaf(f.y, fac, meanAcc[it * 8 + p * 2 + 1]);
                }
            }
        }
        __syncthreads();

        // =================== PV: ctx = (P @ V) * inv =========================
        const int ntv   = wid & 7;
        const int khalf = wid >> 3;
        const int n0v   = ntv * 8;
        float cc[4] = {0.f, 0.f, 0.f, 0.f};

        const fp16* Vb0 = Vf + (size_t)(b * SEQ) * EMB + h * HDIM;

        {
#pragma unroll
            for (int i = 0; i < 4; i++) {
                int idx = tid + i * NTHR;             // 2048 quads
                int row = idx >> 3, q8 = (idx & 7) * 8;
                cp_async16(U_b + (row * KROWS + q8) * 2,
                           Vb0 + (size_t)row * EMB + q8);
            }
            CP_COMMIT();
        }

        for (int ci = 0; ci < SEQ / KCH; ci++) {
            const int buf = ci & 1;
            if (ci + 1 < SEQ / KCH) {
                const int nb = buf ^ 1;
                const int kc2 = (ci + 1) * KCH;
#pragma unroll
                for (int i = 0; i < 4; i++) {
                    int idx = tid + i * NTHR;
                    int row = idx >> 3, q8 = (idx & 7) * 8;
                    cp_async16(U_b + nb * STGB + (row * KROWS + q8) * 2,
                               Vb0 + (size_t)(kc2 + row) * EMB + q8);
                }
                CP_COMMIT();
                CP_WAIT1();
            } else {
                CP_WAIT0();
            }
            __syncthreads();

            const uint32_t vb = U_b + buf * STGB;
            const int kc = ci * KCH;
#pragma unroll
            for (int ks = 0; ks < 8; ks++) {
                int kpos = kc + khalf * 128 + ks * 16;
                int krow = khalf * 128 + ks * 16;
                uint32_t aoff = ((lane & 15) * SROW + kpos + (lane >> 4) * 8) * 2;
                uint32_t af[4];
                ldsm_x4(af[0], af[1], af[2], af[3], S_b + aoff);
                uint32_t boff = ((krow + (lane & 15)) * KROWS + n0v) * 2;
                uint32_t bfr[2];
                ldsm_x2t(bfr[0], bfr[1], vb + boff);
                mma_f16(cc, af, bfr);
            }
            __syncthreads();
        }

        // cross-warp k-half reduction, normalize, store ctx fp16
        {
            int row = lane >> 2;
            int col = n0v + (lane & 3) * 2;
            if (khalf == 1) {
                *(float2*)&red[row * REDW + col]       = make_float2(cc[0], cc[1]);
                *(float2*)&red[(row + 8) * REDW + col] = make_float2(cc[2], cc[3]);
            }
            __syncthreads();
            if (khalf == 0) {
                float2 r0 = *(const float2*)&red[row * REDW + col];
                float2 r1 = *(const float2*)&red[(row + 8) * REDW + col];
                float inv0 = sInv[row], inv1 = sInv[row + 8];
                float v00 = (cc[0] + r0.x) * inv0, v01 = (cc[1] + r0.y) * inv0;
                float v10 = (cc[2] + r1.x) * inv1, v11 = (cc[3] + r1.y) * inv1;
                size_t i0 = (size_t)(b * SEQ + q0 + row) * EMB + h * HDIM + col;
                size_t i1 = (size_t)(b * SEQ + q0 + row + 8) * EMB + h * HDIM + col;
                *(uint32_t*)&ctx[i0] = pack2h(__float2half_rn(v00), __float2half_rn(v01));
                *(uint32_t*)&ctx[i1] = pack2h(__float2half_rn(v10), __float2half_rn(v11));
            }
            __syncthreads();
        }
    }

    // ---- final mean write (once, coalesced) ----
    if (writeMean) {
        float* mrow = meanOut + ((size_t)b * SEQ + q0 + wid) * SEQ;
#pragma unroll
        for (int it = 0; it < 8; it++) {
            int base = it * 256 + lane * 8;
            float4 m0 = make_float4(meanAcc[it * 8 + 0], meanAcc[it * 8 + 1],
                                    meanAcc[it * 8 + 2], meanAcc[it * 8 + 3]);
            float4 m1 = make_float4(meanAcc[it * 8 + 4], meanAcc[it * 8 + 5],
                                    meanAcc[it * 8 + 6], meanAcc[it * 8 + 7]);
            *(float4*)&mrow[base]     = m0;
            *(float4*)&mrow[base + 4] = m1;
        }
    }
}

// ---------------- launch ------------------------------------------------------------
extern "C" void kernel_launch(void* const* d_in, const int* in_sizes, int n_in,
                              void* d_out, int out_size) {
    const float* query = (const float*)d_in[0];
    const float* key_  = (const float*)d_in[1];
    const float* value = (const float*)d_in[2];
    const float* Wq = (const float*)d_in[3];
    const float* bq = (const float*)d_in[4];
    const float* Wk = (const float*)d_in[5];
    const float* bk = (const float*)d_in[6];
    const float* Wv = (const float*)d_in[7];
    const float* bv = (const float*)d_in[8];
    const float* Wo = (const float*)d_in[9];
    const float* bo = (const float*)d_in[10];

    float* out = (float*)d_out;
    const size_t outElems  = (size_t)MROWS * EMB;
    const size_t meanElems = (size_t)BATCH * SEQ * SEQ;
    int writeMean = ((size_t)out_size >= outElems + meanElems) ? 1 : 0;
    float* meanOut = out + outElems;

    fp16 *Ab, *Wb, *Qfb, *Kfb, *Vfb;
    cudaGetSymbolAddress((void**)&Ab,  g_A);
    cudaGetSymbolAddress((void**)&Wb,  g_W);
    cudaGetSymbolAddress((void**)&Qfb, g_Qf);
    cudaGetSymbolAddress((void**)&Kfb, g_Kf);
    cudaGetSymbolAddress((void**)&Vfb, g_Vf);

    const int n4_in = MROWS * EMB / 4;
    const int n4_w  = EMB * EMB / 4;
    dim3 ggemm(EMB / 128, MROWS / 128);   // (8, 64)

    cudaFuncSetAttribute(gemm_hmma, cudaFuncAttributeMaxDynamicSharedMemorySize,
                         GEMM_SMEM);
    cudaFuncSetAttribute(attn_hmma, cudaFuncAttributeMaxDynamicSharedMemorySize,
                         ATTN_SMEM);

    // Q projection -> Qf (rscale folded)
    cvt_kernel<<<n4_w / 256, 256>>>(Wq, Wb, 1.f, n4_w);
    cvt_kernel<<<n4_in / 256, 256>>>(query, Ab, 1.f, n4_in);
    gemm_hmma<<<ggemm, 256, GEMM_SMEM>>>(Ab, Wb, bq, nullptr, Qfb, 0.125f,
                                         MROWS, EMB, EMB);
    // K projection -> Kf
    cvt_kernel<<<n4_w / 256, 256>>>(Wk, Wb, 1.f, n4_w);
    cvt_kernel<<<n4_in / 256, 256>>>(key_, Ab, 1.f, n4_in);
    gemm_hmma<<<ggemm, 256, GEMM_SMEM>>>(Ab, Wb, bk, nullptr, Kfb, 1.f,
                                         MROWS, EMB, EMB);
    // V projection -> Vf
    cvt_kernel<<<n4_w / 256, 256>>>(Wv, Wb, 1.f, n4_w);
    cvt_kernel<<<n4_in / 256, 256>>>(value, Ab, 1.f, n4_in);
    gemm_hmma<<<ggemm, 256, GEMM_SMEM>>>(Ab, Wb, bv, nullptr, Vfb, 1.f,
                                         MROWS, EMB, EMB);

    // attention -> ctx fp16 into g_A, mean accumulated in registers
    attn_hmma<<<dim3(SEQ / QROWS, BATCH), NTHR, ATTN_SMEM>>>(
        Qfb, Kfb, Vfb, Ab, meanOut, writeMean);

    // output projection -> fp32 out
    cvt_kernel<<<n4_w / 256, 256>>>(Wo, Wb, 1.f, n4_w);
    gemm_hmma<<<ggemm, 256, GEMM_SMEM>>>(Ab, Wb, bo, out, nullptr, 1.f,
                                         MROWS, EMB, EMB);
}

// round 10
// speedup vs baseline: 14.6175x; 1.0982x over previous
#include <cuda_runtime.h>
#include <cuda_fp16.h>
#include <math.h>
#include <stdint.h>

#define BATCH 4
#define SEQ   2048
#define EMB   1024
#define HEADS 16
#define HDIM  64
#define MROWS (BATCH*SEQ)   // 8192

typedef __half fp16;

// ---------------- scratch ------------------------------------------------------
__device__ fp16 g_A[MROWS*EMB];     // activation fp16 (input convert / ctx)
__device__ fp16 g_W[EMB*EMB];       // weight fp16 (reused per projection)
__device__ fp16 g_Qf[MROWS*EMB];    // Q fp16 (rscale folded), [b,s,h,d]
__device__ fp16 g_Kf[MROWS*EMB];    // K fp16 [b,s,h,d]
__device__ fp16 g_Vf[MROWS*EMB];    // V fp16 [b,s,h,d]

// ---------------- helpers ------------------------------------------------------
__device__ __forceinline__ uint32_t smem_u32(const void* p) {
    return (uint32_t)__cvta_generic_to_shared(p);
}
__device__ __forceinline__ void cp_async16(uint32_t dst, const void* src) {
    asm volatile("cp.async.cg.shared.global [%0], [%1], 16;"
                 :: "r"(dst), "l"(src));
}
#define CP_COMMIT() asm volatile("cp.async.commit_group;" ::: "memory")
#define CP_WAIT1()  asm volatile("cp.async.wait_group 1;" ::: "memory")
#define CP_WAIT0()  asm volatile("cp.async.wait_group 0;" ::: "memory")

__device__ __forceinline__ void ldsm_x4(uint32_t& r0, uint32_t& r1, uint32_t& r2,
                                        uint32_t& r3, uint32_t addr) {
    asm volatile("ldmatrix.sync.aligned.m8n8.x4.shared.b16 {%0,%1,%2,%3}, [%4];"
                 : "=r"(r0), "=r"(r1), "=r"(r2), "=r"(r3) : "r"(addr));
}
__device__ __forceinline__ void ldsm_x2(uint32_t& r0, uint32_t& r1, uint32_t addr) {
    asm volatile("ldmatrix.sync.aligned.m8n8.x2.shared.b16 {%0,%1}, [%2];"
                 : "=r"(r0), "=r"(r1) : "r"(addr));
}
__device__ __forceinline__ void ldsm_x2t(uint32_t& r0, uint32_t& r1, uint32_t addr) {
    asm volatile("ldmatrix.sync.aligned.m8n8.x2.trans.shared.b16 {%0,%1}, [%2];"
                 : "=r"(r0), "=r"(r1) : "r"(addr));
}
__device__ __forceinline__ void mma_f16(float (&c)[4], const uint32_t (&a)[4],
                                        const uint32_t (&b)[2]) {
    asm volatile(
        "mma.sync.aligned.m16n8k16.row.col.f32.f16.f16.f32 "
        "{%0,%1,%2,%3}, {%4,%5,%6,%7}, {%8,%9}, {%0,%1,%2,%3};"
        : "+f"(c[0]), "+f"(c[1]), "+f"(c[2]), "+f"(c[3])
        : "r"(a[0]), "r"(a[1]), "r"(a[2]), "r"(a[3]), "r"(b[0]), "r"(b[1]));
}
__device__ __forceinline__ uint32_t pack2h(fp16 a, fp16 b) {
    __half2 t = __halves2half2(a, b);
    return *(uint32_t*)&t;
}
__device__ __forceinline__ float fast_exp(float x) {
    const float L2E   = 1.4426950408889634f;
    const float MAGIC = 12582912.0f;           // 1.5 * 2^23
    float t = x * L2E;
    float z = t + MAGIC;
    int   i = __float_as_int(z);
    float k = z - MAGIC;
    float f = t - k;
    float p =         1.3333558146e-3f;
    p = fmaf(p, f,    9.6181291076e-3f);
    p = fmaf(p, f,    5.5504108665e-2f);
    p = fmaf(p, f,    2.4022650696e-1f);
    p = fmaf(p, f,    6.9314718056e-1f);
    p = fmaf(p, f,    1.0f);
    float s = __int_as_float((i - 0x4B400000 + 127) << 23);
    return p * s;
}

// ---------------- convert: fp32 -> fp16 (scaled) ---------------------------------
__global__ __launch_bounds__(256)
void cvt_kernel(const float* __restrict__ src, fp16* __restrict__ dst,
                float scale, int n4) {
    int i = blockIdx.x * 256 + threadIdx.x;
    if (i >= n4) return;
    float4 v = ((const float4*)src)[i];
    uint2 o;
    o.x = pack2h(__float2half_rn(v.x * scale), __float2half_rn(v.y * scale));
    o.y = pack2h(__float2half_rn(v.z * scale), __float2half_rn(v.w * scale));
    ((uint2*)dst)[i] = o;
}

// ---------------- GEMM (fp16 mma, cp.async 2-stage) --------------------------------
#define GROW 40
#define PL   (128*GROW)
#define GSTG (2*PL)
#define GEMM_SMEM (2*GSTG*2)  // 40960

__global__ __launch_bounds__(256, 2)
void gemm_hmma(const fp16* __restrict__ A, const fp16* __restrict__ W,
               const float* __restrict__ bias,
               float* __restrict__ Cf, fp16* __restrict__ Ch,
               float oscale, int M, int N, int K) {
    extern __shared__ fp16 gsm[];
    const uint32_t smb = smem_u32(gsm);

    const int tid  = threadIdx.x;
    const int lane = tid & 31;
    const int wid  = tid >> 5;
    const int wm   = wid >> 2;
    const int wn   = wid & 3;
    const int m0 = blockIdx.y * 128;
    const int n0 = blockIdx.x * 128;

    float acc[4][4][4];
#pragma unroll
    for (int i = 0; i < 4; i++)
#pragma unroll
        for (int j = 0; j < 4; j++)
#pragma unroll
            for (int q = 0; q < 4; q++) acc[i][j][q] = 0.f;

    const int r0 = tid >> 2;
    const int c8 = (tid & 3) * 8;

    {
#pragma unroll
        for (int p = 0; p < 2; p++) {
            const fp16* src = p ? W : A;
            const int rb = p ? n0 : m0;
#pragma unroll
            for (int i = 0; i < 2; i++) {
                int row = r0 + i * 64;
                cp_async16(smb + (p * PL + row * GROW + c8) * 2,
                           src + (size_t)(rb + row) * K + c8);
            }
        }
        CP_COMMIT();
    }

    const int NCH = K / 32;
    for (int ch = 0; ch < NCH; ch++) {
        const int buf = ch & 1;
        if (ch + 1 < NCH) {
            const int nb = buf ^ 1;
            const int k0 = (ch + 1) * 32;
#pragma unroll
            for (int p = 0; p < 2; p++) {
                const fp16* src = p ? W : A;
                const int rb = p ? n0 : m0;
#pragma unroll
                for (int i = 0; i < 2; i++) {
                    int row = r0 + i * 64;
                    cp_async16(smb + (nb * GSTG + p * PL + row * GROW + c8) * 2,
                               src + (size_t)(rb + row) * K + k0 + c8);
                }
            }
            CP_COMMIT();
            CP_WAIT1();
        } else {
            CP_WAIT0();
        }
        __syncthreads();

        const uint32_t bA = buf * GSTG;
#pragma unroll
        for (int kk = 0; kk < 2; kk++) {
            uint32_t af[4][4], bf[4][2];
#pragma unroll
            for (int mt = 0; mt < 4; mt++) {
                uint32_t off = (bA + (wm * 64 + mt * 16 + (lane & 15)) * GROW
                                + kk * 16 + (lane >> 4) * 8) * 2;
                ldsm_x4(af[mt][0], af[mt][1], af[mt][2], af[mt][3], smb + off);
            }
#pragma unroll
            for (int nt = 0; nt < 4; nt++) {
                int l = lane & 15;
                uint32_t off = (bA + PL + (wn * 32 + nt * 8 + (l & 7)) * GROW
                                + kk * 16 + ((l >> 3) & 1) * 8) * 2;
                ldsm_x2(bf[nt][0], bf[nt][1], smb + off);
            }
#pragma unroll
            for (int mt = 0; mt < 4; mt++)
#pragma unroll
                for (int nt = 0; nt < 4; nt++)
                    mma_f16(acc[mt][nt], af[mt], bf[nt]);
        }
        __syncthreads();
    }

#pragma unroll
    for (int nt = 0; nt < 4; nt++) {
        int n = n0 + wn * 32 + nt * 8 + (lane & 3) * 2;
        float b0 = bias[n], b1 = bias[n + 1];
#pragma unroll
        for (int mt = 0; mt < 4; mt++) {
            int m = m0 + wm * 64 + mt * 16 + (lane >> 2);
            float v00 = (acc[mt][nt][0] + b0) * oscale;
            float v01 = (acc[mt][nt][1] + b1) * oscale;
            float v10 = (acc[mt][nt][2] + b0) * oscale;
            float v11 = (acc[mt][nt][3] + b1) * oscale;
            size_t i0 = (size_t)m * N + n;
            size_t i1 = (size_t)(m + 8) * N + n;
            if (Cf) {
                *(float2*)&Cf[i0] = make_float2(v00, v01);
                *(float2*)&Cf[i1] = make_float2(v10, v11);
            }
            if (Ch) {
                *(uint32_t*)&Ch[i0] = pack2h(__float2half_rn(v00), __float2half_rn(v01));
                *(uint32_t*)&Ch[i1] = pack2h(__float2half_rn(v10), __float2half_rn(v11));
            }
        }
    }
}

// ---------------- fused attention (fp16 mma, QROWS=32) ------------------------------
#define QROWS 32
#define KCH   256
#define SROW  2056
#define KROWS 72      // staging row stride (halves): 64 data + 8 pad
#define QROW  72
#define REDW  68
#define NTHR  512
// smem byte layout
#define A_S    0                           // 32*SROW*2 = 131584
#define A_U    131584                      // 2 stages x 36864 = 73728
#define STGB   (KCH*KROWS*2)               // 36864
#define A_QS   (A_U + 2*STGB)              // 205312; Qs 32*72*2 = 4608
#define A_RED  (A_QS + 32*QROW*2)          // 209920; red 32*68*4 = 8704
#define A_SINV (A_RED + 32*REDW*4)         // 218624
#define ATTN_SMEM (A_SINV + 128)           // 218752

__global__ __launch_bounds__(NTHR, 1)
void attn_hmma(const fp16* __restrict__ Qf, const fp16* __restrict__ Kf,
               const fp16* __restrict__ Vf,
               fp16* __restrict__ ctx, float* __restrict__ meanOut, int writeMean) {
    extern __shared__ char smem_raw[];
    fp16*  S    = (fp16*)(smem_raw + A_S);
    fp16*  Qs   = (fp16*)(smem_raw + A_QS);
    float* red  = (float*)(smem_raw + A_RED);
    float* sInv = (float*)(smem_raw + A_SINV);

    const int b    = blockIdx.y;
    const int q0   = blockIdx.x * QROWS;
    const int tid  = threadIdx.x;
    const int lane = tid & 31;
    const int wid  = tid >> 5;
    const float invH = 1.0f / HEADS;

    const uint32_t smb  = smem_u32(smem_raw);
    const uint32_t S_b  = smb + A_S;
    const uint32_t U_b  = smb + A_U;
    const uint32_t Qs_b = smb + A_QS;

    for (int h = 0; h < HEADS; h++) {
        // ---- load Q tile [32][64]
        {
            int row = tid >> 4, c4 = (tid & 15) * 4;
            size_t g = (size_t)(b * SEQ + q0 + row) * EMB + h * HDIM + c4;
            *(uint2*)&Qs[row * QROW + c4] = *(const uint2*)&Qf[g];
        }
        __syncthreads();

        // Q fragments for 2 m-tiles
        uint32_t Af[2][4][4];
#pragma unroll
        for (int mt = 0; mt < 2; mt++)
#pragma unroll
            for (int ds = 0; ds < 4; ds++) {
                uint32_t off = ((mt * 16 + (lane & 15)) * QROW
                                + ds * 16 + (lane >> 4) * 8) * 2;
                ldsm_x4(Af[mt][ds][0], Af[mt][ds][1], Af[mt][ds][2], Af[mt][ds][3],
                        Qs_b + off);
            }

        // =================== scores: S = Q @ K^T ============================
        const fp16* Kb0 = Kf + (size_t)(b * SEQ) * EMB + h * HDIM;

        {
#pragma unroll
            for (int i = 0; i < 4; i++) {
                int idx = tid + i * NTHR;             // 2048 quads
                int row = idx >> 3, q8 = (idx & 7) * 8;
                cp_async16(U_b + (row * KROWS + q8) * 2,
                           Kb0 + (size_t)row * EMB + q8);
            }
            CP_COMMIT();
        }

        for (int ci = 0; ci < SEQ / KCH; ci++) {
            const int buf = ci & 1;
            if (ci + 1 < SEQ / KCH) {
                const int nb = buf ^ 1;
                const int kc2 = (ci + 1) * KCH;
#pragma unroll
                for (int i = 0; i < 4; i++) {
                    int idx = tid + i * NTHR;
                    int row = idx >> 3, q8 = (idx & 7) * 8;
                    cp_async16(U_b + nb * STGB + (row * KROWS + q8) * 2,
                               Kb0 + (size_t)(kc2 + row) * EMB + q8);
                }
                CP_COMMIT();
                CP_WAIT1();
            } else {
                CP_WAIT0();
            }
            __syncthreads();

            const uint32_t kb = U_b + buf * STGB;
            const int l = lane & 15;
#pragma unroll
            for (int nt = 0; nt < 2; nt++) {
                float cc[2][4];
#pragma unroll
                for (int mt = 0; mt < 2; mt++)
#pragma unroll
                    for (int q = 0; q < 4; q++) cc[mt][q] = 0.f;
#pragma unroll
                for (int ds = 0; ds < 4; ds++) {
                    uint32_t boff = ((wid * 16 + nt * 8 + (l & 7)) * KROWS
                                     + ds * 16 + ((l >> 3) & 1) * 8) * 2;
                    uint32_t bfr[2];
                    ldsm_x2(bfr[0], bfr[1], kb + boff);
                    mma_f16(cc[0], Af[0][ds], bfr);
                    mma_f16(cc[1], Af[1][ds], bfr);
                }
#pragma unroll
                for (int mt = 0; mt < 2; mt++) {
                    int row = mt * 16 + (lane >> 2);
                    int col = ci * KCH + wid * 16 + nt * 8 + (lane & 3) * 2;
                    *(uint32_t*)&S[row * SROW + col] =
                        pack2h(__float2half_rn(cc[mt][0]), __float2half_rn(cc[mt][1]));
                    *(uint32_t*)&S[(row + 8) * SROW + col] =
                        pack2h(__float2half_rn(cc[mt][2]), __float2half_rn(cc[mt][3]));
                }
            }
            __syncthreads();
        }

        // ============ softmax: 2 rows per warp; mean via gmem RMW ============
#pragma unroll
        for (int rr = 0; rr < 2; rr++) {
            const int r = wid * 2 + rr;
            float sum = 0.f;
#pragma unroll
            for (int it = 0; it < 8; it++) {
                int base = it * 256 + lane * 8;
                uint4 hv = *(uint4*)&S[r * SROW + base];
                __half2* hp = (__half2*)&hv;
                uint4 ho;
                uint32_t* hop = (uint32_t*)&ho;
#pragma unroll
                for (int p = 0; p < 4; p++) {
                    float2 f = __half22float2(hp[p]);
                    fp16 e0 = __float2half_rn(fast_exp(f.x));
                    fp16 e1 = __float2half_rn(fast_exp(f.y));
                    sum += __half2float(e0) + __half2float(e1);
                    hop[p] = pack2h(e0, e1);
                }
                *(uint4*)&S[r * SROW + base] = ho;
            }
#pragma unroll
            for (int o = 16; o > 0; o >>= 1)
                sum += __shfl_xor_sync(0xffffffffu, sum, o);
            float inv = 1.0f / sum;
            if (lane == 0) sInv[r] = inv;

            if (writeMean) {
                float fac = inv * invH;
                float* mrow = meanOut + ((size_t)b * SEQ + q0 + r) * SEQ;
#pragma unroll
                for (int it = 0; it < 8; it++) {
                    int base = it * 256 + lane * 8;
                    uint4 hv = *(uint4*)&S[r * SROW + base];
                    __half2* hp = (__half2*)&hv;
                    float e[8];
#pragma unroll
                    for (int p = 0; p < 4; p++) {
                        float2 f = __half22float2(hp[p]);
                        e[p * 2]     = f.x;
                        e[p * 2 + 1] = f.y;
                    }
                    if (h == 0) {
                        float4 m0 = make_float4(e[0] * fac, e[1] * fac,
                                                e[2] * fac, e[3] * fac);
                        float4 m1 = make_float4(e[4] * fac, e[5] * fac,
                                                e[6] * fac, e[7] * fac);
                        *(float4*)&mrow[base]     = m0;
                        *(float4*)&mrow[base + 4] = m1;
                    } else {
                        float4 m0 = *(const float4*)&mrow[base];
                        float4 m1 = *(const float4*)&mrow[base + 4];
                        m0.x = fmaf(e[0], fac, m0.x); m0.y = fmaf(e[1], fac, m0.y);
                        m0.z = fmaf(e[2], fac, m0.z); m0.w = fmaf(e[3], fac, m0.w);
                        m1.x = fmaf(e[4], fac, m1.x); m1.y = fmaf(e[5], fac, m1.y);
                        m1.z = fmaf(e[6], fac, m1.z); m1.w = fmaf(e[7], fac, m1.w);
                        *(float4*)&mrow[base]     = m0;
                        *(float4*)&mrow[base + 4] = m1;
                    }
                }
            }
        }
        __syncthreads();

        // =================== PV: ctx = (P @ V) * inv =========================
        const int ntv   = wid & 7;
        const int khalf = wid >> 3;
        const int n0v   = ntv * 8;
        float cc[2][4];
#pragma unroll
        for (int mt = 0; mt < 2; mt++)
#pragma unroll
            for (int q = 0; q < 4; q++) cc[mt][q] = 0.f;

        const fp16* Vb0 = Vf + (size_t)(b * SEQ) * EMB + h * HDIM;

        {
#pragma unroll
            for (int i = 0; i < 4; i++) {
                int idx = tid + i * NTHR;
                int row = idx >> 3, q8 = (idx & 7) * 8;
                cp_async16(U_b + (row * KROWS + q8) * 2,
                           Vb0 + (size_t)row * EMB + q8);
            }
            CP_COMMIT();
        }

        for (int ci = 0; ci < SEQ / KCH; ci++) {
            const int buf = ci & 1;
            if (ci + 1 < SEQ / KCH) {
                const int nb = buf ^ 1;
                const int kc2 = (ci + 1) * KCH;
#pragma unroll
                for (int i = 0; i < 4; i++) {
                    int idx = tid + i * NTHR;
                    int row = idx >> 3, q8 = (idx & 7) * 8;
                    cp_async16(U_b + nb * STGB + (row * KROWS + q8) * 2,
                               Vb0 + (size_t)(kc2 + row) * EMB + q8);
                }
                CP_COMMIT();
                CP_WAIT1();
            } else {
                CP_WAIT0();
            }
            __syncthreads();

            const uint32_t vb = U_b + buf * STGB;
            const int kc = ci * KCH;
#pragma unroll
            for (int ks = 0; ks < 8; ks++) {
                int kpos = kc + khalf * 128 + ks * 16;
                int krow = khalf * 128 + ks * 16;
                uint32_t boff = ((krow + (lane & 15)) * KROWS + n0v) * 2;
                uint32_t bfr[2];
                ldsm_x2t(bfr[0], bfr[1], vb + boff);
#pragma unroll
                for (int mt = 0; mt < 2; mt++) {
                    uint32_t aoff = ((mt * 16 + (lane & 15)) * SROW + kpos
                                     + (lane >> 4) * 8) * 2;
                    uint32_t af[4];
                    ldsm_x4(af[0], af[1], af[2], af[3], S_b + aoff);
                    mma_f16(cc[mt], af, bfr);
                }
            }
            __syncthreads();
        }

        // cross-warp k-half reduction, normalize, store ctx fp16
        {
            if (khalf == 1) {
#pragma unroll
                for (int mt = 0; mt < 2; mt++) {
                    int row = mt * 16 + (lane >> 2);
                    int col = n0v + (lane & 3) * 2;
                    *(float2*)&red[row * REDW + col]       = make_float2(cc[mt][0], cc[mt][1]);
                    *(float2*)&red[(row + 8) * REDW + col] = make_float2(cc[mt][2], cc[mt][3]);
                }
            }
            __syncthreads();
            if (khalf == 0) {
#pragma unroll
                for (int mt = 0; mt < 2; mt++) {
                    int row = mt * 16 + (lane >> 2);
                    int col = n0v + (lane & 3) * 2;
                    float2 r0 = *(const float2*)&red[row * REDW + col];
                    float2 r1 = *(const float2*)&red[(row + 8) * REDW + col];
                    float inv0 = sInv[row], inv1 = sInv[row + 8];
                    float v00 = (cc[mt][0] + r0.x) * inv0, v01 = (cc[mt][1] + r0.y) * inv0;
                    float v10 = (cc[mt][2] + r1.x) * inv1, v11 = (cc[mt][3] + r1.y) * inv1;
                    size_t i0 = (size_t)(b * SEQ + q0 + row) * EMB + h * HDIM + col;
                    size_t i1 = (size_t)(b * SEQ + q0 + row + 8) * EMB + h * HDIM + col;
                    *(uint32_t*)&ctx[i0] = pack2h(__float2half_rn(v00), __float2half_rn(v01));
                    *(uint32_t*)&ctx[i1] = pack2h(__float2half_rn(v10), __float2half_rn(v11));
                }
            }
            __syncthreads();
        }
    }
}

// ---------------- launch ------------------------------------------------------------
extern "C" void kernel_launch(void* const* d_in, const int* in_sizes, int n_in,
                              void* d_out, int out_size) {
    const float* query = (const float*)d_in[0];
    const float* key_  = (const float*)d_in[1];
    const float* value = (const float*)d_in[2];
    const float* Wq = (const float*)d_in[3];
    const float* bq = (const float*)d_in[4];
    const float* Wk = (const float*)d_in[5];
    const float* bk = (const float*)d_in[6];
    const float* Wv = (const float*)d_in[7];
    const float* bv = (const float*)d_in[8];
    const float* Wo = (const float*)d_in[9];
    const float* bo = (const float*)d_in[10];

    float* out = (float*)d_out;
    const size_t outElems  = (size_t)MROWS * EMB;
    const size_t meanElems = (size_t)BATCH * SEQ * SEQ;
    int writeMean = ((size_t)out_size >= outElems + meanElems) ? 1 : 0;
    float* meanOut = out + outElems;

    fp16 *Ab, *Wb, *Qfb, *Kfb, *Vfb;
    cudaGetSymbolAddress((void**)&Ab,  g_A);
    cudaGetSymbolAddress((void**)&Wb,  g_W);
    cudaGetSymbolAddress((void**)&Qfb, g_Qf);
    cudaGetSymbolAddress((void**)&Kfb, g_Kf);
    cudaGetSymbolAddress((void**)&Vfb, g_Vf);

    const int n4_in = MROWS * EMB / 4;
    const int n4_w  = EMB * EMB / 4;
    dim3 ggemm(EMB / 128, MROWS / 128);   // (8, 64)

    cudaFuncSetAttribute(gemm_hmma, cudaFuncAttributeMaxDynamicSharedMemorySize,
                         GEMM_SMEM);
    cudaFuncSetAttribute(attn_hmma, cudaFuncAttributeMaxDynamicSharedMemorySize,
                         ATTN_SMEM);

    // Q projection -> Qf (rscale folded)
    cvt_kernel<<<n4_w / 256, 256>>>(Wq, Wb, 1.f, n4_w);
    cvt_kernel<<<n4_in / 256, 256>>>(query, Ab, 1.f, n4_in);
    gemm_hmma<<<ggemm, 256, GEMM_SMEM>>>(Ab, Wb, bq, nullptr, Qfb, 0.125f,
                                         MROWS, EMB, EMB);
    // K projection -> Kf
    cvt_kernel<<<n4_w / 256, 256>>>(Wk, Wb, 1.f, n4_w);
    cvt_kernel<<<n4_in / 256, 256>>>(key_, Ab, 1.f, n4_in);
    gemm_hmma<<<ggemm, 256, GEMM_SMEM>>>(Ab, Wb, bk, nullptr, Kfb, 1.f,
                                         MROWS, EMB, EMB);
    // V projection -> Vf
    cvt_kernel<<<n4_w / 256, 256>>>(Wv, Wb, 1.f, n4_w);
    cvt_kernel<<<n4_in / 256, 256>>>(value, Ab, 1.f, n4_in);
    gemm_hmma<<<ggemm, 256, GEMM_SMEM>>>(Ab, Wb, bv, nullptr, Vfb, 1.f,
                                         MROWS, EMB, EMB);

    // attention -> ctx fp16 into g_A, mean via gmem RMW
    attn_hmma<<<dim3(SEQ / QROWS, BATCH), NTHR, ATTN_SMEM>>>(
        Qfb, Kfb, Vfb, Ab, meanOut, writeMean);

    // output projection -> fp32 out
    cvt_kernel<<<n4_w / 256, 256>>>(Wo, Wb, 1.f, n4_w);
    gemm_hmma<<<ggemm, 256, GEMM_SMEM>>>(Ab, Wb, bo, out, nullptr, 1.f,
                                         MROWS, EMB, EMB);
}

// round 11
// speedup vs baseline: 14.6447x; 1.0019x over previous
#include <cuda_runtime.h>
#include <cuda_fp16.h>
#include <math.h>
#include <stdint.h>

#define BATCH 4
#define SEQ   2048
#define EMB   1024
#define HEADS 16
#define HDIM  64
#define MROWS (BATCH*SEQ)   // 8192

typedef __half fp16;

// ---------------- scratch ------------------------------------------------------
__device__ fp16 g_A[MROWS*EMB];     // activation fp16 (input convert / ctx)
__device__ fp16 g_W[EMB*EMB];       // weight fp16 (reused per projection)
__device__ fp16 g_Qf[MROWS*EMB];    // Q fp16 (rscale folded), [b,s,h,d]
__device__ fp16 g_Kf[MROWS*EMB];    // K fp16 [b,s,h,d]
__device__ fp16 g_Vf[MROWS*EMB];    // V fp16 [b,s,h,d]

// ---------------- helpers ------------------------------------------------------
__device__ __forceinline__ uint32_t smem_u32(const void* p) {
    return (uint32_t)__cvta_generic_to_shared(p);
}
__device__ __forceinline__ void cp_async16(uint32_t dst, const void* src) {
    asm volatile("cp.async.cg.shared.global [%0], [%1], 16;"
                 :: "r"(dst), "l"(src));
}
#define CP_COMMIT() asm volatile("cp.async.commit_group;" ::: "memory")
#define CP_WAIT1()  asm volatile("cp.async.wait_group 1;" ::: "memory")
#define CP_WAIT0()  asm volatile("cp.async.wait_group 0;" ::: "memory")

__device__ __forceinline__ void ldsm_x4(uint32_t& r0, uint32_t& r1, uint32_t& r2,
                                        uint32_t& r3, uint32_t addr) {
    asm volatile("ldmatrix.sync.aligned.m8n8.x4.shared.b16 {%0,%1,%2,%3}, [%4];"
                 : "=r"(r0), "=r"(r1), "=r"(r2), "=r"(r3) : "r"(addr));
}
__device__ __forceinline__ void ldsm_x2(uint32_t& r0, uint32_t& r1, uint32_t addr) {
    asm volatile("ldmatrix.sync.aligned.m8n8.x2.shared.b16 {%0,%1}, [%2];"
                 : "=r"(r0), "=r"(r1) : "r"(addr));
}
__device__ __forceinline__ void ldsm_x2t(uint32_t& r0, uint32_t& r1, uint32_t addr) {
    asm volatile("ldmatrix.sync.aligned.m8n8.x2.trans.shared.b16 {%0,%1}, [%2];"
                 : "=r"(r0), "=r"(r1) : "r"(addr));
}
__device__ __forceinline__ void mma_f16(float (&c)[4], const uint32_t (&a)[4],
                                        const uint32_t (&b)[2]) {
    asm volatile(
        "mma.sync.aligned.m16n8k16.row.col.f32.f16.f16.f32 "
        "{%0,%1,%2,%3}, {%4,%5,%6,%7}, {%8,%9}, {%0,%1,%2,%3};"
        : "+f"(c[0]), "+f"(c[1]), "+f"(c[2]), "+f"(c[3])
        : "r"(a[0]), "r"(a[1]), "r"(a[2]), "r"(a[3]), "r"(b[0]), "r"(b[1]));
}
__device__ __forceinline__ uint32_t pack2h(fp16 a, fp16 b) {
    __half2 t = __halves2half2(a, b);
    return *(uint32_t*)&t;
}
__device__ __forceinline__ float fast_exp(float x) {
    const float L2E   = 1.4426950408889634f;
    const float MAGIC = 12582912.0f;           // 1.5 * 2^23
    float t = x * L2E;
    float z = t + MAGIC;
    int   i = __float_as_int(z);
    float k = z - MAGIC;
    float f = t - k;
    float p =         1.3333558146e-3f;
    p = fmaf(p, f,    9.6181291076e-3f);
    p = fmaf(p, f,    5.5504108665e-2f);
    p = fmaf(p, f,    2.4022650696e-1f);
    p = fmaf(p, f,    6.9314718056e-1f);
    p = fmaf(p, f,    1.0f);
    float s = __int_as_float((i - 0x4B400000 + 127) << 23);
    return p * s;
}

// ---------------- convert: fp32 -> fp16 (scaled) ---------------------------------
__global__ __launch_bounds__(256)
void cvt_kernel(const float* __restrict__ src, fp16* __restrict__ dst,
                float scale, int n4) {
    int i = blockIdx.x * 256 + threadIdx.x;
    if (i >= n4) return;
    float4 v = ((const float4*)src)[i];
    uint2 o;
    o.x = pack2h(__float2half_rn(v.x * scale), __float2half_rn(v.y * scale));
    o.y = pack2h(__float2half_rn(v.z * scale), __float2half_rn(v.w * scale));
    ((uint2*)dst)[i] = o;
}

// ---------------- GEMM (fp16 mma, cp.async 2-stage) --------------------------------
#define GROW 40
#define PL   (128*GROW)
#define GSTG (2*PL)
#define GEMM_SMEM (2*GSTG*2)  // 40960

__global__ __launch_bounds__(256, 2)
void gemm_hmma(const fp16* __restrict__ A, const fp16* __restrict__ W,
               const float* __restrict__ bias,
               float* __restrict__ Cf, fp16* __restrict__ Ch,
               float oscale, int M, int N, int K) {
    extern __shared__ fp16 gsm[];
    const uint32_t smb = smem_u32(gsm);

    const int tid  = threadIdx.x;
    const int lane = tid & 31;
    const int wid  = tid >> 5;
    const int wm   = wid >> 2;
    const int wn   = wid & 3;
    const int m0 = blockIdx.y * 128;
    const int n0 = blockIdx.x * 128;

    float acc[4][4][4];
#pragma unroll
    for (int i = 0; i < 4; i++)
#pragma unroll
        for (int j = 0; j < 4; j++)
#pragma unroll
            for (int q = 0; q < 4; q++) acc[i][j][q] = 0.f;

    const int r0 = tid >> 2;
    const int c8 = (tid & 3) * 8;

    {
#pragma unroll
        for (int p = 0; p < 2; p++) {
            const fp16* src = p ? W : A;
            const int rb = p ? n0 : m0;
#pragma unroll
            for (int i = 0; i < 2; i++) {
                int row = r0 + i * 64;
                cp_async16(smb + (p * PL + row * GROW + c8) * 2,
                           src + (size_t)(rb + row) * K + c8);
            }
        }
        CP_COMMIT();
    }

    const int NCH = K / 32;
    for (int ch = 0; ch < NCH; ch++) {
        const int buf = ch & 1;
        if (ch + 1 < NCH) {
            const int nb = buf ^ 1;
            const int k0 = (ch + 1) * 32;
#pragma unroll
            for (int p = 0; p < 2; p++) {
                const fp16* src = p ? W : A;
                const int rb = p ? n0 : m0;
#pragma unroll
                for (int i = 0; i < 2; i++) {
                    int row = r0 + i * 64;
                    cp_async16(smb + (nb * GSTG + p * PL + row * GROW + c8) * 2,
                               src + (size_t)(rb + row) * K + k0 + c8);
                }
            }
            CP_COMMIT();
            CP_WAIT1();
        } else {
            CP_WAIT0();
        }
        __syncthreads();

        const uint32_t bA = buf * GSTG;
#pragma unroll
        for (int kk = 0; kk < 2; kk++) {
            uint32_t af[4][4], bf[4][2];
#pragma unroll
            for (int mt = 0; mt < 4; mt++) {
                uint32_t off = (bA + (wm * 64 + mt * 16 + (lane & 15)) * GROW
                                + kk * 16 + (lane >> 4) * 8) * 2;
                ldsm_x4(af[mt][0], af[mt][1], af[mt][2], af[mt][3], smb + off);
            }
#pragma unroll
            for (int nt = 0; nt < 4; nt++) {
                int l = lane & 15;
                uint32_t off = (bA + PL + (wn * 32 + nt * 8 + (l & 7)) * GROW
                                + kk * 16 + ((l >> 3) & 1) * 8) * 2;
                ldsm_x2(bf[nt][0], bf[nt][1], smb + off);
            }
#pragma unroll
            for (int mt = 0; mt < 4; mt++)
#pragma unroll
                for (int nt = 0; nt < 4; nt++)
                    mma_f16(acc[mt][nt], af[mt], bf[nt]);
        }
        __syncthreads();
    }

#pragma unroll
    for (int nt = 0; nt < 4; nt++) {
        int n = n0 + wn * 32 + nt * 8 + (lane & 3) * 2;
        float b0 = bias[n], b1 = bias[n + 1];
#pragma unroll
        for (int mt = 0; mt < 4; mt++) {
            int m = m0 + wm * 64 + mt * 16 + (lane >> 2);
            float v00 = (acc[mt][nt][0] + b0) * oscale;
            float v01 = (acc[mt][nt][1] + b1) * oscale;
            float v10 = (acc[mt][nt][2] + b0) * oscale;
            float v11 = (acc[mt][nt][3] + b1) * oscale;
            size_t i0 = (size_t)m * N + n;
            size_t i1 = (size_t)(m + 8) * N + n;
            if (Cf) {
                *(float2*)&Cf[i0] = make_float2(v00, v01);
                *(float2*)&Cf[i1] = make_float2(v10, v11);
            }
            if (Ch) {
                *(uint32_t*)&Ch[i0] = pack2h(__float2half_rn(v00), __float2half_rn(v01));
                *(uint32_t*)&Ch[i1] = pack2h(__float2half_rn(v10), __float2half_rn(v11));
            }
        }
    }
}

// ---------------- fused single-pass attention --------------------------------------
// Per K-chunk: S = Q@K^T (mma) -> exp -> P (registers, fp16) -> out += P@V (mma).
// P also written once to S smem (needed for the attn-mean output only).
// Warp roles: rg = wid>>3 (q-row group of 16), ks = wid&7 (16-col k-slice of chunk).
#define QROWS 32
#define KCH   128
#define SROW  2056
#define KROWS 72
#define QROW  72
#define NTHR  512
// smem byte layout
#define A_S    0                           // 32*SROW*2 = 131584 (P store; reused as out-reduce)
#define S_BYTES (32*SROW*2)
#define A_U    S_BYTES                     // 2 stages x (K plane + V plane)
#define KPL    (KCH*KROWS*2)               // 18432
#define STGB   (2*KPL)                     // 36864
#define A_QS   (A_U + 2*STGB)              // 205312
#define A_RSUM (A_QS + 32*QROW*2)          // 209920
#define ATTN_SMEM (A_RSUM + 256)           // 210176

__global__ __launch_bounds__(NTHR, 1)
void attn_fused(const fp16* __restrict__ Qf, const fp16* __restrict__ Kf,
                const fp16* __restrict__ Vf,
                fp16* __restrict__ ctx, float* __restrict__ meanOut, int writeMean) {
    extern __shared__ char smem_raw[];
    fp16*  S      = (fp16*)(smem_raw + A_S);
    float* Sred   = (float*)(smem_raw + A_S);     // reused after mean pass
    fp16*  Qs     = (fp16*)(smem_raw + A_QS);
    float* rowsum = (float*)(smem_raw + A_RSUM);

    const int b    = blockIdx.y;
    const int q0   = blockIdx.x * QROWS;
    const int tid  = threadIdx.x;
    const int lane = tid & 31;
    const int wid  = tid >> 5;
    const int rg   = wid >> 3;        // q-row group (rows rg*16 .. +15)
    const int ks   = wid & 7;         // k-slice within chunk (cols ks*16 .. +15)
    const float invH = 1.0f / HEADS;

    const uint32_t smb  = smem_u32(smem_raw);
    const uint32_t U_b  = smb + A_U;
    const uint32_t Qs_b = smb + A_QS;

    const fp16* KbB = Kf + (size_t)(b * SEQ) * EMB;
    const fp16* VbB = Vf + (size_t)(b * SEQ) * EMB;

    for (int h = 0; h < HEADS; h++) {
        // zero rowsum + load Q tile
        if (tid < 32) rowsum[tid] = 0.f;
        {
            int row = tid >> 4, c4 = (tid & 15) * 4;
            size_t g = (size_t)(b * SEQ + q0 + row) * EMB + h * HDIM + c4;
            *(uint2*)&Qs[row * QROW + c4] = *(const uint2*)&Qf[g];
        }
        if (h == 0) {
            // prefetch chunk 0 (K + V planes)
#pragma unroll
            for (int i = 0; i < 4; i++) {
                int idx = tid + i * NTHR;             // 2048 quads
                int pl = idx >> 10, rem = idx & 1023;
                int row = rem >> 3, q8 = (rem & 7) * 8;
                const fp16* src = pl ? (VbB + h * HDIM) : (KbB + h * HDIM);
                cp_async16(U_b + pl * KPL + (row * KROWS + q8) * 2,
                           src + (size_t)row * EMB + q8);
            }
            CP_COMMIT();
        }
        __syncthreads();

        // Q fragments for this warp's row group
        uint32_t Af[4][4];
#pragma unroll
        for (int ds = 0; ds < 4; ds++) {
            uint32_t off = ((rg * 16 + (lane & 15)) * QROW
                            + ds * 16 + (lane >> 4) * 8) * 2;
            ldsm_x4(Af[ds][0], Af[ds][1], Af[ds][2], Af[ds][3], Qs_b + off);
        }

        float out[8][4];
#pragma unroll
        for (int n8 = 0; n8 < 8; n8++)
#pragma unroll
            for (int q = 0; q < 4; q++) out[n8][q] = 0.f;
        float rs0 = 0.f, rs1 = 0.f;

        const fp16* Kb0 = KbB + h * HDIM;
        const fp16* Vb0 = VbB + h * HDIM;
        const int l = lane & 15;

        for (int ci = 0; ci < SEQ / KCH; ci++) {
            const int buf = ci & 1;
            if (ci + 1 < SEQ / KCH) {
                const int nb = buf ^ 1;
                const int kc2 = (ci + 1) * KCH;
#pragma unroll
                for (int i = 0; i < 4; i++) {
                    int idx = tid + i * NTHR;
                    int pl = idx >> 10, rem = idx & 1023;
                    int row = rem >> 3, q8 = (rem & 7) * 8;
                    const fp16* src = pl ? Vb0 : Kb0;
                    cp_async16(U_b + nb * STGB + pl * KPL + (row * KROWS + q8) * 2,
                               src + (size_t)(kc2 + row) * EMB + q8);
                }
                CP_COMMIT();
                CP_WAIT1();
            } else {
                CP_WAIT0();
            }
            __syncthreads();

            const uint32_t kb = U_b + buf * STGB;       // K plane
            const uint32_t vb = kb + KPL;               // V plane

            // ---- scores for this warp's 16 k-cols; exp; pack P a-fragment
            uint32_t pa[4];
#pragma unroll
            for (int nt = 0; nt < 2; nt++) {
                float c[4] = {0.f, 0.f, 0.f, 0.f};
#pragma unroll
                for (int ds = 0; ds < 4; ds++) {
                    uint32_t boff = ((ks * 16 + nt * 8 + (l & 7)) * KROWS
                                     + ds * 16 + ((l >> 3) & 1) * 8) * 2;
                    uint32_t bfr[2];
                    ldsm_x2(bfr[0], bfr[1], kb + boff);
                    mma_f16(c, Af[ds], bfr);
                }
                float e0 = fast_exp(c[0]);
                float e1 = fast_exp(c[1]);
                float e2 = fast_exp(c[2]);
                float e3 = fast_exp(c[3]);
                rs0 += e0 + e1;
                rs1 += e2 + e3;
                uint32_t p01 = pack2h(__float2half_rn(e0), __float2half_rn(e1));
                uint32_t p23 = pack2h(__float2half_rn(e2), __float2half_rn(e3));
                pa[nt * 2]     = p01;
                pa[nt * 2 + 1] = p23;
                // store P to S for the mean output
                int row0 = rg * 16 + (lane >> 2);
                int col  = ci * KCH + ks * 16 + nt * 8 + (lane & 3) * 2;
                *(uint32_t*)&S[row0 * SROW + col]       = p01;
                *(uint32_t*)&S[(row0 + 8) * SROW + col] = p23;
            }

            // ---- PV: out += P(16x16) @ V(16x64)
#pragma unroll
            for (int n8 = 0; n8 < 8; n8++) {
                uint32_t boff = ((ks * 16 + l) * KROWS + n8 * 8) * 2;
                uint32_t bfr[2];
                ldsm_x2t(bfr[0], bfr[1], vb + boff);
                mma_f16(out[n8], pa, bfr);
            }
            __syncthreads();
        }

        // prefetch next head's chunk 0 (overlaps tail phases)
        if (h + 1 < HEADS) {
            const fp16* Kn = KbB + (h + 1) * HDIM;
            const fp16* Vn = VbB + (h + 1) * HDIM;
#pragma unroll
            for (int i = 0; i < 4; i++) {
                int idx = tid + i * NTHR;
                int pl = idx >> 10, rem = idx & 1023;
                int row = rem >> 3, q8 = (rem & 7) * 8;
                const fp16* src = pl ? Vn : Kn;
                cp_async16(U_b + pl * KPL + (row * KROWS + q8) * 2,
                           src + (size_t)row * EMB + q8);
            }
            CP_COMMIT();
        }

        // ---- row-sum reduce: 4-lane shfl then cross-warp atomicAdd
        rs0 += __shfl_xor_sync(0xffffffffu, rs0, 1);
        rs0 += __shfl_xor_sync(0xffffffffu, rs0, 2);
        rs1 += __shfl_xor_sync(0xffffffffu, rs1, 1);
        rs1 += __shfl_xor_sync(0xffffffffu, rs1, 2);
        if ((lane & 3) == 0) {
            int r = rg * 16 + (lane >> 2);
            atomicAdd(&rowsum[r], rs0);
            atomicAdd(&rowsum[r + 8], rs1);
        }
        __syncthreads();

        // ---- mean pass: 2 rows per warp, read P from S, RMW gmem
        if (writeMean) {
#pragma unroll
            for (int rr = 0; rr < 2; rr++) {
                const int r = wid * 2 + rr;
                float fac = invH / rowsum[r];
                float* mrow = meanOut + ((size_t)b * SEQ + q0 + r) * SEQ;
#pragma unroll
                for (int it = 0; it < 8; it++) {
                    int base = it * 256 + lane * 8;
                    uint4 hv = *(uint4*)&S[r * SROW + base];
                    __half2* hp = (__half2*)&hv;
                    float e[8];
#pragma unroll
                    for (int p = 0; p < 4; p++) {
                        float2 f = __half22float2(hp[p]);
                        e[p * 2]     = f.x;
                        e[p * 2 + 1] = f.y;
                    }
                    if (h == 0) {
                        float4 m0 = make_float4(e[0] * fac, e[1] * fac,
                                                e[2] * fac, e[3] * fac);
                        float4 m1 = make_float4(e[4] * fac, e[5] * fac,
                                                e[6] * fac, e[7] * fac);
                        *(float4*)&mrow[base]     = m0;
                        *(float4*)&mrow[base + 4] = m1;
                    } else {
                        float4 m0 = *(const float4*)&mrow[base];
                        float4 m1 = *(const float4*)&mrow[base + 4];
                        m0.x = fmaf(e[0], fac, m0.x); m0.y = fmaf(e[1], fac, m0.y);
                        m0.z = fmaf(e[2], fac, m0.z); m0.w = fmaf(e[3], fac, m0.w);
                        m1.x = fmaf(e[4], fac, m1.x); m1.y = fmaf(e[5], fac, m1.y);
                        m1.z = fmaf(e[6], fac, m1.z); m1.w = fmaf(e[7], fac, m1.w);
                        *(float4*)&mrow[base]     = m0;
                        *(float4*)&mrow[base + 4] = m1;
                    }
                }
            }
        }
        __syncthreads();   // S free after this point

        // ---- out-partial store into Sred[wid][16][64]
        {
            float* dst = Sred + wid * 1024;
            int rl = lane >> 2, cl = (lane & 3) * 2;
#pragma unroll
            for (int n8 = 0; n8 < 8; n8++) {
                *(float2*)&dst[rl * 64 + n8 * 8 + cl]       =
                    make_float2(out[n8][0], out[n8][1]);
                *(float2*)&dst[(rl + 8) * 64 + n8 * 8 + cl] =
                    make_float2(out[n8][2], out[n8][3]);
            }
        }
        __syncthreads();

        // ---- final: 8-way reduce, normalize, store ctx
        {
            int row = tid >> 4;
            int col = (tid & 15) * 4;
            float s4[4] = {0.f, 0.f, 0.f, 0.f};
            int wbase = (row >> 4) * 8;      // warps of this row group
            int off   = (row & 15) * 64 + col;
#pragma unroll
            for (int w = 0; w < 8; w++) {
                const float* src = Sred + (wbase + w) * 1024 + off;
                s4[0] += src[0]; s4[1] += src[1];
                s4[2] += src[2]; s4[3] += src[3];
            }
            float inv = __fdividef(1.f, rowsum[row]);
            uint2 o;
            o.x = pack2h(__float2half_rn(s4[0] * inv), __float2half_rn(s4[1] * inv));
            o.y = pack2h(__float2half_rn(s4[2] * inv), __float2half_rn(s4[3] * inv));
            *(uint2*)&ctx[(size_t)(b * SEQ + q0 + row) * EMB + h * HDIM + col] = o;
        }
        __syncthreads();
    }
}

// ---------------- launch ------------------------------------------------------------
extern "C" void kernel_launch(void* const* d_in, const int* in_sizes, int n_in,
                              void* d_out, int out_size) {
    const float* query = (const float*)d_in[0];
    const float* key_  = (const float*)d_in[1];
    const float* value = (const float*)d_in[2];
    const float* Wq = (const float*)d_in[3];
    const float* bq = (const float*)d_in[4];
    const float* Wk = (const float*)d_in[5];
    const float* bk = (const float*)d_in[6];
    const float* Wv = (const float*)d_in[7];
    const float* bv = (const float*)d_in[8];
    const float* Wo = (const float*)d_in[9];
    const float* bo = (const float*)d_in[10];

    float* out = (float*)d_out;
    const size_t outElems  = (size_t)MROWS * EMB;
    const size_t meanElems = (size_t)BATCH * SEQ * SEQ;
    int writeMean = ((size_t)out_size >= outElems + meanElems) ? 1 : 0;
    float* meanOut = out + outElems;

    fp16 *Ab, *Wb, *Qfb, *Kfb, *Vfb;
    cudaGetSymbolAddress((void**)&Ab,  g_A);
    cudaGetSymbolAddress((void**)&Wb,  g_W);
    cudaGetSymbolAddress((void**)&Qfb, g_Qf);
    cudaGetSymbolAddress((void**)&Kfb, g_Kf);
    cudaGetSymbolAddress((void**)&Vfb, g_Vf);

    const int n4_in = MROWS * EMB / 4;
    const int n4_w  = EMB * EMB / 4;
    dim3 ggemm(EMB / 128, MROWS / 128);   // (8, 64)

    cudaFuncSetAttribute(gemm_hmma, cudaFuncAttributeMaxDynamicSharedMemorySize,
                         GEMM_SMEM);
    cudaFuncSetAttribute(attn_fused, cudaFuncAttributeMaxDynamicSharedMemorySize,
                         ATTN_SMEM);

    // Q projection -> Qf (rscale folded)
    cvt_kernel<<<n4_w / 256, 256>>>(Wq, Wb, 1.f, n4_w);
    cvt_kernel<<<n4_in / 256, 256>>>(query, Ab, 1.f, n4_in);
    gemm_hmma<<<ggemm, 256, GEMM_SMEM>>>(Ab, Wb, bq, nullptr, Qfb, 0.125f,
                                         MROWS, EMB, EMB);
    // K projection -> Kf
    cvt_kernel<<<n4_w / 256, 256>>>(Wk, Wb, 1.f, n4_w);
    cvt_kernel<<<n4_in / 256, 256>>>(key_, Ab, 1.f, n4_in);
    gemm_hmma<<<ggemm, 256, GEMM_SMEM>>>(Ab, Wb, bk, nullptr, Kfb, 1.f,
                                         MROWS, EMB, EMB);
    // V projection -> Vf
    cvt_kernel<<<n4_w / 256, 256>>>(Wv, Wb, 1.f, n4_w);
    cvt_kernel<<<n4_in / 256, 256>>>(value, Ab, 1.f, n4_in);
    gemm_hmma<<<ggemm, 256, GEMM_SMEM>>>(Ab, Wb, bv, nullptr, Vfb, 1.f,
                                         MROWS, EMB, EMB);

    // fused attention -> ctx fp16 into g_A
    attn_fused<<<dim3(SEQ / QROWS, BATCH), NTHR, ATTN_SMEM>>>(
        Qfb, Kfb, Vfb, Ab, meanOut, writeMean);

    // output projection -> fp32 out
    cvt_kernel<<<n4_w / 256, 256>>>(Wo, Wb, 1.f, n4_w);
    gemm_hmma<<<ggemm, 256, GEMM_SMEM>>>(Ab, Wb, bo, out, nullptr, 1.f,
                                         MROWS, EMB, EMB);
}

// round 12
// speedup vs baseline: 15.1937x; 1.0375x over previous
#include <cuda_runtime.h>
#include <cuda_fp16.h>
#include <math.h>
#include <stdint.h>

#define BATCH 4
#define SEQ   2048
#define EMB   1024
#define HEADS 16
#define HDIM  64
#define MROWS (BATCH*SEQ)   // 8192

typedef __half fp16;

// ---------------- scratch ------------------------------------------------------
__device__ fp16 g_A1[MROWS*EMB];    // query cvt / ctx output
__device__ fp16 g_A2[MROWS*EMB];    // key cvt
__device__ fp16 g_A3[MROWS*EMB];    // value cvt
__device__ fp16 g_W1[EMB*EMB];      // Wq
__device__ fp16 g_W2[EMB*EMB];      // Wk
__device__ fp16 g_W3[EMB*EMB];      // Wv
__device__ fp16 g_W4[EMB*EMB];      // Wo
__device__ fp16 g_Qf[MROWS*EMB];    // Q fp16 (rscale folded), [b,s,h,d]
__device__ fp16 g_Kf[MROWS*EMB];    // K fp16 [b,s,h,d]
__device__ fp16 g_Vf[MROWS*EMB];    // V fp16 [b,s,h,d]

// ---------------- helpers ------------------------------------------------------
__device__ __forceinline__ uint32_t smem_u32(const void* p) {
    return (uint32_t)__cvta_generic_to_shared(p);
}
__device__ __forceinline__ void cp_async16(uint32_t dst, const void* src) {
    asm volatile("cp.async.cg.shared.global [%0], [%1], 16;"
                 :: "r"(dst), "l"(src));
}
#define CP_COMMIT() asm volatile("cp.async.commit_group;" ::: "memory")
#define CP_WAIT1()  asm volatile("cp.async.wait_group 1;" ::: "memory")
#define CP_WAIT0()  asm volatile("cp.async.wait_group 0;" ::: "memory")

__device__ __forceinline__ void ldsm_x4(uint32_t& r0, uint32_t& r1, uint32_t& r2,
                                        uint32_t& r3, uint32_t addr) {
    asm volatile("ldmatrix.sync.aligned.m8n8.x4.shared.b16 {%0,%1,%2,%3}, [%4];"
                 : "=r"(r0), "=r"(r1), "=r"(r2), "=r"(r3) : "r"(addr));
}
__device__ __forceinline__ void ldsm_x2(uint32_t& r0, uint32_t& r1, uint32_t addr) {
    asm volatile("ldmatrix.sync.aligned.m8n8.x2.shared.b16 {%0,%1}, [%2];"
                 : "=r"(r0), "=r"(r1) : "r"(addr));
}
__device__ __forceinline__ void ldsm_x2t(uint32_t& r0, uint32_t& r1, uint32_t addr) {
    asm volatile("ldmatrix.sync.aligned.m8n8.x2.trans.shared.b16 {%0,%1}, [%2];"
                 : "=r"(r0), "=r"(r1) : "r"(addr));
}
__device__ __forceinline__ void mma_f16(float (&c)[4], const uint32_t (&a)[4],
                                        const uint32_t (&b)[2]) {
    asm volatile(
        "mma.sync.aligned.m16n8k16.row.col.f32.f16.f16.f32 "
        "{%0,%1,%2,%3}, {%4,%5,%6,%7}, {%8,%9}, {%0,%1,%2,%3};"
        : "+f"(c[0]), "+f"(c[1]), "+f"(c[2]), "+f"(c[3])
        : "r"(a[0]), "r"(a[1]), "r"(a[2]), "r"(a[3]), "r"(b[0]), "r"(b[1]));
}
__device__ __forceinline__ uint32_t pack2h(fp16 a, fp16 b) {
    __half2 t = __halves2half2(a, b);
    return *(uint32_t*)&t;
}
__device__ __forceinline__ float fast_exp(float x) {
    const float L2E   = 1.4426950408889634f;
    const float MAGIC = 12582912.0f;           // 1.5 * 2^23
    float t = x * L2E;
    float z = t + MAGIC;
    int   i = __float_as_int(z);
    float k = z - MAGIC;
    float f = t - k;
    float p =         1.3333558146e-3f;
    p = fmaf(p, f,    9.6181291076e-3f);
    p = fmaf(p, f,    5.5504108665e-2f);
    p = fmaf(p, f,    2.4022650696e-1f);
    p = fmaf(p, f,    6.9314718056e-1f);
    p = fmaf(p, f,    1.0f);
    float s = __int_as_float((i - 0x4B400000 + 127) << 23);
    return p * s;
}

// ---------------- cvt_all: all 7 fp32->fp16 conversions in one launch -------------
#define N4_IN (MROWS*EMB/4)    // 2097152
#define N4_W  (EMB*EMB/4)      // 262144
#define CVT_TOTAL (3*N4_IN + 4*N4_W)

__global__ __launch_bounds__(256)
void cvt_all(const float* __restrict__ q, const float* __restrict__ k,
             const float* __restrict__ v,
             const float* __restrict__ wq, const float* __restrict__ wk,
             const float* __restrict__ wv, const float* __restrict__ wo,
             fp16* __restrict__ A1, fp16* __restrict__ A2, fp16* __restrict__ A3,
             fp16* __restrict__ W1, fp16* __restrict__ W2, fp16* __restrict__ W3,
             fp16* __restrict__ W4) {
    int i = blockIdx.x * 256 + threadIdx.x;
    if (i >= CVT_TOTAL) return;
    const float* src;
    fp16* dst;
    if (i < 3 * N4_IN) {
        int job = i / N4_IN;
        i -= job * N4_IN;
        src = (job == 0) ? q : (job == 1) ? k : v;
        dst = (job == 0) ? A1 : (job == 1) ? A2 : A3;
    } else {
        int j = i - 3 * N4_IN;
        int job = j / N4_W;
        i = j - job * N4_W;
        src = (job == 0) ? wq : (job == 1) ? wk : (job == 2) ? wv : wo;
        dst = (job == 0) ? W1 : (job == 1) ? W2 : (job == 2) ? W3 : W4;
    }
    float4 vv = ((const float4*)src)[i];
    uint2 o;
    o.x = pack2h(__float2half_rn(vv.x), __float2half_rn(vv.y));
    o.y = pack2h(__float2half_rn(vv.z), __float2half_rn(vv.w));
    ((uint2*)dst)[i] = o;
}

// ---------------- GEMM body (fp16 mma, BK=64, cp.async 2-stage) --------------------
#define GROW 72               // smem row stride (halves): 64 + 8 pad
#define PL   (128*GROW)       // halves per plane (9216)
#define GSTG (2*PL)           // halves per stage (A + W)
#define GEMM_SMEM (2*GSTG*2)  // bytes = 73728

__device__ __forceinline__
void gemm_body(const fp16* __restrict__ A, const fp16* __restrict__ W,
               const float* __restrict__ bias,
               float* __restrict__ Cf, fp16* __restrict__ Ch,
               float oscale, int M, int N, int K, char* smraw) {
    const uint32_t smb = smem_u32(smraw);

    const int tid  = threadIdx.x;
    const int lane = tid & 31;
    const int wid  = tid >> 5;
    const int wm   = wid >> 2;
    const int wn   = wid & 3;
    const int m0 = blockIdx.y * 128;
    const int n0 = blockIdx.x * 128;

    float acc[4][4][4];
#pragma unroll
    for (int i = 0; i < 4; i++)
#pragma unroll
        for (int j = 0; j < 4; j++)
#pragma unroll
            for (int qq = 0; qq < 4; qq++) acc[i][j][qq] = 0.f;

    // prefetch chunk 0: 2 planes x 128 rows x 64 halves = 2048 quads, 8/thread
    {
#pragma unroll
        for (int i = 0; i < 8; i++) {
            int idx = tid + i * 256;
            int pl = idx >> 10, rem = idx & 1023;
            int row = rem >> 3, c8 = (rem & 7) * 8;
            const fp16* src = pl ? W : A;
            int rb = pl ? n0 : m0;
            cp_async16(smb + (pl * PL + row * GROW + c8) * 2,
                       src + (size_t)(rb + row) * K + c8);
        }
        CP_COMMIT();
    }

    const int NCH = K / 64;
    for (int ch = 0; ch < NCH; ch++) {
        const int buf = ch & 1;
        if (ch + 1 < NCH) {
            const int nb = buf ^ 1;
            const int k0 = (ch + 1) * 64;
#pragma unroll
            for (int i = 0; i < 8; i++) {
                int idx = tid + i * 256;
                int pl = idx >> 10, rem = idx & 1023;
                int row = rem >> 3, c8 = (rem & 7) * 8;
                const fp16* src = pl ? W : A;
                int rb = pl ? n0 : m0;
                cp_async16(smb + (nb * GSTG + pl * PL + row * GROW + c8) * 2,
                           src + (size_t)(rb + row) * K + k0 + c8);
            }
            CP_COMMIT();
            CP_WAIT1();
        } else {
            CP_WAIT0();
        }
        __syncthreads();

        const uint32_t bA = buf * GSTG;
#pragma unroll
        for (int kk = 0; kk < 4; kk++) {
            uint32_t af[4][4], bf[2][4];
#pragma unroll
            for (int mt = 0; mt < 4; mt++) {
                uint32_t off = (bA + (wm * 64 + mt * 16 + (lane & 15)) * GROW
                                + kk * 16 + (lane >> 4) * 8) * 2;
                ldsm_x4(af[mt][0], af[mt][1], af[mt][2], af[mt][3], smb + off);
            }
#pragma unroll
            for (int ntp = 0; ntp < 2; ntp++) {
                uint32_t off = (bA + PL + (wn * 32 + ntp * 16 + (lane & 15)) * GROW
                                + kk * 16 + (lane >> 4) * 8) * 2;
                ldsm_x4(bf[ntp][0], bf[ntp][1], bf[ntp][2], bf[ntp][3], smb + off);
            }
#pragma unroll
            for (int mt = 0; mt < 4; mt++)
#pragma unroll
                for (int nt = 0; nt < 4; nt++) {
                    uint32_t bb[2] = {bf[nt >> 1][nt & 1], bf[nt >> 1][(nt & 1) + 2]};
                    mma_f16(acc[mt][nt], af[mt], bb);
                }
        }
        __syncthreads();
    }

    // epilogue
#pragma unroll
    for (int nt = 0; nt < 4; nt++) {
        int n = n0 + wn * 32 + nt * 8 + (lane & 3) * 2;
        float b0 = bias[n], b1 = bias[n + 1];
#pragma unroll
        for (int mt = 0; mt < 4; mt++) {
            int m = m0 + wm * 64 + mt * 16 + (lane >> 2);
            float v00 = (acc[mt][nt][0] + b0) * oscale;
            float v01 = (acc[mt][nt][1] + b1) * oscale;
            float v10 = (acc[mt][nt][2] + b0) * oscale;
            float v11 = (acc[mt][nt][3] + b1) * oscale;
            size_t i0 = (size_t)m * N + n;
            size_t i1 = (size_t)(m + 8) * N + n;
            if (Cf) {
                *(float2*)&Cf[i0] = make_float2(v00, v01);
                *(float2*)&Cf[i1] = make_float2(v10, v11);
            }
            if (Ch) {
                *(uint32_t*)&Ch[i0] = pack2h(__float2half_rn(v00), __float2half_rn(v01));
                *(uint32_t*)&Ch[i1] = pack2h(__float2half_rn(v10), __float2half_rn(v11));
            }
        }
    }
}

// fused Q/K/V projections: blockIdx.z selects the job
__global__ __launch_bounds__(256, 2)
void gemm3_hmma(const fp16* __restrict__ A1, const fp16* __restrict__ W1,
                const float* __restrict__ bq, fp16* __restrict__ Qf,
                const fp16* __restrict__ A2, const fp16* __restrict__ W2,
                const float* __restrict__ bk, fp16* __restrict__ Kf,
                const fp16* __restrict__ A3, const fp16* __restrict__ W3,
                const float* __restrict__ bv, fp16* __restrict__ Vf) {
    extern __shared__ char sm[];
    int z = blockIdx.z;
    if (z == 0)
        gemm_body(A1, W1, bq, nullptr, Qf, 0.125f, MROWS, EMB, EMB, sm);
    else if (z == 1)
        gemm_body(A2, W2, bk, nullptr, Kf, 1.f, MROWS, EMB, EMB, sm);
    else
        gemm_body(A3, W3, bv, nullptr, Vf, 1.f, MROWS, EMB, EMB, sm);
}

// single GEMM (output projection)
__global__ __launch_bounds__(256, 2)
void gemm_hmma(const fp16* __restrict__ A, const fp16* __restrict__ W,
               const float* __restrict__ bias, float* __restrict__ Cf,
               float oscale, int M, int N, int K) {
    extern __shared__ char sm[];
    gemm_body(A, W, bias, Cf, nullptr, oscale, M, N, K, sm);
}

// ---------------- fused single-pass attention (unchanged from R10) -----------------
#define QROWS 32
#define KCH   128
#define SROW  2056
#define KROWS 72
#define QROW  72
#define NTHR  512
#define A_S    0
#define S_BYTES (32*SROW*2)
#define A_U    S_BYTES
#define KPL    (KCH*KROWS*2)
#define STGB   (2*KPL)
#define A_QS   (A_U + 2*STGB)
#define A_RSUM (A_QS + 32*QROW*2)
#define ATTN_SMEM (A_RSUM + 256)

__global__ __launch_bounds__(NTHR, 1)
void attn_fused(const fp16* __restrict__ Qf, const fp16* __restrict__ Kf,
                const fp16* __restrict__ Vf,
                fp16* __restrict__ ctx, float* __restrict__ meanOut, int writeMean) {
    extern __shared__ char smem_raw[];
    fp16*  S      = (fp16*)(smem_raw + A_S);
    float* Sred   = (float*)(smem_raw + A_S);
    fp16*  Qs     = (fp16*)(smem_raw + A_QS);
    float* rowsum = (float*)(smem_raw + A_RSUM);

    const int b    = blockIdx.y;
    const int q0   = blockIdx.x * QROWS;
    const int tid  = threadIdx.x;
    const int lane = tid & 31;
    const int wid  = tid >> 5;
    const int rg   = wid >> 3;
    const int ks   = wid & 7;
    const float invH = 1.0f / HEADS;

    const uint32_t smb  = smem_u32(smem_raw);
    const uint32_t U_b  = smb + A_U;
    const uint32_t Qs_b = smb + A_QS;

    const fp16* KbB = Kf + (size_t)(b * SEQ) * EMB;
    const fp16* VbB = Vf + (size_t)(b * SEQ) * EMB;

    for (int h = 0; h < HEADS; h++) {
        if (tid < 32) rowsum[tid] = 0.f;
        {
            int row = tid >> 4, c4 = (tid & 15) * 4;
            size_t g = (size_t)(b * SEQ + q0 + row) * EMB + h * HDIM + c4;
            *(uint2*)&Qs[row * QROW + c4] = *(const uint2*)&Qf[g];
        }
        if (h == 0) {
#pragma unroll
            for (int i = 0; i < 4; i++) {
                int idx = tid + i * NTHR;
                int pl = idx >> 10, rem = idx & 1023;
                int row = rem >> 3, q8 = (rem & 7) * 8;
                const fp16* src = pl ? (VbB + h * HDIM) : (KbB + h * HDIM);
                cp_async16(U_b + pl * KPL + (row * KROWS + q8) * 2,
                           src + (size_t)row * EMB + q8);
            }
            CP_COMMIT();
        }
        __syncthreads();

        uint32_t Af[4][4];
#pragma unroll
        for (int ds = 0; ds < 4; ds++) {
            uint32_t off = ((rg * 16 + (lane & 15)) * QROW
                            + ds * 16 + (lane >> 4) * 8) * 2;
            ldsm_x4(Af[ds][0], Af[ds][1], Af[ds][2], Af[ds][3], Qs_b + off);
        }

        float out[8][4];
#pragma unroll
        for (int n8 = 0; n8 < 8; n8++)
#pragma unroll
            for (int qq = 0; qq < 4; qq++) out[n8][qq] = 0.f;
        float rs0 = 0.f, rs1 = 0.f;

        const fp16* Kb0 = KbB + h * HDIM;
        const fp16* Vb0 = VbB + h * HDIM;
        const int l = lane & 15;

        for (int ci = 0; ci < SEQ / KCH; ci++) {
            const int buf = ci & 1;
            if (ci + 1 < SEQ / KCH) {
                const int nb = buf ^ 1;
                const int kc2 = (ci + 1) * KCH;
#pragma unroll
                for (int i = 0; i < 4; i++) {
                    int idx = tid + i * NTHR;
                    int pl = idx >> 10, rem = idx & 1023;
                    int row = rem >> 3, q8 = (rem & 7) * 8;
                    const fp16* src = pl ? Vb0 : Kb0;
                    cp_async16(U_b + nb * STGB + pl * KPL + (row * KROWS + q8) * 2,
                               src + (size_t)(kc2 + row) * EMB + q8);
                }
                CP_COMMIT();
                CP_WAIT1();
            } else {
                CP_WAIT0();
            }
            __syncthreads();

            const uint32_t kb = U_b + buf * STGB;
            const uint32_t vb = kb + KPL;

            uint32_t pa[4];
#pragma unroll
            for (int nt = 0; nt < 2; nt++) {
                float c[4] = {0.f, 0.f, 0.f, 0.f};
#pragma unroll
                for (int ds = 0; ds < 4; ds++) {
                    uint32_t boff = ((ks * 16 + nt * 8 + (l & 7)) * KROWS
                                     + ds * 16 + ((l >> 3) & 1) * 8) * 2;
                    uint32_t bfr[2];
                    ldsm_x2(bfr[0], bfr[1], kb + boff);
                    mma_f16(c, Af[ds], bfr);
                }
                float e0 = fast_exp(c[0]);
                float e1 = fast_exp(c[1]);
                float e2 = fast_exp(c[2]);
                float e3 = fast_exp(c[3]);
                rs0 += e0 + e1;
                rs1 += e2 + e3;
                uint32_t p01 = pack2h(__float2half_rn(e0), __float2half_rn(e1));
                uint32_t p23 = pack2h(__float2half_rn(e2), __float2half_rn(e3));
                pa[nt * 2]     = p01;
                pa[nt * 2 + 1] = p23;
                int row0 = rg * 16 + (lane >> 2);
                int col  = ci * KCH + ks * 16 + nt * 8 + (lane & 3) * 2;
                *(uint32_t*)&S[row0 * SROW + col]       = p01;
                *(uint32_t*)&S[(row0 + 8) * SROW + col] = p23;
            }

#pragma unroll
            for (int n8 = 0; n8 < 8; n8++) {
                uint32_t boff = ((ks * 16 + l) * KROWS + n8 * 8) * 2;
                uint32_t bfr[2];
                ldsm_x2t(bfr[0], bfr[1], vb + boff);
                mma_f16(out[n8], pa, bfr);
            }
            __syncthreads();
        }

        if (h + 1 < HEADS) {
            const fp16* Kn = KbB + (h + 1) * HDIM;
            const fp16* Vn = VbB + (h + 1) * HDIM;
#pragma unroll
            for (int i = 0; i < 4; i++) {
                int idx = tid + i * NTHR;
                int pl = idx >> 10, rem = idx & 1023;
                int row = rem >> 3, q8 = (rem & 7) * 8;
                const fp16* src = pl ? Vn : Kn;
                cp_async16(U_b + pl * KPL + (row * KROWS + q8) * 2,
                           src + (size_t)row * EMB + q8);
            }
            CP_COMMIT();
        }

        rs0 += __shfl_xor_sync(0xffffffffu, rs0, 1);
        rs0 += __shfl_xor_sync(0xffffffffu, rs0, 2);
        rs1 += __shfl_xor_sync(0xffffffffu, rs1, 1);
        rs1 += __shfl_xor_sync(0xffffffffu, rs1, 2);
        if ((lane & 3) == 0) {
            int r = rg * 16 + (lane >> 2);
            atomicAdd(&rowsum[r], rs0);
            atomicAdd(&rowsum[r + 8], rs1);
        }
        __syncthreads();

        if (writeMean) {
#pragma unroll
            for (int rr = 0; rr < 2; rr++) {
                const int r = wid * 2 + rr;
                float fac = invH / rowsum[r];
                float* mrow = meanOut + ((size_t)b * SEQ + q0 + r) * SEQ;
#pragma unroll
                for (int it = 0; it < 8; it++) {
                    int base = it * 256 + lane * 8;
                    uint4 hv = *(uint4*)&S[r * SROW + base];
                    __half2* hp = (__half2*)&hv;
                    float e[8];
#pragma unroll
                    for (int p = 0; p < 4; p++) {
                        float2 f = __half22float2(hp[p]);
                        e[p * 2]     = f.x;
                        e[p * 2 + 1] = f.y;
                    }
                    if (h == 0) {
                        float4 m0 = make_float4(e[0] * fac, e[1] * fac,
                                                e[2] * fac, e[3] * fac);
                        float4 m1 = make_float4(e[4] * fac, e[5] * fac,
                                                e[6] * fac, e[7] * fac);
                        *(float4*)&mrow[base]     = m0;
                        *(float4*)&mrow[base + 4] = m1;
                    } else {
                        float4 m0 = *(const float4*)&mrow[base];
                        float4 m1 = *(const float4*)&mrow[base + 4];
                        m0.x = fmaf(e[0], fac, m0.x); m0.y = fmaf(e[1], fac, m0.y);
                        m0.z = fmaf(e[2], fac, m0.z); m0.w = fmaf(e[3], fac, m0.w);
                        m1.x = fmaf(e[4], fac, m1.x); m1.y = fmaf(e[5], fac, m1.y);
                        m1.z = fmaf(e[6], fac, m1.z); m1.w = fmaf(e[7], fac, m1.w);
                        *(float4*)&mrow[base]     = m0;
                        *(float4*)&mrow[base + 4] = m1;
                    }
                }
            }
        }
        __syncthreads();

        {
            float* dst = Sred + wid * 1024;
            int rl = lane >> 2, cl = (lane & 3) * 2;
#pragma unroll
            for (int n8 = 0; n8 < 8; n8++) {
                *(float2*)&dst[rl * 64 + n8 * 8 + cl]       =
                    make_float2(out[n8][0], out[n8][1]);
                *(float2*)&dst[(rl + 8) * 64 + n8 * 8 + cl] =
                    make_float2(out[n8][2], out[n8][3]);
            }
        }
        __syncthreads();

        {
            int row = tid >> 4;
            int col = (tid & 15) * 4;
            float s4[4] = {0.f, 0.f, 0.f, 0.f};
            int wbase = (row >> 4) * 8;
            int off   = (row & 15) * 64 + col;
#pragma unroll
            for (int w = 0; w < 8; w++) {
                const float* src = Sred + (wbase + w) * 1024 + off;
                s4[0] += src[0]; s4[1] += src[1];
                s4[2] += src[2]; s4[3] += src[3];
            }
            float inv = __fdividef(1.f, rowsum[row]);
            uint2 o;
            o.x = pack2h(__float2half_rn(s4[0] * inv), __float2half_rn(s4[1] * inv));
            o.y = pack2h(__float2half_rn(s4[2] * inv), __float2half_rn(s4[3] * inv));
            *(uint2*)&ctx[(size_t)(b * SEQ + q0 + row) * EMB + h * HDIM + col] = o;
        }
        __syncthreads();
    }
}

// ---------------- launch ------------------------------------------------------------
extern "C" void kernel_launch(void* const* d_in, const int* in_sizes, int n_in,
                              void* d_out, int out_size) {
    const float* query = (const float*)d_in[0];
    const float* key_  = (const float*)d_in[1];
    const float* value = (const float*)d_in[2];
    const float* Wq = (const float*)d_in[3];
    const float* bq = (const float*)d_in[4];
    const float* Wk = (const float*)d_in[5];
    const float* bk = (const float*)d_in[6];
    const float* Wv = (const float*)d_in[7];
    const float* bv = (const float*)d_in[8];
    const float* Wo = (const float*)d_in[9];
    const float* bo = (const float*)d_in[10];

    float* out = (float*)d_out;
    const size_t outElems  = (size_t)MROWS * EMB;
    const size_t meanElems = (size_t)BATCH * SEQ * SEQ;
    int writeMean = ((size_t)out_size >= outElems + meanElems) ? 1 : 0;
    float* meanOut = out + outElems;

    fp16 *A1, *A2, *A3, *W1, *W2, *W3, *W4, *Qfb, *Kfb, *Vfb;
    cudaGetSymbolAddress((void**)&A1,  g_A1);
    cudaGetSymbolAddress((void**)&A2,  g_A2);
    cudaGetSymbolAddress((void**)&A3,  g_A3);
    cudaGetSymbolAddress((void**)&W1,  g_W1);
    cudaGetSymbolAddress((void**)&W2,  g_W2);
    cudaGetSymbolAddress((void**)&W3,  g_W3);
    cudaGetSymbolAddress((void**)&W4,  g_W4);
    cudaGetSymbolAddress((void**)&Qfb, g_Qf);
    cudaGetSymbolAddress((void**)&Kfb, g_Kf);
    cudaGetSymbolAddress((void**)&Vfb, g_Vf);

    cudaFuncSetAttribute(gemm3_hmma, cudaFuncAttributeMaxDynamicSharedMemorySize,
                         GEMM_SMEM);
    cudaFuncSetAttribute(gemm_hmma, cudaFuncAttributeMaxDynamicSharedMemorySize,
                         GEMM_SMEM);
    cudaFuncSetAttribute(attn_fused, cudaFuncAttributeMaxDynamicSharedMemorySize,
                         ATTN_SMEM);

    // 1) all conversions (7 jobs, one launch)
    cvt_all<<<(CVT_TOTAL + 255) / 256, 256>>>(
        query, key_, value, Wq, Wk, Wv, Wo,
        A1, A2, A3, W1, W2, W3, W4);

    // 2) Q/K/V projections fused in one grid (z = job)
    gemm3_hmma<<<dim3(EMB / 128, MROWS / 128, 3), 256, GEMM_SMEM>>>(
        A1, W1, bq, Qfb,
        A2, W2, bk, Kfb,
        A3, W3, bv, Vfb);

    // 3) fused attention -> ctx fp16 into A1
    attn_fused<<<dim3(SEQ / QROWS, BATCH), NTHR, ATTN_SMEM>>>(
        Qfb, Kfb, Vfb, A1, meanOut, writeMean);

    // 4) output projection -> fp32 out
    gemm_hmma<<<dim3(EMB / 128, MROWS / 128), 256, GEMM_SMEM>>>(
        A1, W4, bo, out, 1.f, MROWS, EMB, EMB);
}